// round 8
// baseline (speedup 1.0000x reference)
#include <cuda_runtime.h>
#include <cuda_bf16.h>
#include <math.h>

#define T   4096
#define CHN 512
#define M3  1536

__device__ float g_qkv[(size_t)2 * M3 * T];
__device__ float g_a[(size_t)2 * CHN * T];
__device__ float g_ir[(size_t)2 * T];

__device__ __forceinline__ unsigned tf32r(float x) {
    unsigned r; asm("cvt.rna.tf32.f32 %0, %1;" : "=r"(r) : "f"(x)); return r;
}
__device__ __forceinline__ void mma8(float c[4], const unsigned a[4],
                                     unsigned b0, unsigned b1) {
    asm volatile("mma.sync.aligned.m16n8k8.row.col.f32.tf32.tf32.f32 "
                 "{%0,%1,%2,%3}, {%4,%5,%6,%7}, {%8,%9}, {%0,%1,%2,%3};"
                 : "+f"(c[0]), "+f"(c[1]), "+f"(c[2]), "+f"(c[3])
                 : "r"(a[0]), "r"(a[1]), "r"(a[2]), "r"(a[3]), "r"(b0), "r"(b1));
}
__device__ __forceinline__ void ldsm4(unsigned r[4], unsigned addr) {
    asm volatile("ldmatrix.sync.aligned.m8n8.x4.shared.b16 {%0,%1,%2,%3}, [%4];"
                 : "=r"(r[0]), "=r"(r[1]), "=r"(r[2]), "=r"(r[3]) : "r"(addr));
}
__device__ __forceinline__ unsigned sel16(unsigned w, unsigned odd) {
    return odd ? (w & 0xffff0000u) : (w << 16);
}
__device__ __forceinline__ unsigned pack2bf(float a, float b) {
    __nv_bfloat162 p = __floats2bfloat162_rn(a, b);
    return *reinterpret_cast<unsigned*>(&p);
}

// ---------------------------------------------------------------------------
__global__ void __launch_bounds__(256) rms_kernel(const float* __restrict__ x) {
    __shared__ float red[8][32];
    int l = threadIdx.x & 31, w = threadIdx.x >> 5;
    int i = blockIdx.x * 32 + l;
    int b = i >> 12, t = i & (T - 1);
    const float* xp = x + (size_t)b * CHN * T + t + (size_t)(w * 64) * T;
    float s = 0.f;
#pragma unroll 16
    for (int j = 0; j < 64; j++) { float v = xp[(size_t)j * T]; s = fmaf(v, v, s); }
    red[w][l] = s;
    __syncthreads();
    if (w == 0) {
        float tot = red[0][l];
#pragma unroll
        for (int k = 1; k < 8; k++) tot += red[k][l];
        g_ir[i] = 22.62741699796952f * rsqrtf(tot * (1.f / CHN) + 1e-8f);
    }
}

// ---------------------------------------------------------------------------
// 128x128 tile, BK=32, 8 warps (warp 32x64). QKV: split (lo bf16). proj: single.
// Software-pipelined: gmem tile k+1 loads into regs while tile k computes.
template<bool QKV>
__global__ void __launch_bounds__(256, 2) gemm_mma(
        const float* __restrict__ W, const float* __restrict__ Xin,
        const float* __restrict__ nw, const float* __restrict__ bias,
        const float* __restrict__ resid, float* __restrict__ outp)
{
    extern __shared__ unsigned smg[];
    unsigned* Ahi = smg;              // [128][36]
    unsigned* Bhi = smg + 4608;       // [128][36]
    unsigned* Alo = smg + 9216;       // [128][20] packed bf16 (QKV only)
    unsigned* Blo = smg + 11776;      // [128][20]
    unsigned baseA = (unsigned)__cvta_generic_to_shared(Ahi);
    unsigned baseB = (unsigned)__cvta_generic_to_shared(Bhi);

    int b = blockIdx.z, m0 = blockIdx.y * 128, t0 = blockIdx.x * 128;
    int tid = threadIdx.x, lane = tid & 31, wid = tid >> 5;
    int wm = wid >> 1, wn = wid & 1, g = lane >> 2, q = lane & 3;
    int grp = lane >> 3, lam = lane & 7;
    unsigned odd = q & 1;
    const float* Xb = (QKV ? Xin : (const float*)g_a) + (size_t)b * CHN * T;
    int bc4 = tid & 7, bt4 = tid >> 3;
    float4 ir4 = make_float4(1.f, 1.f, 1.f, 1.f);
    if (QKV) ir4 = *(const float4*)&g_ir[b * T + t0 + 4 * bt4];

    float acc[2][8][4];
#pragma unroll
    for (int mt = 0; mt < 2; mt++)
#pragma unroll
        for (int nt = 0; nt < 8; nt++)
#pragma unroll
            for (int i = 0; i < 4; i++) acc[mt][nt][i] = 0.f;

    float4 wreg[4], xreg[4];
#pragma unroll
    for (int i = 0; i < 4; i++) {
        int idx = tid + i * 256, row = idx >> 3, c4 = idx & 7;
        wreg[i] = *(const float4*)&W[(size_t)(m0 + row) * CHN + 4 * c4];
    }
#pragma unroll
    for (int j = 0; j < 4; j++)
        xreg[j] = *(const float4*)&Xb[(size_t)(4 * bc4 + j) * T + t0 + 4 * bt4];

    for (int k0 = 0; k0 < CHN; k0 += 32) {
        // ---- store staged regs to smem (with cvt/split/scale) ----
#pragma unroll
        for (int i = 0; i < 4; i++) {
            int idx = tid + i * 256, row = idx >> 3, c4 = idx & 7;
            float4 w = wreg[i];
            unsigned h0 = tf32r(w.x), h1 = tf32r(w.y), h2 = tf32r(w.z), h3 = tf32r(w.w);
            *(uint4*)&Ahi[row * 36 + 4 * c4] = make_uint4(h0, h1, h2, h3);
            if (QKV)
                *(uint2*)&Alo[row * 20 + 2 * c4] = make_uint2(
                    pack2bf(w.x - __uint_as_float(h0), w.y - __uint_as_float(h1)),
                    pack2bf(w.z - __uint_as_float(h2), w.w - __uint_as_float(h3)));
        }
        {
            float4 r[4];
#pragma unroll
            for (int j = 0; j < 4; j++) {
                r[j] = xreg[j];
                if (QKV) {
                    float s = nw[k0 + 4 * bc4 + j];
                    r[j].x *= s * ir4.x; r[j].y *= s * ir4.y;
                    r[j].z *= s * ir4.z; r[j].w *= s * ir4.w;
                }
            }
#pragma unroll
            for (int jp = 0; jp < 4; jp++) {
                float v0 = (&r[0].x)[jp], v1 = (&r[1].x)[jp];
                float v2 = (&r[2].x)[jp], v3 = (&r[3].x)[jp];
                unsigned h0 = tf32r(v0), h1 = tf32r(v1), h2 = tf32r(v2), h3 = tf32r(v3);
                *(uint4*)&Bhi[(4 * bt4 + jp) * 36 + 4 * bc4] = make_uint4(h0, h1, h2, h3);
                if (QKV)
                    *(uint2*)&Blo[(4 * bt4 + jp) * 20 + 2 * bc4] = make_uint2(
                        pack2bf(v0 - __uint_as_float(h0), v1 - __uint_as_float(h1)),
                        pack2bf(v2 - __uint_as_float(h2), v3 - __uint_as_float(h3)));
            }
        }
        __syncthreads();
        // ---- prefetch next k-tile into regs (latency hides under compute) ----
        if (k0 + 32 < CHN) {
            int kn = k0 + 32;
#pragma unroll
            for (int i = 0; i < 4; i++) {
                int idx = tid + i * 256, row = idx >> 3, c4 = idx & 7;
                wreg[i] = *(const float4*)&W[(size_t)(m0 + row) * CHN + kn + 4 * c4];
            }
#pragma unroll
            for (int j = 0; j < 4; j++)
                xreg[j] = *(const float4*)&Xb[(size_t)(kn + 4 * bc4 + j) * T + t0 + 4 * bt4];
        }
        // ---- compute ----
#pragma unroll
        for (int ks = 0; ks < 4; ks++) {
            unsigned ah[2][4], al[2][4];
#pragma unroll
            for (int mt = 0; mt < 2; mt++) {
                unsigned row = wm * 32 + mt * 16 + (grp & 1) * 8 + lam;
                unsigned col = ks * 8 + (grp >> 1) * 4;
                ldsm4(ah[mt], baseA + (row * 36 + col) * 4);
                if (QKV) {
                    int rb = wm * 32 + mt * 16, wq = ks * 4 + (q >> 1);
                    al[mt][0] = sel16(Alo[(rb + g) * 20 + wq], odd);
                    al[mt][1] = sel16(Alo[(rb + g + 8) * 20 + wq], odd);
                    al[mt][2] = sel16(Alo[(rb + g) * 20 + wq + 2], odd);
                    al[mt][3] = sel16(Alo[(rb + g + 8) * 20 + wq + 2], odd);
                }
            }
#pragma unroll
            for (int ntp = 0; ntp < 8; ntp += 2) {
                unsigned row = wn * 64 + (ntp + (grp >> 1)) * 8 + lam;
                unsigned col = ks * 8 + (grp & 1) * 4;
                unsigned bh[4];
                ldsm4(bh, baseB + (row * 36 + col) * 4);
#pragma unroll
                for (int mt = 0; mt < 2; mt++) {
                    mma8(acc[mt][ntp], ah[mt], bh[0], bh[1]);
                    mma8(acc[mt][ntp + 1], ah[mt], bh[2], bh[3]);
                }
                if (QKV) {
                    int wq = ks * 4 + (q >> 1);
#pragma unroll
                    for (int d = 0; d < 2; d++) {
                        int cb = wn * 64 + (ntp + d) * 8;
                        unsigned bl0 = sel16(Blo[(cb + g) * 20 + wq], odd);
                        unsigned bl1 = sel16(Blo[(cb + g) * 20 + wq + 2], odd);
#pragma unroll
                        for (int mt = 0; mt < 2; mt++) {
                            mma8(acc[mt][ntp + d], ah[mt], bl0, bl1);
                            mma8(acc[mt][ntp + d], al[mt], bh[2 * d], bh[2 * d + 1]);
                        }
                    }
                }
            }
        }
        __syncthreads();
    }
#pragma unroll
    for (int mt = 0; mt < 2; mt++) {
        int row = m0 + wm * 32 + mt * 16 + g;
        float bi0 = bias[row], bi1 = bias[row + 8];
#pragma unroll
        for (int nt = 0; nt < 8; nt++) {
            int col = t0 + wn * 64 + nt * 8 + 2 * q;
            if (QKV) {
                *(float2*)&g_qkv[((size_t)b * M3 + row) * T + col] =
                    make_float2(acc[mt][nt][0] + bi0, acc[mt][nt][1] + bi0);
                *(float2*)&g_qkv[((size_t)b * M3 + row + 8) * T + col] =
                    make_float2(acc[mt][nt][2] + bi1, acc[mt][nt][3] + bi1);
            } else {
                size_t i0 = ((size_t)b * CHN + row) * T + col;
                size_t i1 = ((size_t)b * CHN + row + 8) * T + col;
                float2 r0 = *(const float2*)&resid[i0];
                float2 r1 = *(const float2*)&resid[i1];
                *(float2*)&outp[i0] = make_float2(acc[mt][nt][0] + bi0 + r0.x,
                                                  acc[mt][nt][1] + bi0 + r0.y);
                *(float2*)&outp[i1] = make_float2(acc[mt][nt][2] + bi1 + r1.x,
                                                  acc[mt][nt][3] + bi1 + r1.y);
            }
        }
    }
}

// ---------------------------------------------------------------------------
// Flash attention: block = 128 queries x 1 head, 8 warps x 16 rows.
// Software-pipelined: K prefetched before QK, V prefetched during softmax.
__global__ void __launch_bounds__(256, 2) attn_mma() {
    extern __shared__ unsigned sma[];
    unsigned* Ps   = sma;             // [128][68] (Qhi in prologue, then P)
    unsigned* Qlo  = sma + 8704;      // [128][36] packed bf16, persistent
    unsigned* Khi  = sma + 13312;     // [64][68]
    unsigned* Klo  = sma + 17664;     // [64][68] tf32
    unsigned* Vs   = sma + 22016;     // [64][68]
    unsigned basePs = (unsigned)__cvta_generic_to_shared(Ps);
    unsigned baseKh = (unsigned)__cvta_generic_to_shared(Khi);
    unsigned baseKl = (unsigned)__cvta_generic_to_shared(Klo);
    unsigned baseV  = (unsigned)__cvta_generic_to_shared(Vs);

    int t0 = blockIdx.x * 128, head = blockIdx.y;
    int b = head >> 3, hh = head & 7;
    const float* qb = g_qkv + ((size_t)b * M3 + hh * 192) * T;
    const float* kb = qb + (size_t)64 * T;
    const float* vb = qb + (size_t)128 * T;
    int tid = threadIdx.x, lane = tid & 31, wid = tid >> 5;
    int g = lane >> 2, q = lane & 3, rb = wid * 16;
    int grp = lane >> 3, lam = lane & 7;
    unsigned odd = q & 1;
    int c4 = tid & 15, s4 = tid >> 4;

    {   // Q fill: [c][t] -> [t][c] * 0.125, hi tf32 into Ps, lo bf16 into Qlo
#pragma unroll
        for (int it = 0; it < 2; it++) {
            int t4 = (tid >> 4) + it * 16;
            float4 r[4];
#pragma unroll
            for (int j = 0; j < 4; j++) {
                r[j] = *(const float4*)&qb[(size_t)(4 * c4 + j) * T + t0 + 4 * t4];
                r[j].x *= 0.125f; r[j].y *= 0.125f; r[j].z *= 0.125f; r[j].w *= 0.125f;
            }
#pragma unroll
            for (int jp = 0; jp < 4; jp++) {
                float v0 = (&r[0].x)[jp], v1 = (&r[1].x)[jp];
                float v2 = (&r[2].x)[jp], v3 = (&r[3].x)[jp];
                unsigned h0 = tf32r(v0), h1 = tf32r(v1), h2 = tf32r(v2), h3 = tf32r(v3);
                *(uint4*)&Ps[(4 * t4 + jp) * 68 + 4 * c4] = make_uint4(h0, h1, h2, h3);
                *(uint2*)&Qlo[(4 * t4 + jp) * 36 + 2 * c4] = make_uint2(
                    pack2bf(v0 - __uint_as_float(h0), v1 - __uint_as_float(h1)),
                    pack2bf(v2 - __uint_as_float(h2), v3 - __uint_as_float(h3)));
            }
        }
    }
    __syncthreads();
    unsigned qh[8][4];
#pragma unroll
    for (int ks = 0; ks < 8; ks++) {
        unsigned row = rb + (grp & 1) * 8 + lam;
        unsigned col = ks * 8 + (grp >> 1) * 4;
        ldsm4(qh[ks], basePs + (row * 68 + col) * 4);
    }

    float o[8][4];
#pragma unroll
    for (int nt = 0; nt < 8; nt++)
#pragma unroll
        for (int i = 0; i < 4; i++) o[nt][i] = 0.f;
    float m_a = -1e30f, m_b = -1e30f, l_a = 0.f, l_b = 0.f;

    float4 kreg[4], vreg[4];
#pragma unroll
    for (int j = 0; j < 4; j++)
        kreg[j] = *(const float4*)&kb[(size_t)(4 * c4 + j) * T + 4 * s4];
#pragma unroll
    for (int i = 0; i < 4; i++) {
        int idx = tid + i * 256, c = idx >> 4, sv = idx & 15;
        vreg[i] = *(const float4*)&vb[(size_t)c * T + 4 * sv];
    }

    for (int s0 = 0; s0 < T; s0 += 64) {
        int sn = (s0 + 64 < T) ? s0 + 64 : s0;
        __syncthreads();
        {   // store staged K (hi + lo tf32, transposed) and V (single tf32)
#pragma unroll
            for (int jp = 0; jp < 4; jp++) {
                float v0 = (&kreg[0].x)[jp], v1 = (&kreg[1].x)[jp];
                float v2 = (&kreg[2].x)[jp], v3 = (&kreg[3].x)[jp];
                unsigned h0 = tf32r(v0), h1 = tf32r(v1), h2 = tf32r(v2), h3 = tf32r(v3);
                *(uint4*)&Khi[(4 * s4 + jp) * 68 + 4 * c4] = make_uint4(h0, h1, h2, h3);
                *(uint4*)&Klo[(4 * s4 + jp) * 68 + 4 * c4] = make_uint4(
                    tf32r(v0 - __uint_as_float(h0)), tf32r(v1 - __uint_as_float(h1)),
                    tf32r(v2 - __uint_as_float(h2)), tf32r(v3 - __uint_as_float(h3)));
            }
#pragma unroll
            for (int i = 0; i < 4; i++) {
                int idx = tid + i * 256, c = idx >> 4, sv = idx & 15;
                float4 v = vreg[i];
                *(uint4*)&Vs[c * 68 + 4 * sv] =
                    make_uint4(tf32r(v.x), tf32r(v.y), tf32r(v.z), tf32r(v.w));
            }
        }
        __syncthreads();
        // prefetch next K (latency hides under QK compute)
#pragma unroll
        for (int j = 0; j < 4; j++)
            kreg[j] = *(const float4*)&kb[(size_t)(4 * c4 + j) * T + sn + 4 * s4];

        float sacc[8][4];
#pragma unroll
        for (int nt = 0; nt < 8; nt++)
#pragma unroll
            for (int i = 0; i < 4; i++) sacc[nt][i] = 0.f;
#pragma unroll
        for (int ks = 0; ks < 8; ks++) {
            unsigned al[4];
            {
                int wq = ks * 4 + (q >> 1);
                al[0] = sel16(Qlo[(rb + g) * 36 + wq], odd);
                al[1] = sel16(Qlo[(rb + g + 8) * 36 + wq], odd);
                al[2] = sel16(Qlo[(rb + g) * 36 + wq + 2], odd);
                al[3] = sel16(Qlo[(rb + g + 8) * 36 + wq + 2], odd);
            }
#pragma unroll
            for (int ntp = 0; ntp < 8; ntp += 2) {
                unsigned row = (ntp + (grp >> 1)) * 8 + lam;
                unsigned col = ks * 8 + (grp & 1) * 4;
                unsigned off = (row * 68 + col) * 4;
                unsigned kh[4], kl[4];
                ldsm4(kh, baseKh + off);
                ldsm4(kl, baseKl + off);
                mma8(sacc[ntp], qh[ks], kh[0], kh[1]);
                mma8(sacc[ntp], qh[ks], kl[0], kl[1]);
                mma8(sacc[ntp], al, kh[0], kh[1]);
                mma8(sacc[ntp + 1], qh[ks], kh[2], kh[3]);
                mma8(sacc[ntp + 1], qh[ks], kl[2], kl[3]);
                mma8(sacc[ntp + 1], al, kh[2], kh[3]);
            }
        }

        float mx_a = -1e30f, mx_b = -1e30f;
#pragma unroll
        for (int nt = 0; nt < 8; nt++) {
            mx_a = fmaxf(mx_a, fmaxf(sacc[nt][0], sacc[nt][1]));
            mx_b = fmaxf(mx_b, fmaxf(sacc[nt][2], sacc[nt][3]));
        }
        mx_a = fmaxf(mx_a, __shfl_xor_sync(~0u, mx_a, 1));
        mx_a = fmaxf(mx_a, __shfl_xor_sync(~0u, mx_a, 2));
        mx_b = fmaxf(mx_b, __shfl_xor_sync(~0u, mx_b, 1));
        mx_b = fmaxf(mx_b, __shfl_xor_sync(~0u, mx_b, 2));
        float mn_a = fmaxf(m_a, mx_a), mn_b = fmaxf(m_b, mx_b);
        float ca = __expf(m_a - mn_a), cb = __expf(m_b - mn_b);
        float sum_a = 0.f, sum_b = 0.f;
#pragma unroll
        for (int nt = 0; nt < 8; nt++) {
            float p0 = __expf(sacc[nt][0] - mn_a), p1 = __expf(sacc[nt][1] - mn_a);
            float p2 = __expf(sacc[nt][2] - mn_b), p3 = __expf(sacc[nt][3] - mn_b);
            sum_a += p0 + p1; sum_b += p2 + p3;
            *(uint2*)&Ps[(rb + g) * 68 + nt * 8 + 2 * q] = make_uint2(tf32r(p0), tf32r(p1));
            *(uint2*)&Ps[(rb + g + 8) * 68 + nt * 8 + 2 * q] = make_uint2(tf32r(p2), tf32r(p3));
        }
        sum_a += __shfl_xor_sync(~0u, sum_a, 1);
        sum_a += __shfl_xor_sync(~0u, sum_a, 2);
        sum_b += __shfl_xor_sync(~0u, sum_b, 1);
        sum_b += __shfl_xor_sync(~0u, sum_b, 2);
        m_a = mn_a; m_b = mn_b;
        l_a = l_a * ca + sum_a; l_b = l_b * cb + sum_b;
#pragma unroll
        for (int nt = 0; nt < 8; nt++) {
            o[nt][0] *= ca; o[nt][1] *= ca; o[nt][2] *= cb; o[nt][3] *= cb;
        }
        // prefetch next V (latency hides under PV compute)
#pragma unroll
        for (int i = 0; i < 4; i++) {
            int idx = tid + i * 256, c = idx >> 4, sv = idx & 15;
            vreg[i] = *(const float4*)&vb[(size_t)c * T + sn + 4 * sv];
        }
        __syncwarp();
#pragma unroll
        for (int ks = 0; ks < 8; ks++) {
            unsigned ph[4];
            {
                unsigned row = rb + (grp & 1) * 8 + lam;
                unsigned col = ks * 8 + (grp >> 1) * 4;
                ldsm4(ph, basePs + (row * 68 + col) * 4);
            }
#pragma unroll
            for (int ntp = 0; ntp < 8; ntp += 2) {
                unsigned row = (ntp + (grp >> 1)) * 8 + lam;
                unsigned col = ks * 8 + (grp & 1) * 4;
                unsigned vv[4];
                ldsm4(vv, baseV + (row * 68 + col) * 4);
                mma8(o[ntp], ph, vv[0], vv[1]);
                mma8(o[ntp + 1], ph, vv[2], vv[3]);
            }
        }
    }

    float inv_a = 1.f / l_a, inv_b = 1.f / l_b;
    float* ab = g_a + ((size_t)b * CHN + hh * 64) * T;
#pragma unroll
    for (int nt = 0; nt < 8; nt++) {
        int c0 = nt * 8 + 2 * q;
        ab[(size_t)c0 * T + t0 + rb + g]           = o[nt][0] * inv_a;
        ab[(size_t)(c0 + 1) * T + t0 + rb + g]     = o[nt][1] * inv_a;
        ab[(size_t)c0 * T + t0 + rb + g + 8]       = o[nt][2] * inv_b;
        ab[(size_t)(c0 + 1) * T + t0 + rb + g + 8] = o[nt][3] * inv_b;
    }
}

// ---------------------------------------------------------------------------
extern "C" void kernel_launch(void* const* d_in, const int* in_sizes, int n_in,
                              void* d_out, int out_size) {
    const float* x      = (const float*)d_in[0];
    const float* nw     = (const float*)d_in[1];
    const float* qkv_w  = (const float*)d_in[2];
    const float* qkv_b  = (const float*)d_in[3];
    const float* proj_w = (const float*)d_in[4];
    const float* proj_b = (const float*)d_in[5];
    float* out = (float*)d_out;

    const int QKV_SMEM  = 14336 * 4;  // 57344
    const int PROJ_SMEM = 9216 * 4;   // 36864
    const int ATT_SMEM  = 26368 * 4;  // 105472
    static bool init = false;
    if (!init) {
        cudaFuncSetAttribute(gemm_mma<true>,  cudaFuncAttributeMaxDynamicSharedMemorySize, QKV_SMEM);
        cudaFuncSetAttribute(gemm_mma<false>, cudaFuncAttributeMaxDynamicSharedMemorySize, PROJ_SMEM);
        cudaFuncSetAttribute(attn_mma,        cudaFuncAttributeMaxDynamicSharedMemorySize, ATT_SMEM);
        cudaFuncSetAttribute(gemm_mma<true>,  cudaFuncAttributePreferredSharedMemoryCarveout, 100);
        cudaFuncSetAttribute(gemm_mma<false>, cudaFuncAttributePreferredSharedMemoryCarveout, 100);
        cudaFuncSetAttribute(attn_mma,        cudaFuncAttributePreferredSharedMemoryCarveout, 100);
        init = true;
    }
    rms_kernel<<<256, 256>>>(x);
    gemm_mma<true><<<dim3(32, 12, 2), 256, QKV_SMEM>>>(qkv_w, x, nw, qkv_b, nullptr, nullptr);
    attn_mma<<<dim3(32, 16), 256, ATT_SMEM>>>();
    gemm_mma<false><<<dim3(32, 4, 2), 256, PROJ_SMEM>>>(proj_w, nullptr, nullptr, proj_b, x, out);
}

// round 9
// speedup vs baseline: 1.4886x; 1.4886x over previous
#include <cuda_runtime.h>
#include <cuda_fp16.h>
#include <math.h>

#define T   4096
#define CHN 512
#define M3  1536

__device__ float g_qkv[(size_t)2 * M3 * T];
__device__ float g_a[(size_t)2 * CHN * T];
__device__ float g_ir[(size_t)2 * T];

__device__ __forceinline__ unsigned tf32r(float x) {
    unsigned r; asm("cvt.rna.tf32.f32 %0, %1;" : "=r"(r) : "f"(x)); return r;
}
__device__ __forceinline__ void mma8(float c[4], const unsigned a[4],
                                     unsigned b0, unsigned b1) {
    asm volatile("mma.sync.aligned.m16n8k8.row.col.f32.tf32.tf32.f32 "
                 "{%0,%1,%2,%3}, {%4,%5,%6,%7}, {%8,%9}, {%0,%1,%2,%3};"
                 : "+f"(c[0]), "+f"(c[1]), "+f"(c[2]), "+f"(c[3])
                 : "r"(a[0]), "r"(a[1]), "r"(a[2]), "r"(a[3]), "r"(b0), "r"(b1));
}
__device__ __forceinline__ void mma16(float c[4], const unsigned a[4],
                                      unsigned b0, unsigned b1) {
    asm volatile("mma.sync.aligned.m16n8k16.row.col.f32.f16.f16.f32 "
                 "{%0,%1,%2,%3}, {%4,%5,%6,%7}, {%8,%9}, {%0,%1,%2,%3};"
                 : "+f"(c[0]), "+f"(c[1]), "+f"(c[2]), "+f"(c[3])
                 : "r"(a[0]), "r"(a[1]), "r"(a[2]), "r"(a[3]), "r"(b0), "r"(b1));
}
__device__ __forceinline__ void ldsm4(unsigned r[4], unsigned addr) {
    asm volatile("ldmatrix.sync.aligned.m8n8.x4.shared.b16 {%0,%1,%2,%3}, [%4];"
                 : "=r"(r[0]), "=r"(r[1]), "=r"(r[2]), "=r"(r[3]) : "r"(addr));
}
// split (v0,v1) into packed fp16 hi pair + fp16 lo (residual) pair
__device__ __forceinline__ void split2(float v0, float v1, unsigned& hi, unsigned& lo) {
    __half h0 = __float2half_rn(v0), h1 = __float2half_rn(v1);
    __half2 hh = __halves2half2(h0, h1);
    hi = *reinterpret_cast<unsigned*>(&hh);
    __half l0 = __float2half_rn(v0 - __half2float(h0));
    __half l1 = __float2half_rn(v1 - __half2float(h1));
    __half2 ll = __halves2half2(l0, l1);
    lo = *reinterpret_cast<unsigned*>(&ll);
}
__device__ __forceinline__ unsigned pack2h(float a, float b) {
    __half2 p = __floats2half2_rn(a, b);
    return *reinterpret_cast<unsigned*>(&p);
}

// ---------------------------------------------------------------------------
__global__ void __launch_bounds__(256) rms_kernel(const float* __restrict__ x) {
    __shared__ float red[8][32];
    int l = threadIdx.x & 31, w = threadIdx.x >> 5;
    int i = blockIdx.x * 32 + l;
    int b = i >> 12, t = i & (T - 1);
    const float* xp = x + (size_t)b * CHN * T + t + (size_t)(w * 64) * T;
    float s = 0.f;
#pragma unroll 16
    for (int j = 0; j < 64; j++) { float v = xp[(size_t)j * T]; s = fmaf(v, v, s); }
    red[w][l] = s;
    __syncthreads();
    if (w == 0) {
        float tot = red[0][l];
#pragma unroll
        for (int k = 1; k < 8; k++) tot += red[k][l];
        g_ir[i] = 22.62741699796952f * rsqrtf(tot * (1.f / CHN) + 1e-8f);
    }
}

// ---------------------------------------------------------------------------
// QKV GEMM, fp16 split (hh+hl+lh). 128x128 tile, BK=32, 8 warps (warp 32x64).
// W scaled x256 before split (keeps lo out of fp16 subnormals), /256 in epilogue.
__global__ void __launch_bounds__(256, 2) qkv_mma(
        const float* __restrict__ W, const float* __restrict__ Xin,
        const float* __restrict__ nw, const float* __restrict__ bias)
{
    extern __shared__ unsigned smg[];
    unsigned* Ahi = smg;              // [128][20] packed fp16 pairs
    unsigned* Alo = smg + 2560;
    unsigned* Bhi = smg + 5120;
    unsigned* Blo = smg + 7680;       // total 10240 words
    unsigned baseAh = (unsigned)__cvta_generic_to_shared(Ahi);
    unsigned baseAl = (unsigned)__cvta_generic_to_shared(Alo);
    unsigned baseBh = (unsigned)__cvta_generic_to_shared(Bhi);
    unsigned baseBl = (unsigned)__cvta_generic_to_shared(Blo);

    int b = blockIdx.z, m0 = blockIdx.y * 128, t0 = blockIdx.x * 128;
    int tid = threadIdx.x, lane = tid & 31, wid = tid >> 5;
    int wm = wid >> 1, wn = wid & 1, g = lane >> 2, q = lane & 3;
    int grp = lane >> 3, lam = lane & 7;
    const float* Xb = Xin + (size_t)b * CHN * T;
    int bc4 = tid & 7, bt4 = tid >> 3;
    float4 ir4 = *(const float4*)&g_ir[b * T + t0 + 4 * bt4];

    float acc[2][8][4];
#pragma unroll
    for (int mt = 0; mt < 2; mt++)
#pragma unroll
        for (int nt = 0; nt < 8; nt++)
#pragma unroll
            for (int i = 0; i < 4; i++) acc[mt][nt][i] = 0.f;

    for (int k0 = 0; k0 < CHN; k0 += 32) {
#pragma unroll
        for (int i = 0; i < 4; i++) {
            int idx = tid + i * 256, row = idx >> 3, c4 = idx & 7;
            float4 w = *(const float4*)&W[(size_t)(m0 + row) * CHN + k0 + 4 * c4];
            unsigned h01, l01, h23, l23;
            split2(w.x * 256.f, w.y * 256.f, h01, l01);
            split2(w.z * 256.f, w.w * 256.f, h23, l23);
            *(uint2*)&Ahi[row * 20 + 2 * c4] = make_uint2(h01, h23);
            *(uint2*)&Alo[row * 20 + 2 * c4] = make_uint2(l01, l23);
        }
        {
            float4 r[4];
#pragma unroll
            for (int j = 0; j < 4; j++) {
                r[j] = *(const float4*)&Xb[(size_t)(k0 + 4 * bc4 + j) * T + t0 + 4 * bt4];
                float s = nw[k0 + 4 * bc4 + j];
                r[j].x *= s * ir4.x; r[j].y *= s * ir4.y;
                r[j].z *= s * ir4.z; r[j].w *= s * ir4.w;
            }
#pragma unroll
            for (int jp = 0; jp < 4; jp++) {
                unsigned h01, l01, h23, l23;
                split2((&r[0].x)[jp], (&r[1].x)[jp], h01, l01);
                split2((&r[2].x)[jp], (&r[3].x)[jp], h23, l23);
                *(uint2*)&Bhi[(4 * bt4 + jp) * 20 + 2 * bc4] = make_uint2(h01, h23);
                *(uint2*)&Blo[(4 * bt4 + jp) * 20 + 2 * bc4] = make_uint2(l01, l23);
            }
        }
        __syncthreads();
#pragma unroll
        for (int ks = 0; ks < 2; ks++) {
            unsigned ah[2][4], al[2][4];
#pragma unroll
            for (int mt = 0; mt < 2; mt++) {
                unsigned row = wm * 32 + mt * 16 + (grp & 1) * 8 + lam;
                unsigned col = ks * 8 + (grp >> 1) * 4;
                unsigned off = (row * 20 + col) * 4;
                ldsm4(ah[mt], baseAh + off);
                ldsm4(al[mt], baseAl + off);
            }
#pragma unroll
            for (int ntp = 0; ntp < 8; ntp += 2) {
                unsigned row = wn * 64 + (ntp + (grp >> 1)) * 8 + lam;
                unsigned col = ks * 8 + (grp & 1) * 4;
                unsigned off = (row * 20 + col) * 4;
                unsigned bh[4], bl[4];
                ldsm4(bh, baseBh + off);
                ldsm4(bl, baseBl + off);
#pragma unroll
                for (int mt = 0; mt < 2; mt++) {
                    mma16(acc[mt][ntp],     ah[mt], bh[0], bh[1]);
                    mma16(acc[mt][ntp],     ah[mt], bl[0], bl[1]);
                    mma16(acc[mt][ntp],     al[mt], bh[0], bh[1]);
                    mma16(acc[mt][ntp + 1], ah[mt], bh[2], bh[3]);
                    mma16(acc[mt][ntp + 1], ah[mt], bl[2], bl[3]);
                    mma16(acc[mt][ntp + 1], al[mt], bh[2], bh[3]);
                }
            }
        }
        __syncthreads();
    }
#pragma unroll
    for (int mt = 0; mt < 2; mt++) {
        int row = m0 + wm * 32 + mt * 16 + g;
        float bi0 = bias[row], bi1 = bias[row + 8];
#pragma unroll
        for (int nt = 0; nt < 8; nt++) {
            int col = t0 + wn * 64 + nt * 8 + 2 * q;
            *(float2*)&g_qkv[((size_t)b * M3 + row) * T + col] =
                make_float2(acc[mt][nt][0] * (1.f / 256.f) + bi0,
                            acc[mt][nt][1] * (1.f / 256.f) + bi0);
            *(float2*)&g_qkv[((size_t)b * M3 + row + 8) * T + col] =
                make_float2(acc[mt][nt][2] * (1.f / 256.f) + bi1,
                            acc[mt][nt][3] * (1.f / 256.f) + bi1);
        }
    }
}

// ---------------------------------------------------------------------------
// proj GEMM + bias + residual: single tf32 (round-7 proven path).
__global__ void __launch_bounds__(256, 2) proj_mma(
        const float* __restrict__ W, const float* __restrict__ bias,
        const float* __restrict__ resid, float* __restrict__ outp)
{
    extern __shared__ unsigned smg[];
    unsigned* Ahi = smg;              // [128][36]
    unsigned* Bhi = smg + 4608;       // [128][36]
    unsigned baseA = (unsigned)__cvta_generic_to_shared(Ahi);
    unsigned baseB = (unsigned)__cvta_generic_to_shared(Bhi);

    int b = blockIdx.z, m0 = blockIdx.y * 128, t0 = blockIdx.x * 128;
    int tid = threadIdx.x, lane = tid & 31, wid = tid >> 5;
    int wm = wid >> 1, wn = wid & 1, g = lane >> 2, q = lane & 3;
    int grp = lane >> 3, lam = lane & 7;
    const float* Xb = (const float*)g_a + (size_t)b * CHN * T;
    int bc4 = tid & 7, bt4 = tid >> 3;

    float acc[2][8][4];
#pragma unroll
    for (int mt = 0; mt < 2; mt++)
#pragma unroll
        for (int nt = 0; nt < 8; nt++)
#pragma unroll
            for (int i = 0; i < 4; i++) acc[mt][nt][i] = 0.f;

    for (int k0 = 0; k0 < CHN; k0 += 32) {
#pragma unroll
        for (int i = 0; i < 4; i++) {
            int idx = tid + i * 256, row = idx >> 3, c4 = idx & 7;
            float4 w = *(const float4*)&W[(size_t)(m0 + row) * CHN + k0 + 4 * c4];
            *(uint4*)&Ahi[row * 36 + 4 * c4] =
                make_uint4(tf32r(w.x), tf32r(w.y), tf32r(w.z), tf32r(w.w));
        }
        {
            float4 r[4];
#pragma unroll
            for (int j = 0; j < 4; j++)
                r[j] = *(const float4*)&Xb[(size_t)(k0 + 4 * bc4 + j) * T + t0 + 4 * bt4];
#pragma unroll
            for (int jp = 0; jp < 4; jp++)
                *(uint4*)&Bhi[(4 * bt4 + jp) * 36 + 4 * bc4] =
                    make_uint4(tf32r((&r[0].x)[jp]), tf32r((&r[1].x)[jp]),
                               tf32r((&r[2].x)[jp]), tf32r((&r[3].x)[jp]));
        }
        __syncthreads();
#pragma unroll
        for (int ks = 0; ks < 4; ks++) {
            unsigned ah[2][4];
#pragma unroll
            for (int mt = 0; mt < 2; mt++) {
                unsigned row = wm * 32 + mt * 16 + (grp & 1) * 8 + lam;
                unsigned col = ks * 8 + (grp >> 1) * 4;
                ldsm4(ah[mt], baseA + (row * 36 + col) * 4);
            }
#pragma unroll
            for (int ntp = 0; ntp < 8; ntp += 2) {
                unsigned row = wn * 64 + (ntp + (grp >> 1)) * 8 + lam;
                unsigned col = ks * 8 + (grp & 1) * 4;
                unsigned bh[4];
                ldsm4(bh, baseB + (row * 36 + col) * 4);
#pragma unroll
                for (int mt = 0; mt < 2; mt++) {
                    mma8(acc[mt][ntp], ah[mt], bh[0], bh[1]);
                    mma8(acc[mt][ntp + 1], ah[mt], bh[2], bh[3]);
                }
            }
        }
        __syncthreads();
    }
#pragma unroll
    for (int mt = 0; mt < 2; mt++) {
        int row = m0 + wm * 32 + mt * 16 + g;
        float bi0 = bias[row], bi1 = bias[row + 8];
#pragma unroll
        for (int nt = 0; nt < 8; nt++) {
            int col = t0 + wn * 64 + nt * 8 + 2 * q;
            size_t i0 = ((size_t)b * CHN + row) * T + col;
            size_t i1 = ((size_t)b * CHN + row + 8) * T + col;
            float2 r0 = *(const float2*)&resid[i0];
            float2 r1 = *(const float2*)&resid[i1];
            *(float2*)&outp[i0] = make_float2(acc[mt][nt][0] + bi0 + r0.x,
                                              acc[mt][nt][1] + bi0 + r0.y);
            *(float2*)&outp[i1] = make_float2(acc[mt][nt][2] + bi1 + r1.x,
                                              acc[mt][nt][3] + bi1 + r1.y);
        }
    }
}

// ---------------------------------------------------------------------------
// Flash attention, fp16: QK^T split (hh+hl+lh), PV = P_hi x (V_hi + V_lo).
// Block = 128 queries x 1 head, 8 warps x 16 rows; softmax warp-local.
__global__ void __launch_bounds__(256, 2) attn_mma() {
    extern __shared__ unsigned sma[];
    unsigned* Ps  = sma;              // [128][36] Qhi in prologue, then P
    unsigned* Qlo = sma + 4608;       // [128][36] prologue only
    unsigned* Khi = sma + 4608;       // [64][36] overlays Qlo after prologue
    unsigned* Klo = sma + 6912;       // [64][36]
    unsigned* Vh  = sma + 9216;       // [64][36]
    unsigned* Vl  = sma + 11520;      // [64][36]; total 13824 words
    unsigned basePs = (unsigned)__cvta_generic_to_shared(Ps);
    unsigned baseQl = (unsigned)__cvta_generic_to_shared(Qlo);
    unsigned baseKh = (unsigned)__cvta_generic_to_shared(Khi);
    unsigned baseKl = (unsigned)__cvta_generic_to_shared(Klo);
    unsigned baseVh = (unsigned)__cvta_generic_to_shared(Vh);
    unsigned baseVl = (unsigned)__cvta_generic_to_shared(Vl);

    int t0 = blockIdx.x * 128, head = blockIdx.y;
    int b = head >> 3, hh = head & 7;
    const float* qb = g_qkv + ((size_t)b * M3 + hh * 192) * T;
    const float* kb = qb + (size_t)64 * T;
    const float* vb = qb + (size_t)128 * T;
    int tid = threadIdx.x, lane = tid & 31, wid = tid >> 5;
    int g = lane >> 2, q = lane & 3, rb = wid * 16;
    int grp = lane >> 3, lam = lane & 7;
    int c4 = tid & 15;

    {   // Q fill: [c][t] -> [t][c] * 0.125, split fp16
#pragma unroll
        for (int it = 0; it < 2; it++) {
            int t4 = (tid >> 4) + it * 16;
            float4 r[4];
#pragma unroll
            for (int j = 0; j < 4; j++) {
                r[j] = *(const float4*)&qb[(size_t)(4 * c4 + j) * T + t0 + 4 * t4];
                r[j].x *= 0.125f; r[j].y *= 0.125f; r[j].z *= 0.125f; r[j].w *= 0.125f;
            }
#pragma unroll
            for (int jp = 0; jp < 4; jp++) {
                unsigned h01, l01, h23, l23;
                split2((&r[0].x)[jp], (&r[1].x)[jp], h01, l01);
                split2((&r[2].x)[jp], (&r[3].x)[jp], h23, l23);
                *(uint2*)&Ps[(4 * t4 + jp) * 36 + 2 * c4] = make_uint2(h01, h23);
                *(uint2*)&Qlo[(4 * t4 + jp) * 36 + 2 * c4] = make_uint2(l01, l23);
            }
        }
    }
    __syncthreads();
    unsigned qh[4][4], ql[4][4];
#pragma unroll
    for (int ks = 0; ks < 4; ks++) {
        unsigned row = rb + (grp & 1) * 8 + lam;
        unsigned col = ks * 8 + (grp >> 1) * 4;
        unsigned off = (row * 36 + col) * 4;
        ldsm4(qh[ks], basePs + off);
        ldsm4(ql[ks], baseQl + off);
    }

    float o[8][4];
#pragma unroll
    for (int nt = 0; nt < 8; nt++)
#pragma unroll
        for (int i = 0; i < 4; i++) o[nt][i] = 0.f;
    float m_a = -1e30f, m_b = -1e30f, l_a = 0.f, l_b = 0.f;

    for (int s0 = 0; s0 < T; s0 += 64) {
        __syncthreads();   // Qlo frags read (iter 0) / prev PV reads done
        {   // K fill: [c][s] -> [s][c] split; V fill: [c][s] split, direct
            int s4 = tid >> 4;
            float4 r[4];
#pragma unroll
            for (int j = 0; j < 4; j++)
                r[j] = *(const float4*)&kb[(size_t)(4 * c4 + j) * T + s0 + 4 * s4];
#pragma unroll
            for (int jp = 0; jp < 4; jp++) {
                unsigned h01, l01, h23, l23;
                split2((&r[0].x)[jp], (&r[1].x)[jp], h01, l01);
                split2((&r[2].x)[jp], (&r[3].x)[jp], h23, l23);
                *(uint2*)&Khi[(4 * s4 + jp) * 36 + 2 * c4] = make_uint2(h01, h23);
                *(uint2*)&Klo[(4 * s4 + jp) * 36 + 2 * c4] = make_uint2(l01, l23);
            }
#pragma unroll
            for (int i = 0; i < 4; i++) {
                int idx = tid + i * 256, c = idx >> 4, sv = idx & 15;
                float4 v = *(const float4*)&vb[(size_t)c * T + s0 + 4 * sv];
                unsigned h01, l01, h23, l23;
                split2(v.x, v.y, h01, l01);
                split2(v.z, v.w, h23, l23);
                *(uint2*)&Vh[c * 36 + 2 * sv] = make_uint2(h01, h23);
                *(uint2*)&Vl[c * 36 + 2 * sv] = make_uint2(l01, l23);
            }
        }
        __syncthreads();

        float sacc[8][4];
#pragma unroll
        for (int nt = 0; nt < 8; nt++)
#pragma unroll
            for (int i = 0; i < 4; i++) sacc[nt][i] = 0.f;
#pragma unroll
        for (int ks = 0; ks < 4; ks++) {
#pragma unroll
            for (int ntp = 0; ntp < 8; ntp += 2) {
                unsigned row = (ntp + (grp >> 1)) * 8 + lam;
                unsigned col = ks * 8 + (grp & 1) * 4;
                unsigned off = (row * 36 + col) * 4;
                unsigned kh[4], kl[4];
                ldsm4(kh, baseKh + off);
                ldsm4(kl, baseKl + off);
                mma16(sacc[ntp],     qh[ks], kh[0], kh[1]);
                mma16(sacc[ntp],     qh[ks], kl[0], kl[1]);
                mma16(sacc[ntp],     ql[ks], kh[0], kh[1]);
                mma16(sacc[ntp + 1], qh[ks], kh[2], kh[3]);
                mma16(sacc[ntp + 1], qh[ks], kl[2], kl[3]);
                mma16(sacc[ntp + 1], ql[ks], kh[2], kh[3]);
            }
        }

        float mx_a = -1e30f, mx_b = -1e30f;
#pragma unroll
        for (int nt = 0; nt < 8; nt++) {
            mx_a = fmaxf(mx_a, fmaxf(sacc[nt][0], sacc[nt][1]));
            mx_b = fmaxf(mx_b, fmaxf(sacc[nt][2], sacc[nt][3]));
        }
        mx_a = fmaxf(mx_a, __shfl_xor_sync(~0u, mx_a, 1));
        mx_a = fmaxf(mx_a, __shfl_xor_sync(~0u, mx_a, 2));
        mx_b = fmaxf(mx_b, __shfl_xor_sync(~0u, mx_b, 1));
        mx_b = fmaxf(mx_b, __shfl_xor_sync(~0u, mx_b, 2));
        float mn_a = fmaxf(m_a, mx_a), mn_b = fmaxf(m_b, mx_b);
        float ca = __expf(m_a - mn_a), cb = __expf(m_b - mn_b);
        float sum_a = 0.f, sum_b = 0.f;
#pragma unroll
        for (int nt = 0; nt < 8; nt++) {
            float p0 = __expf(sacc[nt][0] - mn_a), p1 = __expf(sacc[nt][1] - mn_a);
            float p2 = __expf(sacc[nt][2] - mn_b), p3 = __expf(sacc[nt][3] - mn_b);
            sum_a += p0 + p1; sum_b += p2 + p3;
            Ps[(rb + g) * 36 + nt * 4 + q]     = pack2h(p0, p1);
            Ps[(rb + g + 8) * 36 + nt * 4 + q] = pack2h(p2, p3);
        }
        sum_a += __shfl_xor_sync(~0u, sum_a, 1);
        sum_a += __shfl_xor_sync(~0u, sum_a, 2);
        sum_b += __shfl_xor_sync(~0u, sum_b, 1);
        sum_b += __shfl_xor_sync(~0u, sum_b, 2);
        m_a = mn_a; m_b = mn_b;
        l_a = l_a * ca + sum_a; l_b = l_b * cb + sum_b;
#pragma unroll
        for (int nt = 0; nt < 8; nt++) {
            o[nt][0] *= ca; o[nt][1] *= ca; o[nt][2] *= cb; o[nt][3] *= cb;
        }
        __syncwarp();
#pragma unroll
        for (int ks = 0; ks < 4; ks++) {
            unsigned ph[4];
            {
                unsigned row = rb + (grp & 1) * 8 + lam;
                unsigned col = ks * 8 + (grp >> 1) * 4;
                ldsm4(ph, basePs + (row * 36 + col) * 4);
            }
#pragma unroll
            for (int ntp = 0; ntp < 8; ntp += 2) {
                unsigned row = (ntp + (grp >> 1)) * 8 + lam;
                unsigned col = ks * 8 + (grp & 1) * 4;
                unsigned off = (row * 36 + col) * 4;
                unsigned vh[4], vl[4];
                ldsm4(vh, baseVh + off);
                ldsm4(vl, baseVl + off);
                mma16(o[ntp],     ph, vh[0], vh[1]);
                mma16(o[ntp],     ph, vl[0], vl[1]);
                mma16(o[ntp + 1], ph, vh[2], vh[3]);
                mma16(o[ntp + 1], ph, vl[2], vl[3]);
            }
        }
    }

    float inv_a = 1.f / l_a, inv_b = 1.f / l_b;
    float* ab = g_a + ((size_t)b * CHN + hh * 64) * T;
#pragma unroll
    for (int nt = 0; nt < 8; nt++) {
        int c0 = nt * 8 + 2 * q;
        ab[(size_t)c0 * T + t0 + rb + g]           = o[nt][0] * inv_a;
        ab[(size_t)(c0 + 1) * T + t0 + rb + g]     = o[nt][1] * inv_a;
        ab[(size_t)c0 * T + t0 + rb + g + 8]       = o[nt][2] * inv_b;
        ab[(size_t)(c0 + 1) * T + t0 + rb + g + 8] = o[nt][3] * inv_b;
    }
}

// ---------------------------------------------------------------------------
extern "C" void kernel_launch(void* const* d_in, const int* in_sizes, int n_in,
                              void* d_out, int out_size) {
    const float* x      = (const float*)d_in[0];
    const float* nw     = (const float*)d_in[1];
    const float* qkv_w  = (const float*)d_in[2];
    const float* qkv_b  = (const float*)d_in[3];
    const float* proj_w = (const float*)d_in[4];
    const float* proj_b = (const float*)d_in[5];
    float* out = (float*)d_out;

    const int QKV_SMEM  = 10240 * 4;  // 40960
    const int PROJ_SMEM = 9216 * 4;   // 36864
    const int ATT_SMEM  = 13824 * 4;  // 55296
    static bool init = false;
    if (!init) {
        cudaFuncSetAttribute(qkv_mma,  cudaFuncAttributeMaxDynamicSharedMemorySize, QKV_SMEM);
        cudaFuncSetAttribute(proj_mma, cudaFuncAttributeMaxDynamicSharedMemorySize, PROJ_SMEM);
        cudaFuncSetAttribute(attn_mma, cudaFuncAttributeMaxDynamicSharedMemorySize, ATT_SMEM);
        cudaFuncSetAttribute(qkv_mma,  cudaFuncAttributePreferredSharedMemoryCarveout, 100);
        cudaFuncSetAttribute(proj_mma, cudaFuncAttributePreferredSharedMemoryCarveout, 100);
        cudaFuncSetAttribute(attn_mma, cudaFuncAttributePreferredSharedMemoryCarveout, 100);
        init = true;
    }
    rms_kernel<<<256, 256>>>(x);
    qkv_mma<<<dim3(32, 12, 2), 256, QKV_SMEM>>>(qkv_w, x, nw, qkv_b);
    attn_mma<<<dim3(32, 16), 256, ATT_SMEM>>>();
    proj_mma<<<dim3(32, 4, 2), 256, PROJ_SMEM>>>(proj_w, proj_b, x, out);
}

// round 10
// speedup vs baseline: 1.8810x; 1.2637x over previous
#include <cuda_runtime.h>
#include <cuda_fp16.h>
#include <math.h>

#define T   4096
#define CHN 512
#define M3  1536

__device__ float g_ir[2 * T];
__device__ float g_a[(size_t)2 * CHN * T];
__device__ unsigned g_xh[(size_t)2 * T * 256], g_xl[(size_t)2 * T * 256];
__device__ unsigned g_wh[(size_t)M3 * 256],    g_wl[(size_t)M3 * 256];
__device__ unsigned g_qkh[(size_t)2 * M3 * 2048], g_qkl[(size_t)2 * M3 * 2048];
__device__ unsigned g_qTh[(size_t)16 * T * 32], g_qTl[(size_t)16 * T * 32];
__device__ unsigned g_kTh[(size_t)16 * T * 32], g_kTl[(size_t)16 * T * 32];

__device__ __forceinline__ unsigned tf32r(float x) {
    unsigned r; asm("cvt.rna.tf32.f32 %0, %1;" : "=r"(r) : "f"(x)); return r;
}
__device__ __forceinline__ void mma8(float c[4], const unsigned a[4],
                                     unsigned b0, unsigned b1) {
    asm volatile("mma.sync.aligned.m16n8k8.row.col.f32.tf32.tf32.f32 "
                 "{%0,%1,%2,%3}, {%4,%5,%6,%7}, {%8,%9}, {%0,%1,%2,%3};"
                 : "+f"(c[0]), "+f"(c[1]), "+f"(c[2]), "+f"(c[3])
                 : "r"(a[0]), "r"(a[1]), "r"(a[2]), "r"(a[3]), "r"(b0), "r"(b1));
}
__device__ __forceinline__ void mma16(float c[4], const unsigned a[4],
                                      unsigned b0, unsigned b1) {
    asm volatile("mma.sync.aligned.m16n8k16.row.col.f32.f16.f16.f32 "
                 "{%0,%1,%2,%3}, {%4,%5,%6,%7}, {%8,%9}, {%0,%1,%2,%3};"
                 : "+f"(c[0]), "+f"(c[1]), "+f"(c[2]), "+f"(c[3])
                 : "r"(a[0]), "r"(a[1]), "r"(a[2]), "r"(a[3]), "r"(b0), "r"(b1));
}
__device__ __forceinline__ void ldsm4(unsigned r[4], unsigned addr) {
    asm volatile("ldmatrix.sync.aligned.m8n8.x4.shared.b16 {%0,%1,%2,%3}, [%4];"
                 : "=r"(r[0]), "=r"(r[1]), "=r"(r[2]), "=r"(r[3]) : "r"(addr));
}
__device__ __forceinline__ void split2(float v0, float v1, unsigned& hi, unsigned& lo) {
    __half h0 = __float2half_rn(v0), h1 = __float2half_rn(v1);
    __half2 hh = __halves2half2(h0, h1);
    hi = *reinterpret_cast<unsigned*>(&hh);
    __half l0 = __float2half_rn(v0 - __half2float(h0));
    __half l1 = __float2half_rn(v1 - __half2float(h1));
    __half2 ll = __halves2half2(l0, l1);
    lo = *reinterpret_cast<unsigned*>(&ll);
}
__device__ __forceinline__ unsigned pack2h(float a, float b) {
    __half2 p = __floats2half2_rn(a, b);
    return *reinterpret_cast<unsigned*>(&p);
}

// ---------------------------------------------------------------------------
__global__ void __launch_bounds__(256) rms_kernel(const float* __restrict__ x) {
    __shared__ float red[8][32];
    int l = threadIdx.x & 31, w = threadIdx.x >> 5;
    int i = blockIdx.x * 32 + l;
    int b = i >> 12, t = i & (T - 1);
    const float* xp = x + (size_t)b * CHN * T + t + (size_t)(w * 64) * T;
    float s = 0.f;
#pragma unroll 16
    for (int j = 0; j < 64; j++) { float v = xp[(size_t)j * T]; s = fmaf(v, v, s); }
    red[w][l] = s;
    __syncthreads();
    if (w == 0) {
        float tot = red[0][l];
#pragma unroll
        for (int k = 1; k < 8; k++) tot += red[k][l];
        g_ir[i] = 22.62741699796952f * rsqrtf(tot * (1.f / CHN) + 1e-8f);
    }
}

// W -> split fp16 (x256), [o][c] pairs along c
__global__ void __launch_bounds__(256) prep_w(const float* __restrict__ W) {
    int i = blockIdx.x * 256 + threadIdx.x;   // float4 index, 196608 total
    float4 w = *(const float4*)&W[(size_t)i * 4];
    unsigned h01, l01, h23, l23;
    split2(w.x * 256.f, w.y * 256.f, h01, l01);
    split2(w.z * 256.f, w.w * 256.f, h23, l23);
    *(uint2*)&g_wh[2 * (size_t)i] = make_uint2(h01, h23);
    *(uint2*)&g_wl[2 * (size_t)i] = make_uint2(l01, l23);
}

// x*nw*ir -> split fp16, transposed to [b][t][c] pairs along c
__global__ void __launch_bounds__(256) prep_x(const float* __restrict__ x,
                                              const float* __restrict__ nw) {
    __shared__ float sx[64][65];
    int t0 = blockIdx.x * 64, c0 = blockIdx.y * 64, b = blockIdx.z;
    int tid = threadIdx.x;
#pragma unroll
    for (int i = 0; i < 4; i++) {
        int idx = tid + i * 256;               // 1024 float4
        int c = idx >> 4, f = idx & 15;
        float4 v = *(const float4*)&x[((size_t)b * CHN + c0 + c) * T + t0 + 4 * f];
        float s = nw[c0 + c];
        float4 ir = *(const float4*)&g_ir[b * T + t0 + 4 * f];
        sx[c][4 * f + 0] = v.x * s * ir.x; sx[c][4 * f + 1] = v.y * s * ir.y;
        sx[c][4 * f + 2] = v.z * s * ir.z; sx[c][4 * f + 3] = v.w * s * ir.w;
    }
    __syncthreads();
#pragma unroll
    for (int i = 0; i < 8; i++) {
        int idx = tid + i * 256;               // 2048 words
        int t = idx >> 5, cp = idx & 31;
        unsigned h, l;
        split2(sx[2 * cp][t], sx[2 * cp + 1][t], h, l);
        size_t dst = ((size_t)b * T + t0 + t) * 256 + (c0 >> 1) + cp;
        g_xh[dst] = h; g_xl[dst] = l;
    }
}

// ---------------------------------------------------------------------------
// QKV GEMM, fp16 split. Fills are pure copies from pre-split gmem.
// Epilogue emits split fp16 [row][t] pairs (q rows pre-scaled 0.125).
__global__ void __launch_bounds__(256, 2) qkv_mma(const float* __restrict__ bias) {
    extern __shared__ unsigned smg[];
    unsigned* Ahi = smg;              // [128][20]
    unsigned* Alo = smg + 2560;
    unsigned* Bhi = smg + 5120;
    unsigned* Blo = smg + 7680;
    unsigned baseAh = (unsigned)__cvta_generic_to_shared(Ahi);
    unsigned baseAl = (unsigned)__cvta_generic_to_shared(Alo);
    unsigned baseBh = (unsigned)__cvta_generic_to_shared(Bhi);
    unsigned baseBl = (unsigned)__cvta_generic_to_shared(Blo);

    int b = blockIdx.z, m0 = blockIdx.y * 128, t0 = blockIdx.x * 128;
    int tid = threadIdx.x, lane = tid & 31, wid = tid >> 5;
    int wm = wid >> 1, wn = wid & 1, g = lane >> 2, q = lane & 3;
    int grp = lane >> 3, lam = lane & 7;

    float acc[2][8][4];
#pragma unroll
    for (int mt = 0; mt < 2; mt++)
#pragma unroll
        for (int nt = 0; nt < 8; nt++)
#pragma unroll
            for (int i = 0; i < 4; i++) acc[mt][nt][i] = 0.f;

    for (int k0 = 0; k0 < CHN; k0 += 32) {
#pragma unroll
        for (int i = 0; i < 2; i++) {
            int idx = tid + i * 256, row = idx >> 2, u = idx & 3;  // 512 uint4
            size_t sa = (size_t)(m0 + row) * 256 + (k0 >> 1) + 4 * u;
            *(uint4*)&Ahi[row * 20 + 4 * u] = *(const uint4*)&g_wh[sa];
            *(uint4*)&Alo[row * 20 + 4 * u] = *(const uint4*)&g_wl[sa];
            size_t sb = ((size_t)b * T + t0 + row) * 256 + (k0 >> 1) + 4 * u;
            *(uint4*)&Bhi[row * 20 + 4 * u] = *(const uint4*)&g_xh[sb];
            *(uint4*)&Blo[row * 20 + 4 * u] = *(const uint4*)&g_xl[sb];
        }
        __syncthreads();
#pragma unroll
        for (int ks = 0; ks < 2; ks++) {
            unsigned ah[2][4], al[2][4];
#pragma unroll
            for (int mt = 0; mt < 2; mt++) {
                unsigned row = wm * 32 + mt * 16 + (grp & 1) * 8 + lam;
                unsigned col = ks * 8 + (grp >> 1) * 4;
                unsigned off = (row * 20 + col) * 4;
                ldsm4(ah[mt], baseAh + off);
                ldsm4(al[mt], baseAl + off);
            }
#pragma unroll
            for (int ntp = 0; ntp < 8; ntp += 2) {
                unsigned row = wn * 64 + (ntp + (grp >> 1)) * 8 + lam;
                unsigned col = ks * 8 + (grp & 1) * 4;
                unsigned off = (row * 20 + col) * 4;
                unsigned bh[4], bl[4];
                ldsm4(bh, baseBh + off);
                ldsm4(bl, baseBl + off);
#pragma unroll
                for (int mt = 0; mt < 2; mt++) {
                    mma16(acc[mt][ntp],     ah[mt], bh[0], bh[1]);
                    mma16(acc[mt][ntp],     ah[mt], bl[0], bl[1]);
                    mma16(acc[mt][ntp],     al[mt], bh[0], bh[1]);
                    mma16(acc[mt][ntp + 1], ah[mt], bh[2], bh[3]);
                    mma16(acc[mt][ntp + 1], ah[mt], bl[2], bl[3]);
                    mma16(acc[mt][ntp + 1], al[mt], bh[2], bh[3]);
                }
            }
        }
        __syncthreads();
    }
#pragma unroll
    for (int mt = 0; mt < 2; mt++) {
        int row = m0 + wm * 32 + mt * 16 + g;
        float bi0 = bias[row], bi1 = bias[row + 8];
        float s0 = ((row % 192) < 64) ? 0.125f : 1.f;
        float s1 = (((row + 8) % 192) < 64) ? 0.125f : 1.f;
#pragma unroll
        for (int nt = 0; nt < 8; nt++) {
            int col = t0 + wn * 64 + nt * 8 + 2 * q;
            float v0 = (acc[mt][nt][0] * (1.f / 256.f) + bi0) * s0;
            float v1 = (acc[mt][nt][1] * (1.f / 256.f) + bi0) * s0;
            float v2 = (acc[mt][nt][2] * (1.f / 256.f) + bi1) * s1;
            float v3 = (acc[mt][nt][3] * (1.f / 256.f) + bi1) * s1;
            unsigned h, l;
            split2(v0, v1, h, l);
            size_t d0 = ((size_t)b * M3 + row) * 2048 + (col >> 1);
            g_qkh[d0] = h; g_qkl[d0] = l;
            split2(v2, v3, h, l);
            size_t d1 = ((size_t)b * M3 + row + 8) * 2048 + (col >> 1);
            g_qkh[d1] = h; g_qkl[d1] = l;
        }
    }
}

// ---------------------------------------------------------------------------
// transpose q,k from [c][t]-pairs to [t][c]-pairs (hi+lo), per (b,h,q|k,t-tile)
__global__ void __launch_bounds__(256) prep_qk() {
    __shared__ unsigned sH[64][33], sL[64][33];
    int t0 = blockIdx.x * 64, bh = blockIdx.y, qk = blockIdx.z;
    int b = bh >> 3, hh = bh & 7;
    size_t src = ((size_t)b * M3 + hh * 192 + qk * 64) * 2048 + (t0 >> 1);
    int tid = threadIdx.x;
#pragma unroll
    for (int i = 0; i < 8; i++) {
        int idx = tid + i * 256, c = idx >> 5, tp = idx & 31;
        sH[c][tp] = g_qkh[src + (size_t)c * 2048 + tp];
        sL[c][tp] = g_qkl[src + (size_t)c * 2048 + tp];
    }
    __syncthreads();
    unsigned* dH = qk ? g_kTh : g_qTh;
    unsigned* dL = qk ? g_kTl : g_qTl;
    size_t obase = ((size_t)bh * T + t0) * 32;
#pragma unroll
    for (int i = 0; i < 8; i++) {
        int idx = tid + i * 256, tl = idx >> 5, cp = idx & 31;
        unsigned A = sH[2 * cp][tl >> 1], B = sH[2 * cp + 1][tl >> 1];
        dH[obase + (size_t)tl * 32 + cp] =
            (tl & 1) ? __byte_perm(A, B, 0x7632) : __byte_perm(A, B, 0x5410);
        A = sL[2 * cp][tl >> 1]; B = sL[2 * cp + 1][tl >> 1];
        dL[obase + (size_t)tl * 32 + cp] =
            (tl & 1) ? __byte_perm(A, B, 0x7632) : __byte_perm(A, B, 0x5410);
    }
}

// ---------------------------------------------------------------------------
// Flash attention, fp16: QK^T split (hh+hl+lh), PV single (V hi only).
// All smem fills are pure uint4 copies of pre-split data.
__global__ void __launch_bounds__(256, 2) attn_mma() {
    extern __shared__ unsigned sma[];
    unsigned* Ps  = sma;              // [128][36] Qhi in prologue, then P
    unsigned* Qlo = sma + 4608;       // prologue only
    unsigned* Khi = sma + 4608;       // [64][36] overlays Qlo
    unsigned* Klo = sma + 6912;       // [64][36]
    unsigned* Vh  = sma + 9216;       // [64][36]; total 11520 words
    unsigned basePs = (unsigned)__cvta_generic_to_shared(Ps);
    unsigned baseQl = (unsigned)__cvta_generic_to_shared(Qlo);
    unsigned baseKh = (unsigned)__cvta_generic_to_shared(Khi);
    unsigned baseKl = (unsigned)__cvta_generic_to_shared(Klo);
    unsigned baseVh = (unsigned)__cvta_generic_to_shared(Vh);

    int t0 = blockIdx.x * 128, head = blockIdx.y;
    int b = head >> 3, hh = head & 7;
    int tid = threadIdx.x, lane = tid & 31, wid = tid >> 5;
    int g = lane >> 2, q = lane & 3, rb = wid * 16;
    int grp = lane >> 3, lam = lane & 7;

    const unsigned* qThp = g_qTh + ((size_t)head * T + t0) * 32;
    const unsigned* qTlp = g_qTl + ((size_t)head * T + t0) * 32;
    const unsigned* kThp = g_kTh + (size_t)head * T * 32;
    const unsigned* kTlp = g_kTl + (size_t)head * T * 32;
    const unsigned* vhp  = g_qkh + ((size_t)b * M3 + hh * 192 + 128) * 2048;

#pragma unroll
    for (int i = 0; i < 4; i++) {
        int idx = tid + i * 256, row = idx >> 3, u = idx & 7;   // 1024 uint4 each
        *(uint4*)&Ps[row * 36 + 4 * u]  = *(const uint4*)&qThp[(size_t)row * 32 + 4 * u];
        *(uint4*)&Qlo[row * 36 + 4 * u] = *(const uint4*)&qTlp[(size_t)row * 32 + 4 * u];
    }
    __syncthreads();
    unsigned qh[4][4], ql[4][4];
#pragma unroll
    for (int ks = 0; ks < 4; ks++) {
        unsigned row = rb + (grp & 1) * 8 + lam;
        unsigned col = ks * 8 + (grp >> 1) * 4;
        unsigned off = (row * 36 + col) * 4;
        ldsm4(qh[ks], basePs + off);
        ldsm4(ql[ks], baseQl + off);
    }

    float o[8][4];
#pragma unroll
    for (int nt = 0; nt < 8; nt++)
#pragma unroll
        for (int i = 0; i < 4; i++) o[nt][i] = 0.f;
    float m_a = -1e30f, m_b = -1e30f, l_a = 0.f, l_b = 0.f;

    for (int s0 = 0; s0 < T; s0 += 64) {
        __syncthreads();
#pragma unroll
        for (int i = 0; i < 2; i++) {
            int idx = tid + i * 256, row = idx >> 3, u = idx & 7;  // 512 uint4 each
            *(uint4*)&Khi[row * 36 + 4 * u] =
                *(const uint4*)&kThp[(size_t)(s0 + row) * 32 + 4 * u];
            *(uint4*)&Klo[row * 36 + 4 * u] =
                *(const uint4*)&kTlp[(size_t)(s0 + row) * 32 + 4 * u];
            *(uint4*)&Vh[row * 36 + 4 * u] =
                *(const uint4*)&vhp[(size_t)row * 2048 + (s0 >> 1) + 4 * u];
        }
        __syncthreads();

        float sacc[8][4];
#pragma unroll
        for (int nt = 0; nt < 8; nt++)
#pragma unroll
            for (int i = 0; i < 4; i++) sacc[nt][i] = 0.f;
#pragma unroll
        for (int ks = 0; ks < 4; ks++) {
#pragma unroll
            for (int ntp = 0; ntp < 8; ntp += 2) {
                unsigned row = (ntp + (grp >> 1)) * 8 + lam;
                unsigned col = ks * 8 + (grp & 1) * 4;
                unsigned off = (row * 36 + col) * 4;
                unsigned kh[4], kl[4];
                ldsm4(kh, baseKh + off);
                ldsm4(kl, baseKl + off);
                mma16(sacc[ntp],     qh[ks], kh[0], kh[1]);
                mma16(sacc[ntp],     qh[ks], kl[0], kl[1]);
                mma16(sacc[ntp],     ql[ks], kh[0], kh[1]);
                mma16(sacc[ntp + 1], qh[ks], kh[2], kh[3]);
                mma16(sacc[ntp + 1], qh[ks], kl[2], kl[3]);
                mma16(sacc[ntp + 1], ql[ks], kh[2], kh[3]);
            }
        }

        float mx_a = -1e30f, mx_b = -1e30f;
#pragma unroll
        for (int nt = 0; nt < 8; nt++) {
            mx_a = fmaxf(mx_a, fmaxf(sacc[nt][0], sacc[nt][1]));
            mx_b = fmaxf(mx_b, fmaxf(sacc[nt][2], sacc[nt][3]));
        }
        mx_a = fmaxf(mx_a, __shfl_xor_sync(~0u, mx_a, 1));
        mx_a = fmaxf(mx_a, __shfl_xor_sync(~0u, mx_a, 2));
        mx_b = fmaxf(mx_b, __shfl_xor_sync(~0u, mx_b, 1));
        mx_b = fmaxf(mx_b, __shfl_xor_sync(~0u, mx_b, 2));
        float mn_a = fmaxf(m_a, mx_a), mn_b = fmaxf(m_b, mx_b);
        float ca = __expf(m_a - mn_a), cb = __expf(m_b - mn_b);
        float sum_a = 0.f, sum_b = 0.f;
#pragma unroll
        for (int nt = 0; nt < 8; nt++) {
            float p0 = __expf(sacc[nt][0] - mn_a), p1 = __expf(sacc[nt][1] - mn_a);
            float p2 = __expf(sacc[nt][2] - mn_b), p3 = __expf(sacc[nt][3] - mn_b);
            sum_a += p0 + p1; sum_b += p2 + p3;
            Ps[(rb + g) * 36 + nt * 4 + q]     = pack2h(p0, p1);
            Ps[(rb + g + 8) * 36 + nt * 4 + q] = pack2h(p2, p3);
        }
        sum_a += __shfl_xor_sync(~0u, sum_a, 1);
        sum_a += __shfl_xor_sync(~0u, sum_a, 2);
        sum_b += __shfl_xor_sync(~0u, sum_b, 1);
        sum_b += __shfl_xor_sync(~0u, sum_b, 2);
        m_a = mn_a; m_b = mn_b;
        l_a = l_a * ca + sum_a; l_b = l_b * cb + sum_b;
#pragma unroll
        for (int nt = 0; nt < 8; nt++) {
            o[nt][0] *= ca; o[nt][1] *= ca; o[nt][2] *= cb; o[nt][3] *= cb;
        }
        __syncwarp();
#pragma unroll
        for (int ks = 0; ks < 4; ks++) {
            unsigned ph[4];
            {
                unsigned row = rb + (grp & 1) * 8 + lam;
                unsigned col = ks * 8 + (grp >> 1) * 4;
                ldsm4(ph, basePs + (row * 36 + col) * 4);
            }
#pragma unroll
            for (int ntp = 0; ntp < 8; ntp += 2) {
                unsigned row = (ntp + (grp >> 1)) * 8 + lam;
                unsigned col = ks * 8 + (grp & 1) * 4;
                unsigned vh[4];
                ldsm4(vh, baseVh + (row * 36 + col) * 4);
                mma16(o[ntp],     ph, vh[0], vh[1]);
                mma16(o[ntp + 1], ph, vh[2], vh[3]);
            }
        }
    }

    float inv_a = 1.f / l_a, inv_b = 1.f / l_b;
    float* ab = g_a + ((size_t)b * CHN + hh * 64) * T;
#pragma unroll
    for (int nt = 0; nt < 8; nt++) {
        int c0 = nt * 8 + 2 * q;
        ab[(size_t)c0 * T + t0 + rb + g]           = o[nt][0] * inv_a;
        ab[(size_t)(c0 + 1) * T + t0 + rb + g]     = o[nt][1] * inv_a;
        ab[(size_t)c0 * T + t0 + rb + g + 8]       = o[nt][2] * inv_b;
        ab[(size_t)(c0 + 1) * T + t0 + rb + g + 8] = o[nt][3] * inv_b;
    }
}

// ---------------------------------------------------------------------------
// proj GEMM + bias + residual: single tf32 (proven path).
__global__ void __launch_bounds__(256, 2) proj_mma(
        const float* __restrict__ W, const float* __restrict__ bias,
        const float* __restrict__ resid, float* __restrict__ outp)
{
    extern __shared__ unsigned smg[];
    unsigned* Ahi = smg;              // [128][36]
    unsigned* Bhi = smg + 4608;       // [128][36]
    unsigned baseA = (unsigned)__cvta_generic_to_shared(Ahi);
    unsigned baseB = (unsigned)__cvta_generic_to_shared(Bhi);

    int b = blockIdx.z, m0 = blockIdx.y * 128, t0 = blockIdx.x * 128;
    int tid = threadIdx.x, lane = tid & 31, wid = tid >> 5;
    int wm = wid >> 1, wn = wid & 1, g = lane >> 2, q = lane & 3;
    int grp = lane >> 3, lam = lane & 7;
    const float* Xb = (const float*)g_a + (size_t)b * CHN * T;
    int bc4 = tid & 7, bt4 = tid >> 3;

    float acc[2][8][4];
#pragma unroll
    for (int mt = 0; mt < 2; mt++)
#pragma unroll
        for (int nt = 0; nt < 8; nt++)
#pragma unroll
            for (int i = 0; i < 4; i++) acc[mt][nt][i] = 0.f;

    for (int k0 = 0; k0 < CHN; k0 += 32) {
#pragma unroll
        for (int i = 0; i < 4; i++) {
            int idx = tid + i * 256, row = idx >> 3, c4 = idx & 7;
            float4 w = *(const float4*)&W[(size_t)(m0 + row) * CHN + k0 + 4 * c4];
            *(uint4*)&Ahi[row * 36 + 4 * c4] =
                make_uint4(tf32r(w.x), tf32r(w.y), tf32r(w.z), tf32r(w.w));
        }
        {
            float4 r[4];
#pragma unroll
            for (int j = 0; j < 4; j++)
                r[j] = *(const float4*)&Xb[(size_t)(k0 + 4 * bc4 + j) * T + t0 + 4 * bt4];
#pragma unroll
            for (int jp = 0; jp < 4; jp++)
                *(uint4*)&Bhi[(4 * bt4 + jp) * 36 + 4 * bc4] =
                    make_uint4(tf32r((&r[0].x)[jp]), tf32r((&r[1].x)[jp]),
                               tf32r((&r[2].x)[jp]), tf32r((&r[3].x)[jp]));
        }
        __syncthreads();
#pragma unroll
        for (int ks = 0; ks < 4; ks++) {
            unsigned ah[2][4];
#pragma unroll
            for (int mt = 0; mt < 2; mt++) {
                unsigned row = wm * 32 + mt * 16 + (grp & 1) * 8 + lam;
                unsigned col = ks * 8 + (grp >> 1) * 4;
                ldsm4(ah[mt], baseA + (row * 36 + col) * 4);
            }
#pragma unroll
            for (int ntp = 0; ntp < 8; ntp += 2) {
                unsigned row = wn * 64 + (ntp + (grp >> 1)) * 8 + lam;
                unsigned col = ks * 8 + (grp & 1) * 4;
                unsigned bh[4];
                ldsm4(bh, baseB + (row * 36 + col) * 4);
#pragma unroll
                for (int mt = 0; mt < 2; mt++) {
                    mma8(acc[mt][ntp], ah[mt], bh[0], bh[1]);
                    mma8(acc[mt][ntp + 1], ah[mt], bh[2], bh[3]);
                }
            }
        }
        __syncthreads();
    }
#pragma unroll
    for (int mt = 0; mt < 2; mt++) {
        int row = m0 + wm * 32 + mt * 16 + g;
        float bi0 = bias[row], bi1 = bias[row + 8];
#pragma unroll
        for (int nt = 0; nt < 8; nt++) {
            int col = t0 + wn * 64 + nt * 8 + 2 * q;
            size_t i0 = ((size_t)b * CHN + row) * T + col;
            size_t i1 = ((size_t)b * CHN + row + 8) * T + col;
            float2 r0 = *(const float2*)&resid[i0];
            float2 r1 = *(const float2*)&resid[i1];
            *(float2*)&outp[i0] = make_float2(acc[mt][nt][0] + bi0 + r0.x,
                                              acc[mt][nt][1] + bi0 + r0.y);
            *(float2*)&outp[i1] = make_float2(acc[mt][nt][2] + bi1 + r1.x,
                                              acc[mt][nt][3] + bi1 + r1.y);
        }
    }
}

// ---------------------------------------------------------------------------
extern "C" void kernel_launch(void* const* d_in, const int* in_sizes, int n_in,
                              void* d_out, int out_size) {
    const float* x      = (const float*)d_in[0];
    const float* nw     = (const float*)d_in[1];
    const float* qkv_w  = (const float*)d_in[2];
    const float* qkv_b  = (const float*)d_in[3];
    const float* proj_w = (const float*)d_in[4];
    const float* proj_b = (const float*)d_in[5];
    float* out = (float*)d_out;

    const int QKV_SMEM  = 10240 * 4;  // 40960
    const int PROJ_SMEM = 9216 * 4;   // 36864
    const int ATT_SMEM  = 11520 * 4;  // 46080
    static bool init = false;
    if (!init) {
        cudaFuncSetAttribute(qkv_mma,  cudaFuncAttributeMaxDynamicSharedMemorySize, QKV_SMEM);
        cudaFuncSetAttribute(proj_mma, cudaFuncAttributeMaxDynamicSharedMemorySize, PROJ_SMEM);
        cudaFuncSetAttribute(attn_mma, cudaFuncAttributeMaxDynamicSharedMemorySize, ATT_SMEM);
        cudaFuncSetAttribute(qkv_mma,  cudaFuncAttributePreferredSharedMemoryCarveout, 100);
        cudaFuncSetAttribute(proj_mma, cudaFuncAttributePreferredSharedMemoryCarveout, 100);
        cudaFuncSetAttribute(attn_mma, cudaFuncAttributePreferredSharedMemoryCarveout, 100);
        init = true;
    }
    rms_kernel<<<256, 256>>>(x);
    prep_w<<<768, 256>>>(qkv_w);
    prep_x<<<dim3(64, 8, 2), 256>>>(x, nw);
    qkv_mma<<<dim3(32, 12, 2), 256, QKV_SMEM>>>(qkv_b);
    prep_qk<<<dim3(64, 16, 2), 256>>>();
    attn_mma<<<dim3(32, 16), 256, ATT_SMEM>>>();
    proj_mma<<<dim3(32, 4, 2), 256, PROJ_SMEM>>>(proj_w, proj_b, x, out);
}

// round 11
// speedup vs baseline: 1.9139x; 1.0175x over previous
#include <cuda_runtime.h>
#include <cuda_fp16.h>
#include <math.h>

#define T   4096
#define CHN 512
#define M3  1536

__device__ float g_ir[2 * T];
__device__ float g_a[(size_t)2 * CHN * T];
__device__ unsigned g_xh[(size_t)2 * T * 256], g_xl[(size_t)2 * T * 256];
__device__ unsigned g_wh[(size_t)M3 * 256],    g_wl[(size_t)M3 * 256];
__device__ unsigned g_qkh[(size_t)2 * M3 * 2048], g_qkl[(size_t)2 * M3 * 2048];
__device__ unsigned g_qTh[(size_t)16 * T * 32], g_qTl[(size_t)16 * T * 32];
__device__ unsigned g_kTh[(size_t)16 * T * 32], g_kTl[(size_t)16 * T * 32];

__device__ __forceinline__ unsigned tf32r(float x) {
    unsigned r; asm("cvt.rna.tf32.f32 %0, %1;" : "=r"(r) : "f"(x)); return r;
}
__device__ __forceinline__ void mma8(float c[4], const unsigned a[4],
                                     unsigned b0, unsigned b1) {
    asm volatile("mma.sync.aligned.m16n8k8.row.col.f32.tf32.tf32.f32 "
                 "{%0,%1,%2,%3}, {%4,%5,%6,%7}, {%8,%9}, {%0,%1,%2,%3};"
                 : "+f"(c[0]), "+f"(c[1]), "+f"(c[2]), "+f"(c[3])
                 : "r"(a[0]), "r"(a[1]), "r"(a[2]), "r"(a[3]), "r"(b0), "r"(b1));
}
__device__ __forceinline__ void mma16(float c[4], const unsigned a[4],
                                      unsigned b0, unsigned b1) {
    asm volatile("mma.sync.aligned.m16n8k16.row.col.f32.f16.f16.f32 "
                 "{%0,%1,%2,%3}, {%4,%5,%6,%7}, {%8,%9}, {%0,%1,%2,%3};"
                 : "+f"(c[0]), "+f"(c[1]), "+f"(c[2]), "+f"(c[3])
                 : "r"(a[0]), "r"(a[1]), "r"(a[2]), "r"(a[3]), "r"(b0), "r"(b1));
}
__device__ __forceinline__ void ldsm4(unsigned r[4], unsigned addr) {
    asm volatile("ldmatrix.sync.aligned.m8n8.x4.shared.b16 {%0,%1,%2,%3}, [%4];"
                 : "=r"(r[0]), "=r"(r[1]), "=r"(r[2]), "=r"(r[3]) : "r"(addr));
}
__device__ __forceinline__ void split2(float v0, float v1, unsigned& hi, unsigned& lo) {
    __half h0 = __float2half_rn(v0), h1 = __float2half_rn(v1);
    __half2 hh = __halves2half2(h0, h1);
    hi = *reinterpret_cast<unsigned*>(&hh);
    __half l0 = __float2half_rn(v0 - __half2float(h0));
    __half l1 = __float2half_rn(v1 - __half2float(h1));
    __half2 ll = __halves2half2(l0, l1);
    lo = *reinterpret_cast<unsigned*>(&ll);
}
__device__ __forceinline__ unsigned pack2h(float a, float b) {
    __half2 p = __floats2half2_rn(a, b);
    return *reinterpret_cast<unsigned*>(&p);
}

// ---------------------------------------------------------------------------
__global__ void __launch_bounds__(256) rms_kernel(const float* __restrict__ x) {
    __shared__ float red[8][32];
    int l = threadIdx.x & 31, w = threadIdx.x >> 5;
    int i = blockIdx.x * 32 + l;
    int b = i >> 12, t = i & (T - 1);
    const float* xp = x + (size_t)b * CHN * T + t + (size_t)(w * 64) * T;
    float s = 0.f;
#pragma unroll 16
    for (int j = 0; j < 64; j++) { float v = xp[(size_t)j * T]; s = fmaf(v, v, s); }
    red[w][l] = s;
    __syncthreads();
    if (w == 0) {
        float tot = red[0][l];
#pragma unroll
        for (int k = 1; k < 8; k++) tot += red[k][l];
        g_ir[i] = 22.62741699796952f * rsqrtf(tot * (1.f / CHN) + 1e-8f);
    }
}

__global__ void __launch_bounds__(256) prep_w(const float* __restrict__ W) {
    int i = blockIdx.x * 256 + threadIdx.x;
    float4 w = *(const float4*)&W[(size_t)i * 4];
    unsigned h01, l01, h23, l23;
    split2(w.x * 256.f, w.y * 256.f, h01, l01);
    split2(w.z * 256.f, w.w * 256.f, h23, l23);
    *(uint2*)&g_wh[2 * (size_t)i] = make_uint2(h01, h23);
    *(uint2*)&g_wl[2 * (size_t)i] = make_uint2(l01, l23);
}

__global__ void __launch_bounds__(256) prep_x(const float* __restrict__ x,
                                              const float* __restrict__ nw) {
    __shared__ float sx[64][65];
    int t0 = blockIdx.x * 64, c0 = blockIdx.y * 64, b = blockIdx.z;
    int tid = threadIdx.x;
#pragma unroll
    for (int i = 0; i < 4; i++) {
        int idx = tid + i * 256;
        int c = idx >> 4, f = idx & 15;
        float4 v = *(const float4*)&x[((size_t)b * CHN + c0 + c) * T + t0 + 4 * f];
        float s = nw[c0 + c];
        float4 ir = *(const float4*)&g_ir[b * T + t0 + 4 * f];
        sx[c][4 * f + 0] = v.x * s * ir.x; sx[c][4 * f + 1] = v.y * s * ir.y;
        sx[c][4 * f + 2] = v.z * s * ir.z; sx[c][4 * f + 3] = v.w * s * ir.w;
    }
    __syncthreads();
#pragma unroll
    for (int i = 0; i < 8; i++) {
        int idx = tid + i * 256;
        int t = idx >> 5, cp = idx & 31;
        unsigned h, l;
        split2(sx[2 * cp][t], sx[2 * cp + 1][t], h, l);
        size_t dst = ((size_t)b * T + t0 + t) * 256 + (c0 >> 1) + cp;
        g_xh[dst] = h; g_xl[dst] = l;
    }
}

// ---------------------------------------------------------------------------
// QKV GEMM, fp16 split, term-major MMA scheduling (RAW distance 8).
__global__ void __launch_bounds__(256, 2) qkv_mma(const float* __restrict__ bias) {
    extern __shared__ unsigned smg[];
    unsigned* Ahi = smg;              // [128][20]
    unsigned* Alo = smg + 2560;
    unsigned* Bhi = smg + 5120;
    unsigned* Blo = smg + 7680;
    unsigned baseAh = (unsigned)__cvta_generic_to_shared(Ahi);
    unsigned baseAl = (unsigned)__cvta_generic_to_shared(Alo);
    unsigned baseBh = (unsigned)__cvta_generic_to_shared(Bhi);
    unsigned baseBl = (unsigned)__cvta_generic_to_shared(Blo);

    int b = blockIdx.z, m0 = blockIdx.y * 128, t0 = blockIdx.x * 128;
    int tid = threadIdx.x, lane = tid & 31, wid = tid >> 5;
    int wm = wid >> 1, wn = wid & 1, g = lane >> 2, q = lane & 3;
    int grp = lane >> 3, lam = lane & 7;

    float acc[2][8][4];
#pragma unroll
    for (int mt = 0; mt < 2; mt++)
#pragma unroll
        for (int nt = 0; nt < 8; nt++)
#pragma unroll
            for (int i = 0; i < 4; i++) acc[mt][nt][i] = 0.f;

    for (int k0 = 0; k0 < CHN; k0 += 32) {
#pragma unroll
        for (int i = 0; i < 2; i++) {
            int idx = tid + i * 256, row = idx >> 2, u = idx & 3;
            size_t sa = (size_t)(m0 + row) * 256 + (k0 >> 1) + 4 * u;
            *(uint4*)&Ahi[row * 20 + 4 * u] = *(const uint4*)&g_wh[sa];
            *(uint4*)&Alo[row * 20 + 4 * u] = *(const uint4*)&g_wl[sa];
            size_t sb = ((size_t)b * T + t0 + row) * 256 + (k0 >> 1) + 4 * u;
            *(uint4*)&Bhi[row * 20 + 4 * u] = *(const uint4*)&g_xh[sb];
            *(uint4*)&Blo[row * 20 + 4 * u] = *(const uint4*)&g_xl[sb];
        }
        __syncthreads();
#pragma unroll
        for (int ks = 0; ks < 2; ks++) {
            unsigned ah[2][4], al[2][4];
#pragma unroll
            for (int mt = 0; mt < 2; mt++) {
                unsigned row = wm * 32 + mt * 16 + (grp & 1) * 8 + lam;
                unsigned col = ks * 8 + (grp >> 1) * 4;
                unsigned off = (row * 20 + col) * 4;
                ldsm4(ah[mt], baseAh + off);
                ldsm4(al[mt], baseAl + off);
            }
#pragma unroll
            for (int half = 0; half < 2; half++) {
                unsigned bh[2][4], bl[2][4];
#pragma unroll
                for (int p = 0; p < 2; p++) {
                    int ntp = half * 4 + 2 * p;
                    unsigned row = wn * 64 + (ntp + (grp >> 1)) * 8 + lam;
                    unsigned col = ks * 8 + (grp & 1) * 4;
                    unsigned off = (row * 20 + col) * 4;
                    ldsm4(bh[p], baseBh + off);
                    ldsm4(bl[p], baseBl + off);
                }
                // term hh: 8 independent accumulators
#pragma unroll
                for (int p = 0; p < 2; p++)
#pragma unroll
                    for (int mt = 0; mt < 2; mt++) {
                        mma16(acc[mt][half * 4 + 2 * p],     ah[mt], bh[p][0], bh[p][1]);
                        mma16(acc[mt][half * 4 + 2 * p + 1], ah[mt], bh[p][2], bh[p][3]);
                    }
                // term hl
#pragma unroll
                for (int p = 0; p < 2; p++)
#pragma unroll
                    for (int mt = 0; mt < 2; mt++) {
                        mma16(acc[mt][half * 4 + 2 * p],     ah[mt], bl[p][0], bl[p][1]);
                        mma16(acc[mt][half * 4 + 2 * p + 1], ah[mt], bl[p][2], bl[p][3]);
                    }
                // term lh
#pragma unroll
                for (int p = 0; p < 2; p++)
#pragma unroll
                    for (int mt = 0; mt < 2; mt++) {
                        mma16(acc[mt][half * 4 + 2 * p],     al[mt], bh[p][0], bh[p][1]);
                        mma16(acc[mt][half * 4 + 2 * p + 1], al[mt], bh[p][2], bh[p][3]);
                    }
            }
        }
        __syncthreads();
    }
#pragma unroll
    for (int mt = 0; mt < 2; mt++) {
        int row = m0 + wm * 32 + mt * 16 + g;
        float bi0 = bias[row], bi1 = bias[row + 8];
        float s0 = ((row % 192) < 64) ? 0.125f : 1.f;
        float s1 = (((row + 8) % 192) < 64) ? 0.125f : 1.f;
#pragma unroll
        for (int nt = 0; nt < 8; nt++) {
            int col = t0 + wn * 64 + nt * 8 + 2 * q;
            float v0 = (acc[mt][nt][0] * (1.f / 256.f) + bi0) * s0;
            float v1 = (acc[mt][nt][1] * (1.f / 256.f) + bi0) * s0;
            float v2 = (acc[mt][nt][2] * (1.f / 256.f) + bi1) * s1;
            float v3 = (acc[mt][nt][3] * (1.f / 256.f) + bi1) * s1;
            unsigned h, l;
            split2(v0, v1, h, l);
            size_t d0 = ((size_t)b * M3 + row) * 2048 + (col >> 1);
            g_qkh[d0] = h; g_qkl[d0] = l;
            split2(v2, v3, h, l);
            size_t d1 = ((size_t)b * M3 + row + 8) * 2048 + (col >> 1);
            g_qkh[d1] = h; g_qkl[d1] = l;
        }
    }
}

// ---------------------------------------------------------------------------
__global__ void __launch_bounds__(256) prep_qk() {
    __shared__ unsigned sH[64][33], sL[64][33];
    int t0 = blockIdx.x * 64, bh = blockIdx.y, qk = blockIdx.z;
    int b = bh >> 3, hh = bh & 7;
    size_t src = ((size_t)b * M3 + hh * 192 + qk * 64) * 2048 + (t0 >> 1);
    int tid = threadIdx.x;
#pragma unroll
    for (int i = 0; i < 8; i++) {
        int idx = tid + i * 256, c = idx >> 5, tp = idx & 31;
        sH[c][tp] = g_qkh[src + (size_t)c * 2048 + tp];
        sL[c][tp] = g_qkl[src + (size_t)c * 2048 + tp];
    }
    __syncthreads();
    unsigned* dH = qk ? g_kTh : g_qTh;
    unsigned* dL = qk ? g_kTl : g_qTl;
    size_t obase = ((size_t)bh * T + t0) * 32;
#pragma unroll
    for (int i = 0; i < 8; i++) {
        int idx = tid + i * 256, tl = idx >> 5, cp = idx & 31;
        unsigned A = sH[2 * cp][tl >> 1], B = sH[2 * cp + 1][tl >> 1];
        dH[obase + (size_t)tl * 32 + cp] =
            (tl & 1) ? __byte_perm(A, B, 0x7632) : __byte_perm(A, B, 0x5410);
        A = sL[2 * cp][tl >> 1]; B = sL[2 * cp + 1][tl >> 1];
        dL[obase + (size_t)tl * 32 + cp] =
            (tl & 1) ? __byte_perm(A, B, 0x7632) : __byte_perm(A, B, 0x5410);
    }
}

// ---------------------------------------------------------------------------
// Flash attention: QK^T split fp16 term-major (RAW distance 4), PV V-hi only.
__global__ void __launch_bounds__(256, 2) attn_mma() {
    extern __shared__ unsigned sma[];
    unsigned* Ps  = sma;              // [128][36]
    unsigned* Qlo = sma + 4608;
    unsigned* Khi = sma + 4608;       // overlays Qlo after prologue
    unsigned* Klo = sma + 6912;
    unsigned* Vh  = sma + 9216;       // total 11520 words
    unsigned basePs = (unsigned)__cvta_generic_to_shared(Ps);
    unsigned baseQl = (unsigned)__cvta_generic_to_shared(Qlo);
    unsigned baseKh = (unsigned)__cvta_generic_to_shared(Khi);
    unsigned baseKl = (unsigned)__cvta_generic_to_shared(Klo);
    unsigned baseVh = (unsigned)__cvta_generic_to_shared(Vh);

    int t0 = blockIdx.x * 128, head = blockIdx.y;
    int b = head >> 3, hh = head & 7;
    int tid = threadIdx.x, lane = tid & 31, wid = tid >> 5;
    int g = lane >> 2, q = lane & 3, rb = wid * 16;
    int grp = lane >> 3, lam = lane & 7;

    const unsigned* qThp = g_qTh + ((size_t)head * T + t0) * 32;
    const unsigned* qTlp = g_qTl + ((size_t)head * T + t0) * 32;
    const unsigned* kThp = g_kTh + (size_t)head * T * 32;
    const unsigned* kTlp = g_kTl + (size_t)head * T * 32;
    const unsigned* vhp  = g_qkh + ((size_t)b * M3 + hh * 192 + 128) * 2048;

#pragma unroll
    for (int i = 0; i < 4; i++) {
        int idx = tid + i * 256, row = idx >> 3, u = idx & 7;
        *(uint4*)&Ps[row * 36 + 4 * u]  = *(const uint4*)&qThp[(size_t)row * 32 + 4 * u];
        *(uint4*)&Qlo[row * 36 + 4 * u] = *(const uint4*)&qTlp[(size_t)row * 32 + 4 * u];
    }
    __syncthreads();
    unsigned qh[4][4], ql[4][4];
#pragma unroll
    for (int ks = 0; ks < 4; ks++) {
        unsigned row = rb + (grp & 1) * 8 + lam;
        unsigned col = ks * 8 + (grp >> 1) * 4;
        unsigned off = (row * 36 + col) * 4;
        ldsm4(qh[ks], basePs + off);
        ldsm4(ql[ks], baseQl + off);
    }

    float o[8][4];
#pragma unroll
    for (int nt = 0; nt < 8; nt++)
#pragma unroll
        for (int i = 0; i < 4; i++) o[nt][i] = 0.f;
    float m_a = -1e30f, m_b = -1e30f, l_a = 0.f, l_b = 0.f;

    for (int s0 = 0; s0 < T; s0 += 64) {
        __syncthreads();
#pragma unroll
        for (int i = 0; i < 2; i++) {
            int idx = tid + i * 256, row = idx >> 3, u = idx & 7;
            *(uint4*)&Khi[row * 36 + 4 * u] =
                *(const uint4*)&kThp[(size_t)(s0 + row) * 32 + 4 * u];
            *(uint4*)&Klo[row * 36 + 4 * u] =
                *(const uint4*)&kTlp[(size_t)(s0 + row) * 32 + 4 * u];
            *(uint4*)&Vh[row * 36 + 4 * u] =
                *(const uint4*)&vhp[(size_t)row * 2048 + (s0 >> 1) + 4 * u];
        }
        __syncthreads();

        float sacc[8][4];
#pragma unroll
        for (int nt = 0; nt < 8; nt++)
#pragma unroll
            for (int i = 0; i < 4; i++) sacc[nt][i] = 0.f;
#pragma unroll
        for (int ks = 0; ks < 4; ks++) {
#pragma unroll
            for (int half = 0; half < 2; half++) {
                unsigned kh[2][4], kl[2][4];
#pragma unroll
                for (int p = 0; p < 2; p++) {
                    int ntp = half * 4 + 2 * p;
                    unsigned row = (ntp + (grp >> 1)) * 8 + lam;
                    unsigned col = ks * 8 + (grp & 1) * 4;
                    unsigned off = (row * 36 + col) * 4;
                    ldsm4(kh[p], baseKh + off);
                    ldsm4(kl[p], baseKl + off);
                }
#pragma unroll
                for (int p = 0; p < 2; p++) {
                    mma16(sacc[half * 4 + 2 * p],     qh[ks], kh[p][0], kh[p][1]);
                    mma16(sacc[half * 4 + 2 * p + 1], qh[ks], kh[p][2], kh[p][3]);
                }
#pragma unroll
                for (int p = 0; p < 2; p++) {
                    mma16(sacc[half * 4 + 2 * p],     qh[ks], kl[p][0], kl[p][1]);
                    mma16(sacc[half * 4 + 2 * p + 1], qh[ks], kl[p][2], kl[p][3]);
                }
#pragma unroll
                for (int p = 0; p < 2; p++) {
                    mma16(sacc[half * 4 + 2 * p],     ql[ks], kh[p][0], kh[p][1]);
                    mma16(sacc[half * 4 + 2 * p + 1], ql[ks], kh[p][2], kh[p][3]);
                }
            }
        }

        float mx_a = -1e30f, mx_b = -1e30f;
#pragma unroll
        for (int nt = 0; nt < 8; nt++) {
            mx_a = fmaxf(mx_a, fmaxf(sacc[nt][0], sacc[nt][1]));
            mx_b = fmaxf(mx_b, fmaxf(sacc[nt][2], sacc[nt][3]));
        }
        mx_a = fmaxf(mx_a, __shfl_xor_sync(~0u, mx_a, 1));
        mx_a = fmaxf(mx_a, __shfl_xor_sync(~0u, mx_a, 2));
        mx_b = fmaxf(mx_b, __shfl_xor_sync(~0u, mx_b, 1));
        mx_b = fmaxf(mx_b, __shfl_xor_sync(~0u, mx_b, 2));
        float mn_a = fmaxf(m_a, mx_a), mn_b = fmaxf(m_b, mx_b);
        float ca = __expf(m_a - mn_a), cb = __expf(m_b - mn_b);
        float sum_a = 0.f, sum_b = 0.f;
#pragma unroll
        for (int nt = 0; nt < 8; nt++) {
            float p0 = __expf(sacc[nt][0] - mn_a), p1 = __expf(sacc[nt][1] - mn_a);
            float p2 = __expf(sacc[nt][2] - mn_b), p3 = __expf(sacc[nt][3] - mn_b);
            sum_a += p0 + p1; sum_b += p2 + p3;
            Ps[(rb + g) * 36 + nt * 4 + q]     = pack2h(p0, p1);
            Ps[(rb + g + 8) * 36 + nt * 4 + q] = pack2h(p2, p3);
        }
        sum_a += __shfl_xor_sync(~0u, sum_a, 1);
        sum_a += __shfl_xor_sync(~0u, sum_a, 2);
        sum_b += __shfl_xor_sync(~0u, sum_b, 1);
        sum_b += __shfl_xor_sync(~0u, sum_b, 2);
        m_a = mn_a; m_b = mn_b;
        l_a = l_a * ca + sum_a; l_b = l_b * cb + sum_b;
#pragma unroll
        for (int nt = 0; nt < 8; nt++) {
            o[nt][0] *= ca; o[nt][1] *= ca; o[nt][2] *= cb; o[nt][3] *= cb;
        }
        __syncwarp();
#pragma unroll
        for (int ks = 0; ks < 4; ks++) {
            unsigned ph[4];
            {
                unsigned row = rb + (grp & 1) * 8 + lam;
                unsigned col = ks * 8 + (grp >> 1) * 4;
                ldsm4(ph, basePs + (row * 36 + col) * 4);
            }
#pragma unroll
            for (int ntp = 0; ntp < 8; ntp += 2) {
                unsigned row = (ntp + (grp >> 1)) * 8 + lam;
                unsigned col = ks * 8 + (grp & 1) * 4;
                unsigned vh[4];
                ldsm4(vh, baseVh + (row * 36 + col) * 4);
                mma16(o[ntp],     ph, vh[0], vh[1]);
                mma16(o[ntp + 1], ph, vh[2], vh[3]);
            }
        }
    }

    float inv_a = 1.f / l_a, inv_b = 1.f / l_b;
    float* ab = g_a + ((size_t)b * CHN + hh * 64) * T;
#pragma unroll
    for (int nt = 0; nt < 8; nt++) {
        int c0 = nt * 8 + 2 * q;
        ab[(size_t)c0 * T + t0 + rb + g]           = o[nt][0] * inv_a;
        ab[(size_t)(c0 + 1) * T + t0 + rb + g]     = o[nt][1] * inv_a;
        ab[(size_t)c0 * T + t0 + rb + g + 8]       = o[nt][2] * inv_b;
        ab[(size_t)(c0 + 1) * T + t0 + rb + g + 8] = o[nt][3] * inv_b;
    }
}

// ---------------------------------------------------------------------------
// proj GEMM + bias + residual: single tf32.
__global__ void __launch_bounds__(256, 2) proj_mma(
        const float* __restrict__ W, const float* __restrict__ bias,
        const float* __restrict__ resid, float* __restrict__ outp)
{
    extern __shared__ unsigned smg[];
    unsigned* Ahi = smg;              // [128][36]
    unsigned* Bhi = smg + 4608;       // [128][36]
    unsigned baseA = (unsigned)__cvta_generic_to_shared(Ahi);
    unsigned baseB = (unsigned)__cvta_generic_to_shared(Bhi);

    int b = blockIdx.z, m0 = blockIdx.y * 128, t0 = blockIdx.x * 128;
    int tid = threadIdx.x, lane = tid & 31, wid = tid >> 5;
    int wm = wid >> 1, wn = wid & 1, g = lane >> 2, q = lane & 3;
    int grp = lane >> 3, lam = lane & 7;
    const float* Xb = (const float*)g_a + (size_t)b * CHN * T;
    int bc4 = tid & 7, bt4 = tid >> 3;

    float acc[2][8][4];
#pragma unroll
    for (int mt = 0; mt < 2; mt++)
#pragma unroll
        for (int nt = 0; nt < 8; nt++)
#pragma unroll
            for (int i = 0; i < 4; i++) acc[mt][nt][i] = 0.f;

    for (int k0 = 0; k0 < CHN; k0 += 32) {
#pragma unroll
        for (int i = 0; i < 4; i++) {
            int idx = tid + i * 256, row = idx >> 3, c4 = idx & 7;
            float4 w = *(const float4*)&W[(size_t)(m0 + row) * CHN + k0 + 4 * c4];
            *(uint4*)&Ahi[row * 36 + 4 * c4] =
                make_uint4(tf32r(w.x), tf32r(w.y), tf32r(w.z), tf32r(w.w));
        }
        {
            float4 r[4];
#pragma unroll
            for (int j = 0; j < 4; j++)
                r[j] = *(const float4*)&Xb[(size_t)(k0 + 4 * bc4 + j) * T + t0 + 4 * bt4];
#pragma unroll
            for (int jp = 0; jp < 4; jp++)
                *(uint4*)&Bhi[(4 * bt4 + jp) * 36 + 4 * bc4] =
                    make_uint4(tf32r((&r[0].x)[jp]), tf32r((&r[1].x)[jp]),
                               tf32r((&r[2].x)[jp]), tf32r((&r[3].x)[jp]));
        }
        __syncthreads();
#pragma unroll
        for (int ks = 0; ks < 4; ks++) {
            unsigned ah[2][4];
#pragma unroll
            for (int mt = 0; mt < 2; mt++) {
                unsigned row = wm * 32 + mt * 16 + (grp & 1) * 8 + lam;
                unsigned col = ks * 8 + (grp >> 1) * 4;
                ldsm4(ah[mt], baseA + (row * 36 + col) * 4);
            }
#pragma unroll
            for (int ntp = 0; ntp < 8; ntp += 2) {
                unsigned row = wn * 64 + (ntp + (grp >> 1)) * 8 + lam;
                unsigned col = ks * 8 + (grp & 1) * 4;
                unsigned bh[4];
                ldsm4(bh, baseB + (row * 36 + col) * 4);
#pragma unroll
                for (int mt = 0; mt < 2; mt++) {
                    mma8(acc[mt][ntp], ah[mt], bh[0], bh[1]);
                    mma8(acc[mt][ntp + 1], ah[mt], bh[2], bh[3]);
                }
            }
        }
        __syncthreads();
    }
#pragma unroll
    for (int mt = 0; mt < 2; mt++) {
        int row = m0 + wm * 32 + mt * 16 + g;
        float bi0 = bias[row], bi1 = bias[row + 8];
#pragma unroll
        for (int nt = 0; nt < 8; nt++) {
            int col = t0 + wn * 64 + nt * 8 + 2 * q;
            size_t i0 = ((size_t)b * CHN + row) * T + col;
            size_t i1 = ((size_t)b * CHN + row + 8) * T + col;
            float2 r0 = *(const float2*)&resid[i0];
            float2 r1 = *(const float2*)&resid[i1];
            *(float2*)&outp[i0] = make_float2(acc[mt][nt][0] + bi0 + r0.x,
                                              acc[mt][nt][1] + bi0 + r0.y);
            *(float2*)&outp[i1] = make_float2(acc[mt][nt][2] + bi1 + r1.x,
                                              acc[mt][nt][3] + bi1 + r1.y);
        }
    }
}

// ---------------------------------------------------------------------------
extern "C" void kernel_launch(void* const* d_in, const int* in_sizes, int n_in,
                              void* d_out, int out_size) {
    const float* x      = (const float*)d_in[0];
    const float* nw     = (const float*)d_in[1];
    const float* qkv_w  = (const float*)d_in[2];
    const float* qkv_b  = (const float*)d_in[3];
    const float* proj_w = (const float*)d_in[4];
    const float* proj_b = (const float*)d_in[5];
    float* out = (float*)d_out;

    const int QKV_SMEM  = 10240 * 4;
    const int PROJ_SMEM = 9216 * 4;
    const int ATT_SMEM  = 11520 * 4;
    static bool init = false;
    if (!init) {
        cudaFuncSetAttribute(qkv_mma,  cudaFuncAttributeMaxDynamicSharedMemorySize, QKV_SMEM);
        cudaFuncSetAttribute(proj_mma, cudaFuncAttributeMaxDynamicSharedMemorySize, PROJ_SMEM);
        cudaFuncSetAttribute(attn_mma, cudaFuncAttributeMaxDynamicSharedMemorySize, ATT_SMEM);
        cudaFuncSetAttribute(qkv_mma,  cudaFuncAttributePreferredSharedMemoryCarveout, 100);
        cudaFuncSetAttribute(proj_mma, cudaFuncAttributePreferredSharedMemoryCarveout, 100);
        cudaFuncSetAttribute(attn_mma, cudaFuncAttributePreferredSharedMemoryCarveout, 100);
        init = true;
    }
    rms_kernel<<<256, 256>>>(x);
    prep_w<<<768, 256>>>(qkv_w);
    prep_x<<<dim3(64, 8, 2), 256>>>(x, nw);
    qkv_mma<<<dim3(32, 12, 2), 256, QKV_SMEM>>>(qkv_b);
    prep_qk<<<dim3(64, 16, 2), 256>>>();
    attn_mma<<<dim3(32, 16), 256, ATT_SMEM>>>();
    proj_mma<<<dim3(32, 4, 2), 256, PROJ_SMEM>>>(proj_w, proj_b, x, out);
}

// round 13
// speedup vs baseline: 2.0106x; 1.0505x over previous
#include <cuda_runtime.h>
#include <cuda_fp16.h>
#include <math.h>

#define T   4096
#define CHN 512
#define M3  1536

__device__ float g_ir[2 * T];
__device__ float g_a[(size_t)2 * CHN * T];
__device__ unsigned g_xh[(size_t)2 * T * 256], g_xl[(size_t)2 * T * 256];
__device__ unsigned g_wh[(size_t)M3 * 256],    g_wl[(size_t)M3 * 256];
__device__ unsigned g_qkh[(size_t)2 * M3 * 2048], g_qkl[(size_t)2 * M3 * 2048];
__device__ unsigned g_qTh[(size_t)16 * T * 32], g_qTl[(size_t)16 * T * 32];
__device__ unsigned g_kTh[(size_t)16 * T * 32], g_kTl[(size_t)16 * T * 32];

__device__ __forceinline__ unsigned tf32r(float x) {
    unsigned r; asm("cvt.rna.tf32.f32 %0, %1;" : "=r"(r) : "f"(x)); return r;
}
__device__ __forceinline__ void mma8(float c[4], const unsigned a[4],
                                     unsigned b0, unsigned b1) {
    asm volatile("mma.sync.aligned.m16n8k8.row.col.f32.tf32.tf32.f32 "
                 "{%0,%1,%2,%3}, {%4,%5,%6,%7}, {%8,%9}, {%0,%1,%2,%3};"
                 : "+f"(c[0]), "+f"(c[1]), "+f"(c[2]), "+f"(c[3])
                 : "r"(a[0]), "r"(a[1]), "r"(a[2]), "r"(a[3]), "r"(b0), "r"(b1));
}
__device__ __forceinline__ void mma16(float c[4], const unsigned a[4],
                                      unsigned b0, unsigned b1) {
    asm volatile("mma.sync.aligned.m16n8k16.row.col.f32.f16.f16.f32 "
                 "{%0,%1,%2,%3}, {%4,%5,%6,%7}, {%8,%9}, {%0,%1,%2,%3};"
                 : "+f"(c[0]), "+f"(c[1]), "+f"(c[2]), "+f"(c[3])
                 : "r"(a[0]), "r"(a[1]), "r"(a[2]), "r"(a[3]), "r"(b0), "r"(b1));
}
__device__ __forceinline__ void ldsm4(unsigned r[4], unsigned addr) {
    asm volatile("ldmatrix.sync.aligned.m8n8.x4.shared.b16 {%0,%1,%2,%3}, [%4];"
                 : "=r"(r[0]), "=r"(r[1]), "=r"(r[2]), "=r"(r[3]) : "r"(addr));
}
__device__ __forceinline__ void split2(float v0, float v1, unsigned& hi, unsigned& lo) {
    __half h0 = __float2half_rn(v0), h1 = __float2half_rn(v1);
    __half2 hh = __halves2half2(h0, h1);
    hi = *reinterpret_cast<unsigned*>(&hh);
    __half l0 = __float2half_rn(v0 - __half2float(h0));
    __half l1 = __float2half_rn(v1 - __half2float(h1));
    __half2 ll = __halves2half2(l0, l1);
    lo = *reinterpret_cast<unsigned*>(&ll);
}
__device__ __forceinline__ unsigned pack2h(float a, float b) {
    __half2 p = __floats2half2_rn(a, b);
    return *reinterpret_cast<unsigned*>(&p);
}
__device__ __forceinline__ void cpa(unsigned saddr, const unsigned* g) {
    asm volatile("cp.async.cg.shared.global [%0], [%1], 16;"
                 :: "r"(saddr), "l"(g) : "memory");
}
#define CPA_COMMIT asm volatile("cp.async.commit_group;" ::: "memory")
#define CPA_WAIT1  asm volatile("cp.async.wait_group 1;" ::: "memory")
#define CPA_WAIT0  asm volatile("cp.async.wait_group 0;" ::: "memory")

// ---------------------------------------------------------------------------
__global__ void __launch_bounds__(256) rms_kernel(const float* __restrict__ x) {
    __shared__ float red[8][32];
    int l = threadIdx.x & 31, w = threadIdx.x >> 5;
    int i = blockIdx.x * 32 + l;
    int b = i >> 12, t = i & (T - 1);
    const float* xp = x + (size_t)b * CHN * T + t + (size_t)(w * 64) * T;
    float s = 0.f;
#pragma unroll 16
    for (int j = 0; j < 64; j++) { float v = xp[(size_t)j * T]; s = fmaf(v, v, s); }
    red[w][l] = s;
    __syncthreads();
    if (w == 0) {
        float tot = red[0][l];
#pragma unroll
        for (int k = 1; k < 8; k++) tot += red[k][l];
        g_ir[i] = 22.62741699796952f * rsqrtf(tot * (1.f / CHN) + 1e-8f);
    }
}

__global__ void __launch_bounds__(256) prep_w(const float* __restrict__ W) {
    int i = blockIdx.x * 256 + threadIdx.x;
    float4 w = *(const float4*)&W[(size_t)i * 4];
    unsigned h01, l01, h23, l23;
    split2(w.x * 256.f, w.y * 256.f, h01, l01);
    split2(w.z * 256.f, w.w * 256.f, h23, l23);
    *(uint2*)&g_wh[2 * (size_t)i] = make_uint2(h01, h23);
    *(uint2*)&g_wl[2 * (size_t)i] = make_uint2(l01, l23);
}

__global__ void __launch_bounds__(256) prep_x(const float* __restrict__ x,
                                              const float* __restrict__ nw) {
    __shared__ float sx[64][65];
    int t0 = blockIdx.x * 64, c0 = blockIdx.y * 64, b = blockIdx.z;
    int tid = threadIdx.x;
#pragma unroll
    for (int i = 0; i < 4; i++) {
        int idx = tid + i * 256;
        int c = idx >> 4, f = idx & 15;
        float4 v = *(const float4*)&x[((size_t)b * CHN + c0 + c) * T + t0 + 4 * f];
        float s = nw[c0 + c];
        float4 ir = *(const float4*)&g_ir[b * T + t0 + 4 * f];
        sx[c][4 * f + 0] = v.x * s * ir.x; sx[c][4 * f + 1] = v.y * s * ir.y;
        sx[c][4 * f + 2] = v.z * s * ir.z; sx[c][4 * f + 3] = v.w * s * ir.w;
    }
    __syncthreads();
#pragma unroll
    for (int i = 0; i < 8; i++) {
        int idx = tid + i * 256;
        int t = idx >> 5, cp = idx & 31;
        unsigned h, l;
        split2(sx[2 * cp][t], sx[2 * cp + 1][t], h, l);
        size_t dst = ((size_t)b * T + t0 + t) * 256 + (c0 >> 1) + cp;
        g_xh[dst] = h; g_xl[dst] = l;
    }
}

// ---------------------------------------------------------------------------
// QKV GEMM, fp16 split, cp.async 2-stage double-buffered fills.
// Stage layout (words): Ahi 0, Alo 2560, Bhi 5120, Blo 7680; stage size 10240.
__global__ void __launch_bounds__(256, 2) qkv_mma(const float* __restrict__ bias) {
    extern __shared__ unsigned smg[];
    unsigned base = (unsigned)__cvta_generic_to_shared(smg);

    int b = blockIdx.z, m0 = blockIdx.y * 128, t0 = blockIdx.x * 128;
    int tid = threadIdx.x, lane = tid & 31, wid = tid >> 5;
    int wm = wid >> 1, wn = wid & 1, g = lane >> 2, q = lane & 3;
    int grp = lane >> 3, lam = lane & 7;

    float acc[2][8][4];
#pragma unroll
    for (int mt = 0; mt < 2; mt++)
#pragma unroll
        for (int nt = 0; nt < 8; nt++)
#pragma unroll
            for (int i = 0; i < 4; i++) acc[mt][nt][i] = 0.f;

    auto fill = [&](int kc, int st) {
        unsigned sb0 = base + st * 10240 * 4;
#pragma unroll
        for (int i = 0; i < 2; i++) {
            int idx = tid + i * 256, row = idx >> 2, u = idx & 3;
            unsigned off = (row * 20 + 4 * u) * 4;
            size_t sa = (size_t)(m0 + row) * 256 + kc * 16 + 4 * u;
            cpa(sb0 + off,            &g_wh[sa]);
            cpa(sb0 + 2560 * 4 + off, &g_wl[sa]);
            size_t sb = ((size_t)b * T + t0 + row) * 256 + kc * 16 + 4 * u;
            cpa(sb0 + 5120 * 4 + off, &g_xh[sb]);
            cpa(sb0 + 7680 * 4 + off, &g_xl[sb]);
        }
    };

    fill(0, 0); CPA_COMMIT;
    for (int kc = 0; kc < 16; kc++) {
        if (kc < 15) { fill(kc + 1, (kc + 1) & 1); CPA_COMMIT; CPA_WAIT1; }
        else         { CPA_WAIT0; }
        __syncthreads();
        unsigned stb = base + (kc & 1) * 10240 * 4;
        unsigned baseAh = stb, baseAl = stb + 2560 * 4;
        unsigned baseBh = stb + 5120 * 4, baseBl = stb + 7680 * 4;
#pragma unroll
        for (int ks = 0; ks < 2; ks++) {
            unsigned ah[2][4], al[2][4];
#pragma unroll
            for (int mt = 0; mt < 2; mt++) {
                unsigned row = wm * 32 + mt * 16 + (grp & 1) * 8 + lam;
                unsigned col = ks * 8 + (grp >> 1) * 4;
                unsigned off = (row * 20 + col) * 4;
                ldsm4(ah[mt], baseAh + off);
                ldsm4(al[mt], baseAl + off);
            }
#pragma unroll
            for (int half = 0; half < 2; half++) {
                unsigned bh[2][4], bl[2][4];
#pragma unroll
                for (int p = 0; p < 2; p++) {
                    int ntp = half * 4 + 2 * p;
                    unsigned row = wn * 64 + (ntp + (grp >> 1)) * 8 + lam;
                    unsigned col = ks * 8 + (grp & 1) * 4;
                    unsigned off = (row * 20 + col) * 4;
                    ldsm4(bh[p], baseBh + off);
                    ldsm4(bl[p], baseBl + off);
                }
#pragma unroll
                for (int p = 0; p < 2; p++)
#pragma unroll
                    for (int mt = 0; mt < 2; mt++) {
                        mma16(acc[mt][half * 4 + 2 * p],     ah[mt], bh[p][0], bh[p][1]);
                        mma16(acc[mt][half * 4 + 2 * p + 1], ah[mt], bh[p][2], bh[p][3]);
                    }
#pragma unroll
                for (int p = 0; p < 2; p++)
#pragma unroll
                    for (int mt = 0; mt < 2; mt++) {
                        mma16(acc[mt][half * 4 + 2 * p],     ah[mt], bl[p][0], bl[p][1]);
                        mma16(acc[mt][half * 4 + 2 * p + 1], ah[mt], bl[p][2], bl[p][3]);
                    }
#pragma unroll
                for (int p = 0; p < 2; p++)
#pragma unroll
                    for (int mt = 0; mt < 2; mt++) {
                        mma16(acc[mt][half * 4 + 2 * p],     al[mt], bh[p][0], bh[p][1]);
                        mma16(acc[mt][half * 4 + 2 * p + 1], al[mt], bh[p][2], bh[p][3]);
                    }
            }
        }
        __syncthreads();
    }
#pragma unroll
    for (int mt = 0; mt < 2; mt++) {
        int row = m0 + wm * 32 + mt * 16 + g;
        float bi0 = bias[row], bi1 = bias[row + 8];
        float s0 = ((row % 192) < 64) ? 0.125f : 1.f;
        float s1 = (((row + 8) % 192) < 64) ? 0.125f : 1.f;
#pragma unroll
        for (int nt = 0; nt < 8; nt++) {
            int col = t0 + wn * 64 + nt * 8 + 2 * q;
            float v0 = (acc[mt][nt][0] * (1.f / 256.f) + bi0) * s0;
            float v1 = (acc[mt][nt][1] * (1.f / 256.f) + bi0) * s0;
            float v2 = (acc[mt][nt][2] * (1.f / 256.f) + bi1) * s1;
            float v3 = (acc[mt][nt][3] * (1.f / 256.f) + bi1) * s1;
            unsigned h, l;
            split2(v0, v1, h, l);
            size_t d0 = ((size_t)b * M3 + row) * 2048 + (col >> 1);
            g_qkh[d0] = h; g_qkl[d0] = l;
            split2(v2, v3, h, l);
            size_t d1 = ((size_t)b * M3 + row + 8) * 2048 + (col >> 1);
            g_qkh[d1] = h; g_qkl[d1] = l;
        }
    }
}

// ---------------------------------------------------------------------------
__global__ void __launch_bounds__(256) prep_qk() {
    __shared__ unsigned sH[64][33], sL[64][33];
    int t0 = blockIdx.x * 64, bh = blockIdx.y, qk = blockIdx.z;
    int b = bh >> 3, hh = bh & 7;
    size_t src = ((size_t)b * M3 + hh * 192 + qk * 64) * 2048 + (t0 >> 1);
    int tid = threadIdx.x;
#pragma unroll
    for (int i = 0; i < 8; i++) {
        int idx = tid + i * 256, c = idx >> 5, tp = idx & 31;
        sH[c][tp] = g_qkh[src + (size_t)c * 2048 + tp];
        sL[c][tp] = g_qkl[src + (size_t)c * 2048 + tp];
    }
    __syncthreads();
    unsigned* dH = qk ? g_kTh : g_qTh;
    unsigned* dL = qk ? g_kTl : g_qTl;
    size_t obase = ((size_t)bh * T + t0) * 32;
#pragma unroll
    for (int i = 0; i < 8; i++) {
        int idx = tid + i * 256, tl = idx >> 5, cp = idx & 31;
        unsigned A = sH[2 * cp][tl >> 1], B = sH[2 * cp + 1][tl >> 1];
        dH[obase + (size_t)tl * 32 + cp] =
            (tl & 1) ? __byte_perm(A, B, 0x7632) : __byte_perm(A, B, 0x5410);
        A = sL[2 * cp][tl >> 1]; B = sL[2 * cp + 1][tl >> 1];
        dL[obase + (size_t)tl * 32 + cp] =
            (tl & 1) ? __byte_perm(A, B, 0x7632) : __byte_perm(A, B, 0x5410);
    }
}

// ---------------------------------------------------------------------------
// Flash attention: QK^T split fp16, PV V-hi. cp.async 2-stage K/Kl/V fills.
// Smem words: Ps[0,4608); stages at 4608 + st*6912 (Khi 0, Klo 2304, Vh 4608).
__global__ void __launch_bounds__(256, 2) attn_mma() {
    extern __shared__ unsigned sma[];
    unsigned base = (unsigned)__cvta_generic_to_shared(sma);
    unsigned* Ps  = sma;
    unsigned* Qlo = sma + 4608;
    unsigned basePs = base;
    unsigned baseQl = base + 4608 * 4;

    int t0 = blockIdx.x * 128, head = blockIdx.y;
    int b = head >> 3, hh = head & 7;
    int tid = threadIdx.x, lane = tid & 31, wid = tid >> 5;
    int g = lane >> 2, q = lane & 3, rb = wid * 16;
    int grp = lane >> 3, lam = lane & 7;

    const unsigned* qThp = g_qTh + ((size_t)head * T + t0) * 32;
    const unsigned* qTlp = g_qTl + ((size_t)head * T + t0) * 32;
    const unsigned* kThp = g_kTh + (size_t)head * T * 32;
    const unsigned* kTlp = g_kTl + (size_t)head * T * 32;
    const unsigned* vhp  = g_qkh + ((size_t)b * M3 + hh * 192 + 128) * 2048;

#pragma unroll
    for (int i = 0; i < 4; i++) {
        int idx = tid + i * 256, row = idx >> 3, u = idx & 7;
        *(uint4*)&Ps[row * 36 + 4 * u]  = *(const uint4*)&qThp[(size_t)row * 32 + 4 * u];
        *(uint4*)&Qlo[row * 36 + 4 * u] = *(const uint4*)&qTlp[(size_t)row * 32 + 4 * u];
    }
    __syncthreads();
    unsigned qh[4][4], ql[4][4];
#pragma unroll
    for (int ks = 0; ks < 4; ks++) {
        unsigned row = rb + (grp & 1) * 8 + lam;
        unsigned col = ks * 8 + (grp >> 1) * 4;
        unsigned off = (row * 36 + col) * 4;
        ldsm4(qh[ks], basePs + off);
        ldsm4(ql[ks], baseQl + off);
    }
    __syncthreads();   // all q frags loaded before stage0 overwrites Qlo

    auto fillKV = [&](int it, int st) {
        unsigned sb0 = base + (4608 + st * 6912) * 4;
        int s0 = it * 64;
#pragma unroll
        for (int i = 0; i < 2; i++) {
            int idx = tid + i * 256, row = idx >> 3, u = idx & 7;
            unsigned off = (row * 36 + 4 * u) * 4;
            cpa(sb0 + off,            &kThp[(size_t)(s0 + row) * 32 + 4 * u]);
            cpa(sb0 + 2304 * 4 + off, &kTlp[(size_t)(s0 + row) * 32 + 4 * u]);
            cpa(sb0 + 4608 * 4 + off, &vhp[(size_t)row * 2048 + (s0 >> 1) + 4 * u]);
        }
    };

    float o[8][4];
#pragma unroll
    for (int nt = 0; nt < 8; nt++)
#pragma unroll
        for (int i = 0; i < 4; i++) o[nt][i] = 0.f;
    float m_a = -1e30f, m_b = -1e30f, l_a = 0.f, l_b = 0.f;

    fillKV(0, 0); CPA_COMMIT;
    for (int it = 0; it < 64; it++) {
        if (it < 63) { fillKV(it + 1, (it + 1) & 1); CPA_COMMIT; CPA_WAIT1; }
        else         { CPA_WAIT0; }
        __syncthreads();
        unsigned stb = base + (4608 + (it & 1) * 6912) * 4;
        unsigned baseKh = stb, baseKl = stb + 2304 * 4, baseVh = stb + 4608 * 4;

        float sacc[8][4];
#pragma unroll
        for (int nt = 0; nt < 8; nt++)
#pragma unroll
            for (int i = 0; i < 4; i++) sacc[nt][i] = 0.f;
#pragma unroll
        for (int ks = 0; ks < 4; ks++) {
#pragma unroll
            for (int half = 0; half < 2; half++) {
                unsigned kh[2][4], kl[2][4];
#pragma unroll
                for (int p = 0; p < 2; p++) {
                    int ntp = half * 4 + 2 * p;
                    unsigned row = (ntp + (grp >> 1)) * 8 + lam;
                    unsigned col = ks * 8 + (grp & 1) * 4;
                    unsigned off = (row * 36 + col) * 4;
                    ldsm4(kh[p], baseKh + off);
                    ldsm4(kl[p], baseKl + off);
                }
#pragma unroll
                for (int p = 0; p < 2; p++) {
                    mma16(sacc[half * 4 + 2 * p],     qh[ks], kh[p][0], kh[p][1]);
                    mma16(sacc[half * 4 + 2 * p + 1], qh[ks], kh[p][2], kh[p][3]);
                }
#pragma unroll
                for (int p = 0; p < 2; p++) {
                    mma16(sacc[half * 4 + 2 * p],     qh[ks], kl[p][0], kl[p][1]);
                    mma16(sacc[half * 4 + 2 * p + 1], qh[ks], kl[p][2], kl[p][3]);
                }
#pragma unroll
                for (int p = 0; p < 2; p++) {
                    mma16(sacc[half * 4 + 2 * p],     ql[ks], kh[p][0], kh[p][1]);
                    mma16(sacc[half * 4 + 2 * p + 1], ql[ks], kh[p][2], kh[p][3]);
                }
            }
        }

        float mx_a = -1e30f, mx_b = -1e30f;
#pragma unroll
        for (int nt = 0; nt < 8; nt++) {
            mx_a = fmaxf(mx_a, fmaxf(sacc[nt][0], sacc[nt][1]));
            mx_b = fmaxf(mx_b, fmaxf(sacc[nt][2], sacc[nt][3]));
        }
        mx_a = fmaxf(mx_a, __shfl_xor_sync(~0u, mx_a, 1));
        mx_a = fmaxf(mx_a, __shfl_xor_sync(~0u, mx_a, 2));
        mx_b = fmaxf(mx_b, __shfl_xor_sync(~0u, mx_b, 1));
        mx_b = fmaxf(mx_b, __shfl_xor_sync(~0u, mx_b, 2));
        float mn_a = fmaxf(m_a, mx_a), mn_b = fmaxf(m_b, mx_b);
        float ca = __expf(m_a - mn_a), cb = __expf(m_b - mn_b);
        float sum_a = 0.f, sum_b = 0.f;
#pragma unroll
        for (int nt = 0; nt < 8; nt++) {
            float p0 = __expf(sacc[nt][0] - mn_a), p1 = __expf(sacc[nt][1] - mn_a);
            float p2 = __expf(sacc[nt][2] - mn_b), p3 = __expf(sacc[nt][3] - mn_b);
            sum_a += p0 + p1; sum_b += p2 + p3;
            Ps[(rb + g) * 36 + nt * 4 + q]     = pack2h(p0, p1);
            Ps[(rb + g + 8) * 36 + nt * 4 + q] = pack2h(p2, p3);
        }
        sum_a += __shfl_xor_sync(~0u, sum_a, 1);
        sum_a += __shfl_xor_sync(~0u, sum_a, 2);
        sum_b += __shfl_xor_sync(~0u, sum_b, 1);
        sum_b += __shfl_xor_sync(~0u, sum_b, 2);
        m_a = mn_a; m_b = mn_b;
        l_a = l_a * ca + sum_a; l_b = l_b * cb + sum_b;
#pragma unroll
        for (int nt = 0; nt < 8; nt++) {
            o[nt][0] *= ca; o[nt][1] *= ca; o[nt][2] *= cb; o[nt][3] *= cb;
        }
        __syncwarp();
#pragma unroll
        for (int ks = 0; ks < 4; ks++) {
            unsigned ph[4];
            {
                unsigned row = rb + (grp & 1) * 8 + lam;
                unsigned col = ks * 8 + (grp >> 1) * 4;
                ldsm4(ph, basePs + (row * 36 + col) * 4);
            }
#pragma unroll
            for (int ntp = 0; ntp < 8; ntp += 2) {
                unsigned row = (ntp + (grp >> 1)) * 8 + lam;
                unsigned col = ks * 8 + (grp & 1) * 4;
                unsigned vh[4];
                ldsm4(vh, baseVh + (row * 36 + col) * 4);
                mma16(o[ntp],     ph, vh[0], vh[1]);
                mma16(o[ntp + 1], ph, vh[2], vh[3]);
            }
        }
        __syncthreads();
    }

    float inv_a = 1.f / l_a, inv_b = 1.f / l_b;
    float* ab = g_a + ((size_t)b * CHN + hh * 64) * T;
#pragma unroll
    for (int nt = 0; nt < 8; nt++) {
        int c0 = nt * 8 + 2 * q;
        ab[(size_t)c0 * T + t0 + rb + g]           = o[nt][0] * inv_a;
        ab[(size_t)(c0 + 1) * T + t0 + rb + g]     = o[nt][1] * inv_a;
        ab[(size_t)c0 * T + t0 + rb + g + 8]       = o[nt][2] * inv_b;
        ab[(size_t)(c0 + 1) * T + t0 + rb + g + 8] = o[nt][3] * inv_b;
    }
}

// ---------------------------------------------------------------------------
// proj GEMM + bias + residual: single tf32 (unchanged proven path).
__global__ void __launch_bounds__(256, 2) proj_mma(
        const float* __restrict__ W, const float* __restrict__ bias,
        const float* __restrict__ resid, float* __restrict__ outp)
{
    extern __shared__ unsigned smg[];
    unsigned* Ahi = smg;              // [128][36]
    unsigned* Bhi = smg + 4608;       // [128][36]
    unsigned baseA = (unsigned)__cvta_generic_to_shared(Ahi);
    unsigned baseB = (unsigned)__cvta_generic_to_shared(Bhi);

    int b = blockIdx.z, m0 = blockIdx.y * 128, t0 = blockIdx.x * 128;
    int tid = threadIdx.x, lane = tid & 31, wid = tid >> 5;
    int wm = wid >> 1, wn = wid & 1, g = lane >> 2, q = lane & 3;
    int grp = lane >> 3, lam = lane & 7;
    const float* Xb = (const float*)g_a + (size_t)b * CHN * T;
    int bc4 = tid & 7, bt4 = tid >> 3;

    float acc[2][8][4];
#pragma unroll
    for (int mt = 0; mt < 2; mt++)
#pragma unroll
        for (int nt = 0; nt < 8; nt++)
#pragma unroll
            for (int i = 0; i < 4; i++) acc[mt][nt][i] = 0.f;

    for (int k0 = 0; k0 < CHN; k0 += 32) {
#pragma unroll
        for (int i = 0; i < 4; i++) {
            int idx = tid + i * 256, row = idx >> 3, c4 = idx & 7;
            float4 w = *(const float4*)&W[(size_t)(m0 + row) * CHN + k0 + 4 * c4];
            *(uint4*)&Ahi[row * 36 + 4 * c4] =
                make_uint4(tf32r(w.x), tf32r(w.y), tf32r(w.z), tf32r(w.w));
        }
        {
            float4 r[4];
#pragma unroll
            for (int j = 0; j < 4; j++)
                r[j] = *(const float4*)&Xb[(size_t)(k0 + 4 * bc4 + j) * T + t0 + 4 * bt4];
#pragma unroll
            for (int jp = 0; jp < 4; jp++)
                *(uint4*)&Bhi[(4 * bt4 + jp) * 36 + 4 * bc4] =
                    make_uint4(tf32r((&r[0].x)[jp]), tf32r((&r[1].x)[jp]),
                               tf32r((&r[2].x)[jp]), tf32r((&r[3].x)[jp]));
        }
        __syncthreads();
#pragma unroll
        for (int ks = 0; ks < 4; ks++) {
            unsigned ah[2][4];
#pragma unroll
            for (int mt = 0; mt < 2; mt++) {
                unsigned row = wm * 32 + mt * 16 + (grp & 1) * 8 + lam;
                unsigned col = ks * 8 + (grp >> 1) * 4;
                ldsm4(ah[mt], baseA + (row * 36 + col) * 4);
            }
#pragma unroll
            for (int ntp = 0; ntp < 8; ntp += 2) {
                unsigned row = wn * 64 + (ntp + (grp >> 1)) * 8 + lam;
                unsigned col = ks * 8 + (grp & 1) * 4;
                unsigned bh[4];
                ldsm4(bh, baseB + (row * 36 + col) * 4);
#pragma unroll
                for (int mt = 0; mt < 2; mt++) {
                    mma8(acc[mt][ntp], ah[mt], bh[0], bh[1]);
                    mma8(acc[mt][ntp + 1], ah[mt], bh[2], bh[3]);
                }
            }
        }
        __syncthreads();
    }
#pragma unroll
    for (int mt = 0; mt < 2; mt++) {
        int row = m0 + wm * 32 + mt * 16 + g;
        float bi0 = bias[row], bi1 = bias[row + 8];
#pragma unroll
        for (int nt = 0; nt < 8; nt++) {
            int col = t0 + wn * 64 + nt * 8 + 2 * q;
            size_t i0 = ((size_t)b * CHN + row) * T + col;
            size_t i1 = ((size_t)b * CHN + row + 8) * T + col;
            float2 r0 = *(const float2*)&resid[i0];
            float2 r1 = *(const float2*)&resid[i1];
            *(float2*)&outp[i0] = make_float2(acc[mt][nt][0] + bi0 + r0.x,
                                              acc[mt][nt][1] + bi0 + r0.y);
            *(float2*)&outp[i1] = make_float2(acc[mt][nt][2] + bi1 + r1.x,
                                              acc[mt][nt][3] + bi1 + r1.y);
        }
    }
}

// ---------------------------------------------------------------------------
extern "C" void kernel_launch(void* const* d_in, const int* in_sizes, int n_in,
                              void* d_out, int out_size) {
    const float* x      = (const float*)d_in[0];
    const float* nw     = (const float*)d_in[1];
    const float* qkv_w  = (const float*)d_in[2];
    const float* qkv_b  = (const float*)d_in[3];
    const float* proj_w = (const float*)d_in[4];
    const float* proj_b = (const float*)d_in[5];
    float* out = (float*)d_out;

    const int QKV_SMEM  = 20480 * 4;  // 81920 (2 stages)
    const int PROJ_SMEM = 9216 * 4;   // 36864
    const int ATT_SMEM  = 18432 * 4;  // 73728 (Ps + 2 stages)
    static bool init = false;
    if (!init) {
        cudaFuncSetAttribute(qkv_mma,  cudaFuncAttributeMaxDynamicSharedMemorySize, QKV_SMEM);
        cudaFuncSetAttribute(proj_mma, cudaFuncAttributeMaxDynamicSharedMemorySize, PROJ_SMEM);
        cudaFuncSetAttribute(attn_mma, cudaFuncAttributeMaxDynamicSharedMemorySize, ATT_SMEM);
        cudaFuncSetAttribute(qkv_mma,  cudaFuncAttributePreferredSharedMemoryCarveout, 100);
        cudaFuncSetAttribute(proj_mma, cudaFuncAttributePreferredSharedMemoryCarveout, 100);
        cudaFuncSetAttribute(attn_mma, cudaFuncAttributePreferredSharedMemoryCarveout, 100);
        init = true;
    }
    rms_kernel<<<256, 256>>>(x);
    prep_w<<<768, 256>>>(qkv_w);
    prep_x<<<dim3(64, 8, 2), 256>>>(x, nw);
    qkv_mma<<<dim3(32, 12, 2), 256, QKV_SMEM>>>(qkv_b);
    prep_qk<<<dim3(64, 16, 2), 256>>>();
    attn_mma<<<dim3(32, 16), 256, ATT_SMEM>>>();
    proj_mma<<<dim3(32, 4, 2), 256, PROJ_SMEM>>>(proj_w, proj_b, x, out);
}

// round 14
// speedup vs baseline: 2.0766x; 1.0328x over previous
#include <cuda_runtime.h>
#include <cuda_fp16.h>
#include <math.h>

#define T   4096
#define CHN 512
#define M3  1536

__device__ float g_ir[2 * T];
__device__ float g_a[(size_t)2 * CHN * T];
__device__ unsigned g_xh[(size_t)2 * T * 256], g_xl[(size_t)2 * T * 256];
__device__ unsigned g_wh[(size_t)M3 * 256],    g_wl[(size_t)M3 * 256];
__device__ unsigned g_qkh[(size_t)2 * M3 * 2048], g_qkl[(size_t)2 * M3 * 2048];
__device__ unsigned g_qTh[(size_t)16 * T * 32], g_qTl[(size_t)16 * T * 32];
__device__ unsigned g_kTh[(size_t)16 * T * 32], g_kTl[(size_t)16 * T * 32];

__device__ __forceinline__ unsigned tf32r(float x) {
    unsigned r; asm("cvt.rna.tf32.f32 %0, %1;" : "=r"(r) : "f"(x)); return r;
}
__device__ __forceinline__ float ex2(float x) {
    float r; asm("ex2.approx.f32 %0, %1;" : "=f"(r) : "f"(x)); return r;
}
__device__ __forceinline__ void mma8(float c[4], const unsigned a[4],
                                     unsigned b0, unsigned b1) {
    asm volatile("mma.sync.aligned.m16n8k8.row.col.f32.tf32.tf32.f32 "
                 "{%0,%1,%2,%3}, {%4,%5,%6,%7}, {%8,%9}, {%0,%1,%2,%3};"
                 : "+f"(c[0]), "+f"(c[1]), "+f"(c[2]), "+f"(c[3])
                 : "r"(a[0]), "r"(a[1]), "r"(a[2]), "r"(a[3]), "r"(b0), "r"(b1));
}
__device__ __forceinline__ void mma16(float c[4], const unsigned a[4],
                                      unsigned b0, unsigned b1) {
    asm volatile("mma.sync.aligned.m16n8k16.row.col.f32.f16.f16.f32 "
                 "{%0,%1,%2,%3}, {%4,%5,%6,%7}, {%8,%9}, {%0,%1,%2,%3};"
                 : "+f"(c[0]), "+f"(c[1]), "+f"(c[2]), "+f"(c[3])
                 : "r"(a[0]), "r"(a[1]), "r"(a[2]), "r"(a[3]), "r"(b0), "r"(b1));
}
__device__ __forceinline__ void ldsm4(unsigned r[4], unsigned addr) {
    asm volatile("ldmatrix.sync.aligned.m8n8.x4.shared.b16 {%0,%1,%2,%3}, [%4];"
                 : "=r"(r[0]), "=r"(r[1]), "=r"(r[2]), "=r"(r[3]) : "r"(addr));
}
__device__ __forceinline__ void split2(float v0, float v1, unsigned& hi, unsigned& lo) {
    __half h0 = __float2half_rn(v0), h1 = __float2half_rn(v1);
    __half2 hh = __halves2half2(h0, h1);
    hi = *reinterpret_cast<unsigned*>(&hh);
    __half l0 = __float2half_rn(v0 - __half2float(h0));
    __half l1 = __float2half_rn(v1 - __half2float(h1));
    __half2 ll = __halves2half2(l0, l1);
    lo = *reinterpret_cast<unsigned*>(&ll);
}
__device__ __forceinline__ unsigned pack2h(float a, float b) {
    __half2 p = __floats2half2_rn(a, b);
    return *reinterpret_cast<unsigned*>(&p);
}
__device__ __forceinline__ void cpa(unsigned saddr, const unsigned* g) {
    asm volatile("cp.async.cg.shared.global [%0], [%1], 16;"
                 :: "r"(saddr), "l"(g) : "memory");
}
#define CPA_COMMIT asm volatile("cp.async.commit_group;" ::: "memory")
#define CPA_WAIT0  asm volatile("cp.async.wait_group 0;" ::: "memory")

// ---------------------------------------------------------------------------
__global__ void __launch_bounds__(256) rms_kernel(const float* __restrict__ x) {
    __shared__ float red[8][32];
    int l = threadIdx.x & 31, w = threadIdx.x >> 5;
    int i = blockIdx.x * 32 + l;
    int b = i >> 12, t = i & (T - 1);
    const float* xp = x + (size_t)b * CHN * T + t + (size_t)(w * 64) * T;
    float s = 0.f;
#pragma unroll 16
    for (int j = 0; j < 64; j++) { float v = xp[(size_t)j * T]; s = fmaf(v, v, s); }
    red[w][l] = s;
    __syncthreads();
    if (w == 0) {
        float tot = red[0][l];
#pragma unroll
        for (int k = 1; k < 8; k++) tot += red[k][l];
        g_ir[i] = 22.62741699796952f * rsqrtf(tot * (1.f / CHN) + 1e-8f);
    }
}

__global__ void __launch_bounds__(256) prep_w(const float* __restrict__ W) {
    int i = blockIdx.x * 256 + threadIdx.x;
    float4 w = *(const float4*)&W[(size_t)i * 4];
    unsigned h01, l01, h23, l23;
    split2(w.x * 256.f, w.y * 256.f, h01, l01);
    split2(w.z * 256.f, w.w * 256.f, h23, l23);
    *(uint2*)&g_wh[2 * (size_t)i] = make_uint2(h01, h23);
    *(uint2*)&g_wl[2 * (size_t)i] = make_uint2(l01, l23);
}

__global__ void __launch_bounds__(256) prep_x(const float* __restrict__ x,
                                              const float* __restrict__ nw) {
    __shared__ float sx[64][65];
    int t0 = blockIdx.x * 64, c0 = blockIdx.y * 64, b = blockIdx.z;
    int tid = threadIdx.x;
#pragma unroll
    for (int i = 0; i < 4; i++) {
        int idx = tid + i * 256;
        int c = idx >> 4, f = idx & 15;
        float4 v = *(const float4*)&x[((size_t)b * CHN + c0 + c) * T + t0 + 4 * f];
        float s = nw[c0 + c];
        float4 ir = *(const float4*)&g_ir[b * T + t0 + 4 * f];
        sx[c][4 * f + 0] = v.x * s * ir.x; sx[c][4 * f + 1] = v.y * s * ir.y;
        sx[c][4 * f + 2] = v.z * s * ir.z; sx[c][4 * f + 3] = v.w * s * ir.w;
    }
    __syncthreads();
#pragma unroll
    for (int i = 0; i < 8; i++) {
        int idx = tid + i * 256;
        int t = idx >> 5, cp = idx & 31;
        unsigned h, l;
        split2(sx[2 * cp][t], sx[2 * cp + 1][t], h, l);
        size_t dst = ((size_t)b * T + t0 + t) * 256 + (c0 >> 1) + cp;
        g_xh[dst] = h; g_xl[dst] = l;
    }
}

// ---------------------------------------------------------------------------
// QKV GEMM, fp16 split, cp.async 2-stage, ONE barrier per k-tile.
__global__ void __launch_bounds__(256, 2) qkv_mma(const float* __restrict__ bias) {
    extern __shared__ unsigned smg[];
    unsigned base = (unsigned)__cvta_generic_to_shared(smg);

    int b = blockIdx.z, m0 = blockIdx.y * 128, t0 = blockIdx.x * 128;
    int tid = threadIdx.x, lane = tid & 31, wid = tid >> 5;
    int wm = wid >> 1, wn = wid & 1, g = lane >> 2, q = lane & 3;
    int grp = lane >> 3, lam = lane & 7;

    float acc[2][8][4];
#pragma unroll
    for (int mt = 0; mt < 2; mt++)
#pragma unroll
        for (int nt = 0; nt < 8; nt++)
#pragma unroll
            for (int i = 0; i < 4; i++) acc[mt][nt][i] = 0.f;

    auto fill = [&](int kc, int st) {
        unsigned sb0 = base + st * 10240 * 4;
#pragma unroll
        for (int i = 0; i < 2; i++) {
            int idx = tid + i * 256, row = idx >> 2, u = idx & 3;
            unsigned off = (row * 20 + 4 * u) * 4;
            size_t sa = (size_t)(m0 + row) * 256 + kc * 16 + 4 * u;
            cpa(sb0 + off,            &g_wh[sa]);
            cpa(sb0 + 2560 * 4 + off, &g_wl[sa]);
            size_t sb = ((size_t)b * T + t0 + row) * 256 + kc * 16 + 4 * u;
            cpa(sb0 + 5120 * 4 + off, &g_xh[sb]);
            cpa(sb0 + 7680 * 4 + off, &g_xl[sb]);
        }
    };

    fill(0, 0); CPA_COMMIT;
    for (int kc = 0; kc < 16; kc++) {
        CPA_WAIT0;
        __syncthreads();
        if (kc < 15) { fill(kc + 1, (kc + 1) & 1); CPA_COMMIT; }
        unsigned stb = base + (kc & 1) * 10240 * 4;
        unsigned baseAh = stb, baseAl = stb + 2560 * 4;
        unsigned baseBh = stb + 5120 * 4, baseBl = stb + 7680 * 4;
#pragma unroll
        for (int ks = 0; ks < 2; ks++) {
            unsigned ah[2][4], al[2][4];
#pragma unroll
            for (int mt = 0; mt < 2; mt++) {
                unsigned row = wm * 32 + mt * 16 + (grp & 1) * 8 + lam;
                unsigned col = ks * 8 + (grp >> 1) * 4;
                unsigned off = (row * 20 + col) * 4;
                ldsm4(ah[mt], baseAh + off);
                ldsm4(al[mt], baseAl + off);
            }
#pragma unroll
            for (int half = 0; half < 2; half++) {
                unsigned bh[2][4], bl[2][4];
#pragma unroll
                for (int p = 0; p < 2; p++) {
                    int ntp = half * 4 + 2 * p;
                    unsigned row = wn * 64 + (ntp + (grp >> 1)) * 8 + lam;
                    unsigned col = ks * 8 + (grp & 1) * 4;
                    unsigned off = (row * 20 + col) * 4;
                    ldsm4(bh[p], baseBh + off);
                    ldsm4(bl[p], baseBl + off);
                }
#pragma unroll
                for (int p = 0; p < 2; p++)
#pragma unroll
                    for (int mt = 0; mt < 2; mt++) {
                        mma16(acc[mt][half * 4 + 2 * p],     ah[mt], bh[p][0], bh[p][1]);
                        mma16(acc[mt][half * 4 + 2 * p + 1], ah[mt], bh[p][2], bh[p][3]);
                    }
#pragma unroll
                for (int p = 0; p < 2; p++)
#pragma unroll
                    for (int mt = 0; mt < 2; mt++) {
                        mma16(acc[mt][half * 4 + 2 * p],     ah[mt], bl[p][0], bl[p][1]);
                        mma16(acc[mt][half * 4 + 2 * p + 1], ah[mt], bl[p][2], bl[p][3]);
                    }
#pragma unroll
                for (int p = 0; p < 2; p++)
#pragma unroll
                    for (int mt = 0; mt < 2; mt++) {
                        mma16(acc[mt][half * 4 + 2 * p],     al[mt], bh[p][0], bh[p][1]);
                        mma16(acc[mt][half * 4 + 2 * p + 1], al[mt], bh[p][2], bh[p][3]);
                    }
            }
        }
        __syncthreads();
    }
    // q rows pre-scaled by ch^-0.5 * log2(e) for exp2-domain softmax
#pragma unroll
    for (int mt = 0; mt < 2; mt++) {
        int row = m0 + wm * 32 + mt * 16 + g;
        float bi0 = bias[row], bi1 = bias[row + 8];
        float s0 = ((row % 192) < 64) ? 0.18033688f : 1.f;
        float s1 = (((row + 8) % 192) < 64) ? 0.18033688f : 1.f;
#pragma unroll
        for (int nt = 0; nt < 8; nt++) {
            int col = t0 + wn * 64 + nt * 8 + 2 * q;
            float v0 = (acc[mt][nt][0] * (1.f / 256.f) + bi0) * s0;
            float v1 = (acc[mt][nt][1] * (1.f / 256.f) + bi0) * s0;
            float v2 = (acc[mt][nt][2] * (1.f / 256.f) + bi1) * s1;
            float v3 = (acc[mt][nt][3] * (1.f / 256.f) + bi1) * s1;
            unsigned h, l;
            split2(v0, v1, h, l);
            size_t d0 = ((size_t)b * M3 + row) * 2048 + (col >> 1);
            g_qkh[d0] = h; g_qkl[d0] = l;
            split2(v2, v3, h, l);
            size_t d1 = ((size_t)b * M3 + row + 8) * 2048 + (col >> 1);
            g_qkh[d1] = h; g_qkl[d1] = l;
        }
    }
}

// ---------------------------------------------------------------------------
__global__ void __launch_bounds__(256) prep_qk() {
    __shared__ unsigned sH[64][33], sL[64][33];
    int t0 = blockIdx.x * 64, bh = blockIdx.y, qk = blockIdx.z;
    int b = bh >> 3, hh = bh & 7;
    size_t src = ((size_t)b * M3 + hh * 192 + qk * 64) * 2048 + (t0 >> 1);
    int tid = threadIdx.x;
#pragma unroll
    for (int i = 0; i < 8; i++) {
        int idx = tid + i * 256, c = idx >> 5, tp = idx & 31;
        sH[c][tp] = g_qkh[src + (size_t)c * 2048 + tp];
        sL[c][tp] = g_qkl[src + (size_t)c * 2048 + tp];
    }
    __syncthreads();
    unsigned* dH = qk ? g_kTh : g_qTh;
    unsigned* dL = qk ? g_kTl : g_qTl;
    size_t obase = ((size_t)bh * T + t0) * 32;
#pragma unroll
    for (int i = 0; i < 8; i++) {
        int idx = tid + i * 256, tl = idx >> 5, cp = idx & 31;
        unsigned A = sH[2 * cp][tl >> 1], B = sH[2 * cp + 1][tl >> 1];
        dH[obase + (size_t)tl * 32 + cp] =
            (tl & 1) ? __byte_perm(A, B, 0x7632) : __byte_perm(A, B, 0x5410);
        A = sL[2 * cp][tl >> 1]; B = sL[2 * cp + 1][tl >> 1];
        dL[obase + (size_t)tl * 32 + cp] =
            (tl & 1) ? __byte_perm(A, B, 0x7632) : __byte_perm(A, B, 0x5410);
    }
}

// ---------------------------------------------------------------------------
// Flash attention: QK^T split fp16, PV V-hi. cp.async 2-stage,
// ONE barrier per s-tile; softmax in exp2 domain.
__global__ void __launch_bounds__(256, 2) attn_mma() {
    extern __shared__ unsigned sma[];
    unsigned base = (unsigned)__cvta_generic_to_shared(sma);
    unsigned* Ps  = sma;
    unsigned* Qlo = sma + 4608;
    unsigned basePs = base;
    unsigned baseQl = base + 4608 * 4;

    int t0 = blockIdx.x * 128, head = blockIdx.y;
    int b = head >> 3, hh = head & 7;
    int tid = threadIdx.x, lane = tid & 31, wid = tid >> 5;
    int g = lane >> 2, q = lane & 3, rb = wid * 16;
    int grp = lane >> 3, lam = lane & 7;

    const unsigned* qThp = g_qTh + ((size_t)head * T + t0) * 32;
    const unsigned* qTlp = g_qTl + ((size_t)head * T + t0) * 32;
    const unsigned* kThp = g_kTh + (size_t)head * T * 32;
    const unsigned* kTlp = g_kTl + (size_t)head * T * 32;
    const unsigned* vhp  = g_qkh + ((size_t)b * M3 + hh * 192 + 128) * 2048;

#pragma unroll
    for (int i = 0; i < 4; i++) {
        int idx = tid + i * 256, row = idx >> 3, u = idx & 7;
        *(uint4*)&Ps[row * 36 + 4 * u]  = *(const uint4*)&qThp[(size_t)row * 32 + 4 * u];
        *(uint4*)&Qlo[row * 36 + 4 * u] = *(const uint4*)&qTlp[(size_t)row * 32 + 4 * u];
    }
    __syncthreads();
    unsigned qh[4][4], ql[4][4];
#pragma unroll
    for (int ks = 0; ks < 4; ks++) {
        unsigned row = rb + (grp & 1) * 8 + lam;
        unsigned col = ks * 8 + (grp >> 1) * 4;
        unsigned off = (row * 36 + col) * 4;
        ldsm4(qh[ks], basePs + off);
        ldsm4(ql[ks], baseQl + off);
    }
    __syncthreads();   // q frags loaded before stage0 overwrites Qlo

    auto fillKV = [&](int it, int st) {
        unsigned sb0 = base + (4608 + st * 6912) * 4;
        int s0 = it * 64;
#pragma unroll
        for (int i = 0; i < 2; i++) {
            int idx = tid + i * 256, row = idx >> 3, u = idx & 7;
            unsigned off = (row * 36 + 4 * u) * 4;
            cpa(sb0 + off,            &kThp[(size_t)(s0 + row) * 32 + 4 * u]);
            cpa(sb0 + 2304 * 4 + off, &kTlp[(size_t)(s0 + row) * 32 + 4 * u]);
            cpa(sb0 + 4608 * 4 + off, &vhp[(size_t)row * 2048 + (s0 >> 1) + 4 * u]);
        }
    };

    float o[8][4];
#pragma unroll
    for (int nt = 0; nt < 8; nt++)
#pragma unroll
        for (int i = 0; i < 4; i++) o[nt][i] = 0.f;
    float m_a = -1e30f, m_b = -1e30f, l_a = 0.f, l_b = 0.f;

    fillKV(0, 0); CPA_COMMIT;
    for (int it = 0; it < 64; it++) {
        CPA_WAIT0;
        __syncthreads();
        if (it < 63) { fillKV(it + 1, (it + 1) & 1); CPA_COMMIT; }
        unsigned stb = base + (4608 + (it & 1) * 6912) * 4;
        unsigned baseKh = stb, baseKl = stb + 2304 * 4, baseVh = stb + 4608 * 4;

        float sacc[8][4];
#pragma unroll
        for (int nt = 0; nt < 8; nt++)
#pragma unroll
            for (int i = 0; i < 4; i++) sacc[nt][i] = 0.f;
#pragma unroll
        for (int ks = 0; ks < 4; ks++) {
#pragma unroll
            for (int half = 0; half < 2; half++) {
                unsigned kh[2][4], kl[2][4];
#pragma unroll
                for (int p = 0; p < 2; p++) {
                    int ntp = half * 4 + 2 * p;
                    unsigned row = (ntp + (grp >> 1)) * 8 + lam;
                    unsigned col = ks * 8 + (grp & 1) * 4;
                    unsigned off = (row * 36 + col) * 4;
                    ldsm4(kh[p], baseKh + off);
                    ldsm4(kl[p], baseKl + off);
                }
#pragma unroll
                for (int p = 0; p < 2; p++) {
                    mma16(sacc[half * 4 + 2 * p],     qh[ks], kh[p][0], kh[p][1]);
                    mma16(sacc[half * 4 + 2 * p + 1], qh[ks], kh[p][2], kh[p][3]);
                }
#pragma unroll
                for (int p = 0; p < 2; p++) {
                    mma16(sacc[half * 4 + 2 * p],     qh[ks], kl[p][0], kl[p][1]);
                    mma16(sacc[half * 4 + 2 * p + 1], qh[ks], kl[p][2], kl[p][3]);
                }
#pragma unroll
                for (int p = 0; p < 2; p++) {
                    mma16(sacc[half * 4 + 2 * p],     ql[ks], kh[p][0], kh[p][1]);
                    mma16(sacc[half * 4 + 2 * p + 1], ql[ks], kh[p][2], kh[p][3]);
                }
            }
        }

        float mx_a = -1e30f, mx_b = -1e30f;
#pragma unroll
        for (int nt = 0; nt < 8; nt++) {
            mx_a = fmaxf(mx_a, fmaxf(sacc[nt][0], sacc[nt][1]));
            mx_b = fmaxf(mx_b, fmaxf(sacc[nt][2], sacc[nt][3]));
        }
        mx_a = fmaxf(mx_a, __shfl_xor_sync(~0u, mx_a, 1));
        mx_a = fmaxf(mx_a, __shfl_xor_sync(~0u, mx_a, 2));
        mx_b = fmaxf(mx_b, __shfl_xor_sync(~0u, mx_b, 1));
        mx_b = fmaxf(mx_b, __shfl_xor_sync(~0u, mx_b, 2));
        float mn_a = fmaxf(m_a, mx_a), mn_b = fmaxf(m_b, mx_b);
        float ca = ex2(m_a - mn_a), cb = ex2(m_b - mn_b);
        float sum_a = 0.f, sum_b = 0.f;
#pragma unroll
        for (int nt = 0; nt < 8; nt++) {
            float p0 = ex2(sacc[nt][0] - mn_a), p1 = ex2(sacc[nt][1] - mn_a);
            float p2 = ex2(sacc[nt][2] - mn_b), p3 = ex2(sacc[nt][3] - mn_b);
            sum_a += p0 + p1; sum_b += p2 + p3;
            Ps[(rb + g) * 36 + nt * 4 + q]     = pack2h(p0, p1);
            Ps[(rb + g + 8) * 36 + nt * 4 + q] = pack2h(p2, p3);
        }
        sum_a += __shfl_xor_sync(~0u, sum_a, 1);
        sum_a += __shfl_xor_sync(~0u, sum_a, 2);
        sum_b += __shfl_xor_sync(~0u, sum_b, 1);
        sum_b += __shfl_xor_sync(~0u, sum_b, 2);
        m_a = mn_a; m_b = mn_b;
        l_a = l_a * ca + sum_a; l_b = l_b * cb + sum_b;
#pragma unroll
        for (int nt = 0; nt < 8; nt++) {
            o[nt][0] *= ca; o[nt][1] *= ca; o[nt][2] *= cb; o[nt][3] *= cb;
        }
        __syncwarp();
#pragma unroll
        for (int ks = 0; ks < 4; ks++) {
            unsigned ph[4];
            {
                unsigned row = rb + (grp & 1) * 8 + lam;
                unsigned col = ks * 8 + (grp >> 1) * 4;
                ldsm4(ph, basePs + (row * 36 + col) * 4);
            }
#pragma unroll
            for (int ntp = 0; ntp < 8; ntp += 2) {
                unsigned row = (ntp + (grp >> 1)) * 8 + lam;
                unsigned col = ks * 8 + (grp & 1) * 4;
                unsigned vh[4];
                ldsm4(vh, baseVh + (row * 36 + col) * 4);
                mma16(o[ntp],     ph, vh[0], vh[1]);
                mma16(o[ntp + 1], ph, vh[2], vh[3]);
            }
        }
    }

    float inv_a = 1.f / l_a, inv_b = 1.f / l_b;
    float* ab = g_a + ((size_t)b * CHN + hh * 64) * T;
#pragma unroll
    for (int nt = 0; nt < 8; nt++) {
        int c0 = nt * 8 + 2 * q;
        ab[(size_t)c0 * T + t0 + rb + g]           = o[nt][0] * inv_a;
        ab[(size_t)(c0 + 1) * T + t0 + rb + g]     = o[nt][1] * inv_a;
        ab[(size_t)c0 * T + t0 + rb + g + 8]       = o[nt][2] * inv_b;
        ab[(size_t)(c0 + 1) * T + t0 + rb + g + 8] = o[nt][3] * inv_b;
    }
}

// ---------------------------------------------------------------------------
// proj GEMM + bias + residual: single tf32 (unchanged proven path).
__global__ void __launch_bounds__(256, 2) proj_mma(
        const float* __restrict__ W, const float* __restrict__ bias,
        const float* __restrict__ resid, float* __restrict__ outp)
{
    extern __shared__ unsigned smg[];
    unsigned* Ahi = smg;              // [128][36]
    unsigned* Bhi = smg + 4608;       // [128][36]
    unsigned baseA = (unsigned)__cvta_generic_to_shared(Ahi);
    unsigned baseB = (unsigned)__cvta_generic_to_shared(Bhi);

    int b = blockIdx.z, m0 = blockIdx.y * 128, t0 = blockIdx.x * 128;
    int tid = threadIdx.x, lane = tid & 31, wid = tid >> 5;
    int wm = wid >> 1, wn = wid & 1, g = lane >> 2, q = lane & 3;
    int grp = lane >> 3, lam = lane & 7;
    const float* Xb = (const float*)g_a + (size_t)b * CHN * T;
    int bc4 = tid & 7, bt4 = tid >> 3;

    float acc[2][8][4];
#pragma unroll
    for (int mt = 0; mt < 2; mt++)
#pragma unroll
        for (int nt = 0; nt < 8; nt++)
#pragma unroll
            for (int i = 0; i < 4; i++) acc[mt][nt][i] = 0.f;

    for (int k0 = 0; k0 < CHN; k0 += 32) {
#pragma unroll
        for (int i = 0; i < 4; i++) {
            int idx = tid + i * 256, row = idx >> 3, c4 = idx & 7;
            float4 w = *(const float4*)&W[(size_t)(m0 + row) * CHN + k0 + 4 * c4];
            *(uint4*)&Ahi[row * 36 + 4 * c4] =
                make_uint4(tf32r(w.x), tf32r(w.y), tf32r(w.z), tf32r(w.w));
        }
        {
            float4 r[4];
#pragma unroll
            for (int j = 0; j < 4; j++)
                r[j] = *(const float4*)&Xb[(size_t)(k0 + 4 * bc4 + j) * T + t0 + 4 * bt4];
#pragma unroll
            for (int jp = 0; jp < 4; jp++)
                *(uint4*)&Bhi[(4 * bt4 + jp) * 36 + 4 * bc4] =
                    make_uint4(tf32r((&r[0].x)[jp]), tf32r((&r[1].x)[jp]),
                               tf32r((&r[2].x)[jp]), tf32r((&r[3].x)[jp]));
        }
        __syncthreads();
#pragma unroll
        for (int ks = 0; ks < 4; ks++) {
            unsigned ah[2][4];
#pragma unroll
            for (int mt = 0; mt < 2; mt++) {
                unsigned row = wm * 32 + mt * 16 + (grp & 1) * 8 + lam;
                unsigned col = ks * 8 + (grp >> 1) * 4;
                ldsm4(ah[mt], baseA + (row * 36 + col) * 4);
            }
#pragma unroll
            for (int ntp = 0; ntp < 8; ntp += 2) {
                unsigned row = wn * 64 + (ntp + (grp >> 1)) * 8 + lam;
                unsigned col = ks * 8 + (grp & 1) * 4;
                unsigned bh[4];
                ldsm4(bh, baseB + (row * 36 + col) * 4);
#pragma unroll
                for (int mt = 0; mt < 2; mt++) {
                    mma8(acc[mt][ntp], ah[mt], bh[0], bh[1]);
                    mma8(acc[mt][ntp + 1], ah[mt], bh[2], bh[3]);
                }
            }
        }
        __syncthreads();
    }
#pragma unroll
    for (int mt = 0; mt < 2; mt++) {
        int row = m0 + wm * 32 + mt * 16 + g;
        float bi0 = bias[row], bi1 = bias[row + 8];
#pragma unroll
        for (int nt = 0; nt < 8; nt++) {
            int col = t0 + wn * 64 + nt * 8 + 2 * q;
            size_t i0 = ((size_t)b * CHN + row) * T + col;
            size_t i1 = ((size_t)b * CHN + row + 8) * T + col;
            float2 r0 = *(const float2*)&resid[i0];
            float2 r1 = *(const float2*)&resid[i1];
            *(float2*)&outp[i0] = make_float2(acc[mt][nt][0] + bi0 + r0.x,
                                              acc[mt][nt][1] + bi0 + r0.y);
            *(float2*)&outp[i1] = make_float2(acc[mt][nt][2] + bi1 + r1.x,
                                              acc[mt][nt][3] + bi1 + r1.y);
        }
    }
}

// ---------------------------------------------------------------------------
extern "C" void kernel_launch(void* const* d_in, const int* in_sizes, int n_in,
                              void* d_out, int out_size) {
    const float* x      = (const float*)d_in[0];
    const float* nw     = (const float*)d_in[1];
    const float* qkv_w  = (const float*)d_in[2];
    const float* qkv_b  = (const float*)d_in[3];
    const float* proj_w = (const float*)d_in[4];
    const float* proj_b = (const float*)d_in[5];
    float* out = (float*)d_out;

    const int QKV_SMEM  = 20480 * 4;  // 81920 (2 stages)
    const int PROJ_SMEM = 9216 * 4;   // 36864
    const int ATT_SMEM  = 18432 * 4;  // 73728 (Ps + 2 stages)
    static bool init = false;
    if (!init) {
        cudaFuncSetAttribute(qkv_mma,  cudaFuncAttributeMaxDynamicSharedMemorySize, QKV_SMEM);
        cudaFuncSetAttribute(proj_mma, cudaFuncAttributeMaxDynamicSharedMemorySize, PROJ_SMEM);
        cudaFuncSetAttribute(attn_mma, cudaFuncAttributeMaxDynamicSharedMemorySize, ATT_SMEM);
        cudaFuncSetAttribute(qkv_mma,  cudaFuncAttributePreferredSharedMemoryCarveout, 100);
        cudaFuncSetAttribute(proj_mma, cudaFuncAttributePreferredSharedMemoryCarveout, 100);
        cudaFuncSetAttribute(attn_mma, cudaFuncAttributePreferredSharedMemoryCarveout, 100);
        init = true;
    }
    rms_kernel<<<256, 256>>>(x);
    prep_w<<<768, 256>>>(qkv_w);
    prep_x<<<dim3(64, 8, 2), 256>>>(x, nw);
    qkv_mma<<<dim3(32, 12, 2), 256, QKV_SMEM>>>(qkv_b);
    prep_qk<<<dim3(64, 16, 2), 256>>>();
    attn_mma<<<dim3(32, 16), 256, ATT_SMEM>>>();
    proj_mma<<<dim3(32, 4, 2), 256, PROJ_SMEM>>>(proj_w, proj_b, x, out);
}

// round 15
// speedup vs baseline: 2.2153x; 1.0668x over previous
#include <cuda_runtime.h>
#include <cuda_fp16.h>
#include <math.h>

#define T   4096
#define CHN 512
#define M3  1536

__device__ float g_ir[2 * T];
__device__ float g_a[(size_t)2 * CHN * T];
__device__ unsigned g_xh[(size_t)2 * T * 256], g_xl[(size_t)2 * T * 256];
__device__ unsigned g_wh[(size_t)M3 * 256],    g_wl[(size_t)M3 * 256];
__device__ unsigned g_vh[(size_t)2 * M3 * 2048];                 // v hi plane ([c][t] pairs)
__device__ unsigned g_qTh[(size_t)16 * T * 32], g_qTl[(size_t)16 * T * 32];
__device__ unsigned g_kTh[(size_t)16 * T * 32], g_kTl[(size_t)16 * T * 32];

__device__ __forceinline__ unsigned tf32r(float x) {
    unsigned r; asm("cvt.rna.tf32.f32 %0, %1;" : "=r"(r) : "f"(x)); return r;
}
__device__ __forceinline__ float ex2(float x) {
    float r; asm("ex2.approx.f32 %0, %1;" : "=f"(r) : "f"(x)); return r;
}
__device__ __forceinline__ void mma8(float c[4], const unsigned a[4],
                                     unsigned b0, unsigned b1) {
    asm volatile("mma.sync.aligned.m16n8k8.row.col.f32.tf32.tf32.f32 "
                 "{%0,%1,%2,%3}, {%4,%5,%6,%7}, {%8,%9}, {%0,%1,%2,%3};"
                 : "+f"(c[0]), "+f"(c[1]), "+f"(c[2]), "+f"(c[3])
                 : "r"(a[0]), "r"(a[1]), "r"(a[2]), "r"(a[3]), "r"(b0), "r"(b1));
}
__device__ __forceinline__ void mma16(float c[4], const unsigned a[4],
                                      unsigned b0, unsigned b1) {
    asm volatile("mma.sync.aligned.m16n8k16.row.col.f32.f16.f16.f32 "
                 "{%0,%1,%2,%3}, {%4,%5,%6,%7}, {%8,%9}, {%0,%1,%2,%3};"
                 : "+f"(c[0]), "+f"(c[1]), "+f"(c[2]), "+f"(c[3])
                 : "r"(a[0]), "r"(a[1]), "r"(a[2]), "r"(a[3]), "r"(b0), "r"(b1));
}
__device__ __forceinline__ void ldsm4(unsigned r[4], unsigned addr) {
    asm volatile("ldmatrix.sync.aligned.m8n8.x4.shared.b16 {%0,%1,%2,%3}, [%4];"
                 : "=r"(r[0]), "=r"(r[1]), "=r"(r[2]), "=r"(r[3]) : "r"(addr));
}
__device__ __forceinline__ void split2(float v0, float v1, unsigned& hi, unsigned& lo) {
    __half h0 = __float2half_rn(v0), h1 = __float2half_rn(v1);
    __half2 hh = __halves2half2(h0, h1);
    hi = *reinterpret_cast<unsigned*>(&hh);
    __half l0 = __float2half_rn(v0 - __half2float(h0));
    __half l1 = __float2half_rn(v1 - __half2float(h1));
    __half2 ll = __halves2half2(l0, l1);
    lo = *reinterpret_cast<unsigned*>(&ll);
}
__device__ __forceinline__ unsigned pack2h(float a, float b) {
    __half2 p = __floats2half2_rn(a, b);
    return *reinterpret_cast<unsigned*>(&p);
}
__device__ __forceinline__ void cpa(unsigned saddr, const unsigned* g) {
    asm volatile("cp.async.cg.shared.global [%0], [%1], 16;"
                 :: "r"(saddr), "l"(g) : "memory");
}
#define CPA_COMMIT asm volatile("cp.async.commit_group;" ::: "memory")
#define CPA_WAIT0  asm volatile("cp.async.wait_group 0;" ::: "memory")

// ---------------------------------------------------------------------------
__global__ void __launch_bounds__(256) rms_kernel(const float* __restrict__ x) {
    __shared__ float red[8][32];
    int l = threadIdx.x & 31, w = threadIdx.x >> 5;
    int i = blockIdx.x * 32 + l;
    int b = i >> 12, t = i & (T - 1);
    const float* xp = x + (size_t)b * CHN * T + t + (size_t)(w * 64) * T;
    float s = 0.f;
#pragma unroll 16
    for (int j = 0; j < 64; j++) { float v = xp[(size_t)j * T]; s = fmaf(v, v, s); }
    red[w][l] = s;
    __syncthreads();
    if (w == 0) {
        float tot = red[0][l];
#pragma unroll
        for (int k = 1; k < 8; k++) tot += red[k][l];
        g_ir[i] = 22.62741699796952f * rsqrtf(tot * (1.f / CHN) + 1e-8f);
    }
}

__global__ void __launch_bounds__(256) prep_w(const float* __restrict__ W) {
    int i = blockIdx.x * 256 + threadIdx.x;
    float4 w = *(const float4*)&W[(size_t)i * 4];
    unsigned h01, l01, h23, l23;
    split2(w.x * 256.f, w.y * 256.f, h01, l01);
    split2(w.z * 256.f, w.w * 256.f, h23, l23);
    *(uint2*)&g_wh[2 * (size_t)i] = make_uint2(h01, h23);
    *(uint2*)&g_wl[2 * (size_t)i] = make_uint2(l01, l23);
}

__global__ void __launch_bounds__(256) prep_x(const float* __restrict__ x,
                                              const float* __restrict__ nw) {
    __shared__ float sx[64][65];
    int t0 = blockIdx.x * 64, c0 = blockIdx.y * 64, b = blockIdx.z;
    int tid = threadIdx.x;
#pragma unroll
    for (int i = 0; i < 4; i++) {
        int idx = tid + i * 256;
        int c = idx >> 4, f = idx & 15;
        float4 v = *(const float4*)&x[((size_t)b * CHN + c0 + c) * T + t0 + 4 * f];
        float s = nw[c0 + c];
        float4 ir = *(const float4*)&g_ir[b * T + t0 + 4 * f];
        sx[c][4 * f + 0] = v.x * s * ir.x; sx[c][4 * f + 1] = v.y * s * ir.y;
        sx[c][4 * f + 2] = v.z * s * ir.z; sx[c][4 * f + 3] = v.w * s * ir.w;
    }
    __syncthreads();
#pragma unroll
    for (int i = 0; i < 8; i++) {
        int idx = tid + i * 256;
        int t = idx >> 5, cp = idx & 31;
        unsigned h, l;
        split2(sx[2 * cp][t], sx[2 * cp + 1][t], h, l);
        size_t dst = ((size_t)b * T + t0 + t) * 256 + (c0 >> 1) + cp;
        g_xh[dst] = h; g_xl[dst] = l;
    }
}

// ---------------------------------------------------------------------------
// QKV GEMM, fp16 split, cp.async 2-stage, one barrier per k-tile.
// Fused epilogue: q/k rows -> transposed split planes (via smem), v -> hi plane.
__global__ void __launch_bounds__(256, 2) qkv_mma(const float* __restrict__ bias) {
    extern __shared__ unsigned smg[];
    unsigned base = (unsigned)__cvta_generic_to_shared(smg);

    int b = blockIdx.z, m0 = blockIdx.y * 128, t0 = blockIdx.x * 128;
    int tid = threadIdx.x, lane = tid & 31, wid = tid >> 5;
    int wm = wid >> 1, wn = wid & 1, g = lane >> 2, q = lane & 3;
    int grp = lane >> 3, lam = lane & 7;

    float acc[2][8][4];
#pragma unroll
    for (int mt = 0; mt < 2; mt++)
#pragma unroll
        for (int nt = 0; nt < 8; nt++)
#pragma unroll
            for (int i = 0; i < 4; i++) acc[mt][nt][i] = 0.f;

    auto fill = [&](int kc, int st) {
        unsigned sb0 = base + st * 10240 * 4;
#pragma unroll
        for (int i = 0; i < 2; i++) {
            int idx = tid + i * 256, row = idx >> 2, u = idx & 3;
            unsigned off = (row * 20 + 4 * u) * 4;
            size_t sa = (size_t)(m0 + row) * 256 + kc * 16 + 4 * u;
            cpa(sb0 + off,            &g_wh[sa]);
            cpa(sb0 + 2560 * 4 + off, &g_wl[sa]);
            size_t sb = ((size_t)b * T + t0 + row) * 256 + kc * 16 + 4 * u;
            cpa(sb0 + 5120 * 4 + off, &g_xh[sb]);
            cpa(sb0 + 7680 * 4 + off, &g_xl[sb]);
        }
    };

    fill(0, 0); CPA_COMMIT;
    for (int kc = 0; kc < 16; kc++) {
        CPA_WAIT0;
        __syncthreads();
        if (kc < 15) { fill(kc + 1, (kc + 1) & 1); CPA_COMMIT; }
        unsigned stb = base + (kc & 1) * 10240 * 4;
        unsigned baseAh = stb, baseAl = stb + 2560 * 4;
        unsigned baseBh = stb + 5120 * 4, baseBl = stb + 7680 * 4;
#pragma unroll
        for (int ks = 0; ks < 2; ks++) {
            unsigned ah[2][4], al[2][4];
#pragma unroll
            for (int mt = 0; mt < 2; mt++) {
                unsigned row = wm * 32 + mt * 16 + (grp & 1) * 8 + lam;
                unsigned col = ks * 8 + (grp >> 1) * 4;
                unsigned off = (row * 20 + col) * 4;
                ldsm4(ah[mt], baseAh + off);
                ldsm4(al[mt], baseAl + off);
            }
#pragma unroll
            for (int half = 0; half < 2; half++) {
                unsigned bh[2][4], bl[2][4];
#pragma unroll
                for (int p = 0; p < 2; p++) {
                    int ntp = half * 4 + 2 * p;
                    unsigned row = wn * 64 + (ntp + (grp >> 1)) * 8 + lam;
                    unsigned col = ks * 8 + (grp & 1) * 4;
                    unsigned off = (row * 20 + col) * 4;
                    ldsm4(bh[p], baseBh + off);
                    ldsm4(bl[p], baseBl + off);
                }
#pragma unroll
                for (int p = 0; p < 2; p++)
#pragma unroll
                    for (int mt = 0; mt < 2; mt++) {
                        mma16(acc[mt][half * 4 + 2 * p],     ah[mt], bh[p][0], bh[p][1]);
                        mma16(acc[mt][half * 4 + 2 * p + 1], ah[mt], bh[p][2], bh[p][3]);
                    }
#pragma unroll
                for (int p = 0; p < 2; p++)
#pragma unroll
                    for (int mt = 0; mt < 2; mt++) {
                        mma16(acc[mt][half * 4 + 2 * p],     ah[mt], bl[p][0], bl[p][1]);
                        mma16(acc[mt][half * 4 + 2 * p + 1], ah[mt], bl[p][2], bl[p][3]);
                    }
#pragma unroll
                for (int p = 0; p < 2; p++)
#pragma unroll
                    for (int mt = 0; mt < 2; mt++) {
                        mma16(acc[mt][half * 4 + 2 * p],     al[mt], bh[p][0], bh[p][1]);
                        mma16(acc[mt][half * 4 + 2 * p + 1], al[mt], bh[p][2], bh[p][3]);
                    }
            }
        }
        __syncthreads();
    }

    // ---- phase 1: final values into smem ts[t][row] (row stride 133) ----
    float* ts = (float*)smg;
#pragma unroll
    for (int mt = 0; mt < 2; mt++) {
        int rowl = wm * 32 + mt * 16 + g;
        int row = m0 + rowl;
        float bi0 = bias[row], bi1 = bias[row + 8];
        // q rows pre-scaled by ch^-0.5 * log2(e) for exp2-domain softmax
        float s0 = ((row % 192) < 64) ? 0.18033688f : 1.f;
        float s1 = (((row + 8) % 192) < 64) ? 0.18033688f : 1.f;
#pragma unroll
        for (int nt = 0; nt < 8; nt++) {
            int coll = wn * 64 + nt * 8 + 2 * q;
            ts[coll * 133 + rowl]           = (acc[mt][nt][0] * (1.f / 256.f) + bi0) * s0;
            ts[(coll + 1) * 133 + rowl]     = (acc[mt][nt][1] * (1.f / 256.f) + bi0) * s0;
            ts[coll * 133 + rowl + 8]       = (acc[mt][nt][2] * (1.f / 256.f) + bi1) * s1;
            ts[(coll + 1) * 133 + rowl + 8] = (acc[mt][nt][3] * (1.f / 256.f) + bi1) * s1;
        }
    }
    __syncthreads();

    // ---- phase 2: emit per-segment outputs ----
#pragma unroll
    for (int half = 0; half < 2; half++) {
        int grow0 = m0 + half * 64;
        int st = (grow0 / 64) % 3;           // 0=q, 1=k, 2=v
        int hh2 = grow0 / 192;
        if (st < 2) {
            unsigned* dH = st ? g_kTh : g_qTh;
            unsigned* dL = st ? g_kTl : g_qTl;
            size_t obase = ((size_t)(b * 8 + hh2) * T + t0) * 32;
#pragma unroll
            for (int i = 0; i < 16; i++) {
                int idx = tid + i * 256;
                int t = idx >> 5, cp = idx & 31;
                unsigned h, l;
                split2(ts[t * 133 + half * 64 + 2 * cp],
                       ts[t * 133 + half * 64 + 2 * cp + 1], h, l);
                size_t d = obase + (size_t)t * 32 + cp;
                dH[d] = h; dL[d] = l;
            }
        } else {
#pragma unroll
            for (int i = 0; i < 16; i++) {
                int idx = tid + i * 256;
                int c = idx >> 6, tp = idx & 63;
                unsigned h, l;
                split2(ts[(2 * tp) * 133 + half * 64 + c],
                       ts[(2 * tp + 1) * 133 + half * 64 + c], h, l);
                g_vh[((size_t)b * M3 + grow0 + c) * 2048 + ((t0 >> 1) + tp)] = h;
            }
        }
    }
}

// ---------------------------------------------------------------------------
// Flash attention: QK^T split fp16, PV with P kept in registers (C-frag==A-frag).
__global__ void __launch_bounds__(256, 2) attn_mma() {
    extern __shared__ unsigned sma[];
    unsigned base = (unsigned)__cvta_generic_to_shared(sma);
    unsigned* Ps  = sma;
    unsigned* Qlo = sma + 4608;
    unsigned basePs = base;
    unsigned baseQl = base + 4608 * 4;

    int t0 = blockIdx.x * 128, head = blockIdx.y;
    int b = head >> 3, hh = head & 7;
    int tid = threadIdx.x, lane = tid & 31, wid = tid >> 5;
    int g = lane >> 2, q = lane & 3, rb = wid * 16;
    int grp = lane >> 3, lam = lane & 7;

    const unsigned* qThp = g_qTh + ((size_t)head * T + t0) * 32;
    const unsigned* qTlp = g_qTl + ((size_t)head * T + t0) * 32;
    const unsigned* kThp = g_kTh + (size_t)head * T * 32;
    const unsigned* kTlp = g_kTl + (size_t)head * T * 32;
    const unsigned* vhp  = g_vh + ((size_t)b * M3 + hh * 192 + 128) * 2048;

#pragma unroll
    for (int i = 0; i < 4; i++) {
        int idx = tid + i * 256, row = idx >> 3, u = idx & 7;
        *(uint4*)&Ps[row * 36 + 4 * u]  = *(const uint4*)&qThp[(size_t)row * 32 + 4 * u];
        *(uint4*)&Qlo[row * 36 + 4 * u] = *(const uint4*)&qTlp[(size_t)row * 32 + 4 * u];
    }
    __syncthreads();
    unsigned qh[4][4], ql[4][4];
#pragma unroll
    for (int ks = 0; ks < 4; ks++) {
        unsigned row = rb + (grp & 1) * 8 + lam;
        unsigned col = ks * 8 + (grp >> 1) * 4;
        unsigned off = (row * 36 + col) * 4;
        ldsm4(qh[ks], basePs + off);
        ldsm4(ql[ks], baseQl + off);
    }
    __syncthreads();   // q frags loaded before stage0 overwrites Qlo

    auto fillKV = [&](int it, int st) {
        unsigned sb0 = base + (4608 + st * 6912) * 4;
        int s0 = it * 64;
#pragma unroll
        for (int i = 0; i < 2; i++) {
            int idx = tid + i * 256, row = idx >> 3, u = idx & 7;
            unsigned off = (row * 36 + 4 * u) * 4;
            cpa(sb0 + off,            &kThp[(size_t)(s0 + row) * 32 + 4 * u]);
            cpa(sb0 + 2304 * 4 + off, &kTlp[(size_t)(s0 + row) * 32 + 4 * u]);
            cpa(sb0 + 4608 * 4 + off, &vhp[(size_t)row * 2048 + (s0 >> 1) + 4 * u]);
        }
    };

    float o[8][4];
#pragma unroll
    for (int nt = 0; nt < 8; nt++)
#pragma unroll
        for (int i = 0; i < 4; i++) o[nt][i] = 0.f;
    float m_a = -1e30f, m_b = -1e30f, l_a = 0.f, l_b = 0.f;

    fillKV(0, 0); CPA_COMMIT;
    for (int it = 0; it < 64; it++) {
        CPA_WAIT0;
        __syncthreads();
        if (it < 63) { fillKV(it + 1, (it + 1) & 1); CPA_COMMIT; }
        unsigned stb = base + (4608 + (it & 1) * 6912) * 4;
        unsigned baseKh = stb, baseKl = stb + 2304 * 4, baseVh = stb + 4608 * 4;

        float sacc[8][4];
#pragma unroll
        for (int nt = 0; nt < 8; nt++)
#pragma unroll
            for (int i = 0; i < 4; i++) sacc[nt][i] = 0.f;
#pragma unroll
        for (int ks = 0; ks < 4; ks++) {
#pragma unroll
            for (int half = 0; half < 2; half++) {
                unsigned kh[2][4], kl[2][4];
#pragma unroll
                for (int p = 0; p < 2; p++) {
                    int ntp = half * 4 + 2 * p;
                    unsigned row = (ntp + (grp >> 1)) * 8 + lam;
                    unsigned col = ks * 8 + (grp & 1) * 4;
                    unsigned off = (row * 36 + col) * 4;
                    ldsm4(kh[p], baseKh + off);
                    ldsm4(kl[p], baseKl + off);
                }
#pragma unroll
                for (int p = 0; p < 2; p++) {
                    mma16(sacc[half * 4 + 2 * p],     qh[ks], kh[p][0], kh[p][1]);
                    mma16(sacc[half * 4 + 2 * p + 1], qh[ks], kh[p][2], kh[p][3]);
                }
#pragma unroll
                for (int p = 0; p < 2; p++) {
                    mma16(sacc[half * 4 + 2 * p],     qh[ks], kl[p][0], kl[p][1]);
                    mma16(sacc[half * 4 + 2 * p + 1], qh[ks], kl[p][2], kl[p][3]);
                }
#pragma unroll
                for (int p = 0; p < 2; p++) {
                    mma16(sacc[half * 4 + 2 * p],     ql[ks], kh[p][0], kh[p][1]);
                    mma16(sacc[half * 4 + 2 * p + 1], ql[ks], kh[p][2], kh[p][3]);
                }
            }
        }

        float mx_a = -1e30f, mx_b = -1e30f;
#pragma unroll
        for (int nt = 0; nt < 8; nt++) {
            mx_a = fmaxf(mx_a, fmaxf(sacc[nt][0], sacc[nt][1]));
            mx_b = fmaxf(mx_b, fmaxf(sacc[nt][2], sacc[nt][3]));
        }
        mx_a = fmaxf(mx_a, __shfl_xor_sync(~0u, mx_a, 1));
        mx_a = fmaxf(mx_a, __shfl_xor_sync(~0u, mx_a, 2));
        mx_b = fmaxf(mx_b, __shfl_xor_sync(~0u, mx_b, 1));
        mx_b = fmaxf(mx_b, __shfl_xor_sync(~0u, mx_b, 2));
        float mn_a = fmaxf(m_a, mx_a), mn_b = fmaxf(m_b, mx_b);
        float ca = ex2(m_a - mn_a), cb = ex2(m_b - mn_b);
        float sum_a = 0.f, sum_b = 0.f;
        unsigned ph2[8][2];
#pragma unroll
        for (int nt = 0; nt < 8; nt++) {
            float p0 = ex2(sacc[nt][0] - mn_a), p1 = ex2(sacc[nt][1] - mn_a);
            float p2 = ex2(sacc[nt][2] - mn_b), p3 = ex2(sacc[nt][3] - mn_b);
            sum_a += p0 + p1; sum_b += p2 + p3;
            ph2[nt][0] = pack2h(p0, p1);
            ph2[nt][1] = pack2h(p2, p3);
        }
        sum_a += __shfl_xor_sync(~0u, sum_a, 1);
        sum_a += __shfl_xor_sync(~0u, sum_a, 2);
        sum_b += __shfl_xor_sync(~0u, sum_b, 1);
        sum_b += __shfl_xor_sync(~0u, sum_b, 2);
        m_a = mn_a; m_b = mn_b;
        l_a = l_a * ca + sum_a; l_b = l_b * cb + sum_b;
#pragma unroll
        for (int nt = 0; nt < 8; nt++) {
            o[nt][0] *= ca; o[nt][1] *= ca; o[nt][2] *= cb; o[nt][3] *= cb;
        }
        // PV: P fragments come straight from registers (C-frag == A-frag layout)
#pragma unroll
        for (int ks = 0; ks < 4; ks++) {
            unsigned pa[4] = { ph2[2 * ks][0], ph2[2 * ks][1],
                               ph2[2 * ks + 1][0], ph2[2 * ks + 1][1] };
#pragma unroll
            for (int ntp = 0; ntp < 8; ntp += 2) {
                unsigned row = (ntp + (grp >> 1)) * 8 + lam;
                unsigned col = ks * 8 + (grp & 1) * 4;
                unsigned vh[4];
                ldsm4(vh, baseVh + (row * 36 + col) * 4);
                mma16(o[ntp],     pa, vh[0], vh[1]);
                mma16(o[ntp + 1], pa, vh[2], vh[3]);
            }
        }
    }

    float inv_a = 1.f / l_a, inv_b = 1.f / l_b;
    float* ab = g_a + ((size_t)b * CHN + hh * 64) * T;
#pragma unroll
    for (int nt = 0; nt < 8; nt++) {
        int c0 = nt * 8 + 2 * q;
        ab[(size_t)c0 * T + t0 + rb + g]           = o[nt][0] * inv_a;
        ab[(size_t)(c0 + 1) * T + t0 + rb + g]     = o[nt][1] * inv_a;
        ab[(size_t)c0 * T + t0 + rb + g + 8]       = o[nt][2] * inv_b;
        ab[(size_t)(c0 + 1) * T + t0 + rb + g + 8] = o[nt][3] * inv_b;
    }
}

// ---------------------------------------------------------------------------
// proj GEMM + bias + residual: single tf32 (unchanged proven path).
__global__ void __launch_bounds__(256, 2) proj_mma(
        const float* __restrict__ W, const float* __restrict__ bias,
        const float* __restrict__ resid, float* __restrict__ outp)
{
    extern __shared__ unsigned smg[];
    unsigned* Ahi = smg;              // [128][36]
    unsigned* Bhi = smg + 4608;       // [128][36]
    unsigned baseA = (unsigned)__cvta_generic_to_shared(Ahi);
    unsigned baseB = (unsigned)__cvta_generic_to_shared(Bhi);

    int b = blockIdx.z, m0 = blockIdx.y * 128, t0 = blockIdx.x * 128;
    int tid = threadIdx.x, lane = tid & 31, wid = tid >> 5;
    int wm = wid >> 1, wn = wid & 1, g = lane >> 2, q = lane & 3;
    int grp = lane >> 3, lam = lane & 7;
    const float* Xb = (const float*)g_a + (size_t)b * CHN * T;
    int bc4 = tid & 7, bt4 = tid >> 3;

    float acc[2][8][4];
#pragma unroll
    for (int mt = 0; mt < 2; mt++)
#pragma unroll
        for (int nt = 0; nt < 8; nt++)
#pragma unroll
            for (int i = 0; i < 4; i++) acc[mt][nt][i] = 0.f;

    for (int k0 = 0; k0 < CHN; k0 += 32) {
#pragma unroll
        for (int i = 0; i < 4; i++) {
            int idx = tid + i * 256, row = idx >> 3, c4 = idx & 7;
            float4 w = *(const float4*)&W[(size_t)(m0 + row) * CHN + k0 + 4 * c4];
            *(uint4*)&Ahi[row * 36 + 4 * c4] =
                make_uint4(tf32r(w.x), tf32r(w.y), tf32r(w.z), tf32r(w.w));
        }
        {
            float4 r[4];
#pragma unroll
            for (int j = 0; j < 4; j++)
                r[j] = *(const float4*)&Xb[(size_t)(k0 + 4 * bc4 + j) * T + t0 + 4 * bt4];
#pragma unroll
            for (int jp = 0; jp < 4; jp++)
                *(uint4*)&Bhi[(4 * bt4 + jp) * 36 + 4 * bc4] =
                    make_uint4(tf32r((&r[0].x)[jp]), tf32r((&r[1].x)[jp]),
                               tf32r((&r[2].x)[jp]), tf32r((&r[3].x)[jp]));
        }
        __syncthreads();
#pragma unroll
        for (int ks = 0; ks < 4; ks++) {
            unsigned ah[2][4];
#pragma unroll
            for (int mt = 0; mt < 2; mt++) {
                unsigned row = wm * 32 + mt * 16 + (grp & 1) * 8 + lam;
                unsigned col = ks * 8 + (grp >> 1) * 4;
                ldsm4(ah[mt], baseA + (row * 36 + col) * 4);
            }
#pragma unroll
            for (int ntp = 0; ntp < 8; ntp += 2) {
                unsigned row = wn * 64 + (ntp + (grp >> 1)) * 8 + lam;
                unsigned col = ks * 8 + (grp & 1) * 4;
                unsigned bh[4];
                ldsm4(bh, baseB + (row * 36 + col) * 4);
#pragma unroll
                for (int mt = 0; mt < 2; mt++) {
                    mma8(acc[mt][ntp], ah[mt], bh[0], bh[1]);
                    mma8(acc[mt][ntp + 1], ah[mt], bh[2], bh[3]);
                }
            }
        }
        __syncthreads();
    }
#pragma unroll
    for (int mt = 0; mt < 2; mt++) {
        int row = m0 + wm * 32 + mt * 16 + g;
        float bi0 = bias[row], bi1 = bias[row + 8];
#pragma unroll
        for (int nt = 0; nt < 8; nt++) {
            int col = t0 + wn * 64 + nt * 8 + 2 * q;
            size_t i0 = ((size_t)b * CHN + row) * T + col;
            size_t i1 = ((size_t)b * CHN + row + 8) * T + col;
            float2 r0 = *(const float2*)&resid[i0];
            float2 r1 = *(const float2*)&resid[i1];
            *(float2*)&outp[i0] = make_float2(acc[mt][nt][0] + bi0 + r0.x,
                                              acc[mt][nt][1] + bi0 + r0.y);
            *(float2*)&outp[i1] = make_float2(acc[mt][nt][2] + bi1 + r1.x,
                                              acc[mt][nt][3] + bi1 + r1.y);
        }
    }
}

// ---------------------------------------------------------------------------
extern "C" void kernel_launch(void* const* d_in, const int* in_sizes, int n_in,
                              void* d_out, int out_size) {
    const float* x      = (const float*)d_in[0];
    const float* nw     = (const float*)d_in[1];
    const float* qkv_w  = (const float*)d_in[2];
    const float* qkv_b  = (const float*)d_in[3];
    const float* proj_w = (const float*)d_in[4];
    const float* proj_b = (const float*)d_in[5];
    float* out = (float*)d_out;

    const int QKV_SMEM  = 20480 * 4;  // 81920 (2 stages; epilogue reuses as ts)
    const int PROJ_SMEM = 9216 * 4;   // 36864
    const int ATT_SMEM  = 18432 * 4;  // 73728 (Ps + 2 stages)
    static bool init = false;
    if (!init) {
        cudaFuncSetAttribute(qkv_mma,  cudaFuncAttributeMaxDynamicSharedMemorySize, QKV_SMEM);
        cudaFuncSetAttribute(proj_mma, cudaFuncAttributeMaxDynamicSharedMemorySize, PROJ_SMEM);
        cudaFuncSetAttribute(attn_mma, cudaFuncAttributeMaxDynamicSharedMemorySize, ATT_SMEM);
        cudaFuncSetAttribute(qkv_mma,  cudaFuncAttributePreferredSharedMemoryCarveout, 100);
        cudaFuncSetAttribute(proj_mma, cudaFuncAttributePreferredSharedMemoryCarveout, 100);
        cudaFuncSetAttribute(attn_mma, cudaFuncAttributePreferredSharedMemoryCarveout, 100);
        init = true;
    }
    rms_kernel<<<256, 256>>>(x);
    prep_w<<<768, 256>>>(qkv_w);
    prep_x<<<dim3(64, 8, 2), 256>>>(x, nw);
    qkv_mma<<<dim3(32, 12, 2), 256, QKV_SMEM>>>(qkv_b);
    attn_mma<<<dim3(32, 16), 256, ATT_SMEM>>>();
    proj_mma<<<dim3(32, 4, 2), 256, PROJ_SMEM>>>(proj_w, proj_b, x, out);
}

// round 17
// speedup vs baseline: 2.3280x; 1.0509x over previous
#include <cuda_runtime.h>
#include <cuda_fp16.h>
#include <math.h>

#define T   4096
#define CHN 512
#define M3  1536

__device__ float g_ir[2 * T];
__device__ unsigned g_xh[(size_t)2 * T * 256], g_xl[(size_t)2 * T * 256];
__device__ unsigned g_wh[(size_t)M3 * 256],    g_wl[(size_t)M3 * 256];
__device__ unsigned g_pwh[(size_t)CHN * 256];                    // proj_w hi ([o][c] pairs)
__device__ unsigned g_vh[(size_t)2 * M3 * 2048];                 // v hi plane ([c][t] pairs)
__device__ unsigned g_aTh[(size_t)2 * T * 256];                  // a hi plane ([t][c] pairs)
__device__ unsigned g_qTh[(size_t)16 * T * 32], g_qTl[(size_t)16 * T * 32];
__device__ unsigned g_kTh[(size_t)16 * T * 32], g_kTl[(size_t)16 * T * 32];

__device__ __forceinline__ float ex2(float x) {
    float r; asm("ex2.approx.f32 %0, %1;" : "=f"(r) : "f"(x)); return r;
}
__device__ __forceinline__ void mma16(float c[4], const unsigned a[4],
                                      unsigned b0, unsigned b1) {
    asm volatile("mma.sync.aligned.m16n8k16.row.col.f32.f16.f16.f32 "
                 "{%0,%1,%2,%3}, {%4,%5,%6,%7}, {%8,%9}, {%0,%1,%2,%3};"
                 : "+f"(c[0]), "+f"(c[1]), "+f"(c[2]), "+f"(c[3])
                 : "r"(a[0]), "r"(a[1]), "r"(a[2]), "r"(a[3]), "r"(b0), "r"(b1));
}
__device__ __forceinline__ void ldsm4(unsigned r[4], unsigned addr) {
    asm volatile("ldmatrix.sync.aligned.m8n8.x4.shared.b16 {%0,%1,%2,%3}, [%4];"
                 : "=r"(r[0]), "=r"(r[1]), "=r"(r[2]), "=r"(r[3]) : "r"(addr));
}
__device__ __forceinline__ void split2(float v0, float v1, unsigned& hi, unsigned& lo) {
    __half h0 = __float2half_rn(v0), h1 = __float2half_rn(v1);
    __half2 hh = __halves2half2(h0, h1);
    hi = *reinterpret_cast<unsigned*>(&hh);
    __half l0 = __float2half_rn(v0 - __half2float(h0));
    __half l1 = __float2half_rn(v1 - __half2float(h1));
    __half2 ll = __halves2half2(l0, l1);
    lo = *reinterpret_cast<unsigned*>(&ll);
}
__device__ __forceinline__ unsigned pack2h(float a, float b) {
    __half2 p = __floats2half2_rn(a, b);
    return *reinterpret_cast<unsigned*>(&p);
}
__device__ __forceinline__ void cpa(unsigned saddr, const unsigned* g) {
    asm volatile("cp.async.cg.shared.global [%0], [%1], 16;"
                 :: "r"(saddr), "l"(g) : "memory");
}
#define CPA_COMMIT asm volatile("cp.async.commit_group;" ::: "memory")
#define CPA_WAIT0  asm volatile("cp.async.wait_group 0;" ::: "memory")

// ---------------------------------------------------------------------------
__global__ void __launch_bounds__(256) rms_kernel(const float* __restrict__ x) {
    __shared__ float red[8][32];
    int l = threadIdx.x & 31, w = threadIdx.x >> 5;
    int i = blockIdx.x * 32 + l;
    int b = i >> 12, t = i & (T - 1);
    const float* xp = x + (size_t)b * CHN * T + t + (size_t)(w * 64) * T;
    float s = 0.f;
#pragma unroll 16
    for (int j = 0; j < 64; j++) { float v = xp[(size_t)j * T]; s = fmaf(v, v, s); }
    red[w][l] = s;
    __syncthreads();
    if (w == 0) {
        float tot = red[0][l];
#pragma unroll
        for (int k = 1; k < 8; k++) tot += red[k][l];
        g_ir[i] = 22.62741699796952f * rsqrtf(tot * (1.f / CHN) + 1e-8f);
    }
}

__global__ void __launch_bounds__(256) prep_w(const float* __restrict__ W) {
    int i = blockIdx.x * 256 + threadIdx.x;
    float4 w = *(const float4*)&W[(size_t)i * 4];
    unsigned h01, l01, h23, l23;
    split2(w.x * 256.f, w.y * 256.f, h01, l01);
    split2(w.z * 256.f, w.w * 256.f, h23, l23);
    *(uint2*)&g_wh[2 * (size_t)i] = make_uint2(h01, h23);
    *(uint2*)&g_wl[2 * (size_t)i] = make_uint2(l01, l23);
}

__global__ void __launch_bounds__(256) prep_pw(const float* __restrict__ W) {
    int i = blockIdx.x * 256 + threadIdx.x;   // 65536 float4 (512x512)
    float4 w = *(const float4*)&W[(size_t)i * 4];
    *(uint2*)&g_pwh[2 * (size_t)i] = make_uint2(
        pack2h(w.x * 256.f, w.y * 256.f), pack2h(w.z * 256.f, w.w * 256.f));
}

__global__ void __launch_bounds__(256) prep_x(const float* __restrict__ x,
                                              const float* __restrict__ nw) {
    __shared__ float sx[64][65];
    int t0 = blockIdx.x * 64, c0 = blockIdx.y * 64, b = blockIdx.z;
    int tid = threadIdx.x;
#pragma unroll
    for (int i = 0; i < 4; i++) {
        int idx = tid + i * 256;
        int c = idx >> 4, f = idx & 15;
        float4 v = *(const float4*)&x[((size_t)b * CHN + c0 + c) * T + t0 + 4 * f];
        float s = nw[c0 + c];
        float4 ir = *(const float4*)&g_ir[b * T + t0 + 4 * f];
        sx[c][4 * f + 0] = v.x * s * ir.x; sx[c][4 * f + 1] = v.y * s * ir.y;
        sx[c][4 * f + 2] = v.z * s * ir.z; sx[c][4 * f + 3] = v.w * s * ir.w;
    }
    __syncthreads();
#pragma unroll
    for (int i = 0; i < 8; i++) {
        int idx = tid + i * 256;
        int t = idx >> 5, cp = idx & 31;
        unsigned h, l;
        split2(sx[2 * cp][t], sx[2 * cp + 1][t], h, l);
        size_t dst = ((size_t)b * T + t0 + t) * 256 + (c0 >> 1) + cp;
        g_xh[dst] = h; g_xl[dst] = l;
    }
}

// ---------------------------------------------------------------------------
// QKV GEMM, fp16 split, cp.async 2-stage, one barrier per k-tile.
// Fused epilogue: q/k -> transposed split planes; v -> hi plane.
__global__ void __launch_bounds__(256, 2) qkv_mma(const float* __restrict__ bias) {
    extern __shared__ unsigned smg[];
    unsigned base = (unsigned)__cvta_generic_to_shared(smg);

    int b = blockIdx.z, m0 = blockIdx.y * 128, t0 = blockIdx.x * 128;
    int tid = threadIdx.x, lane = tid & 31, wid = tid >> 5;
    int wm = wid >> 1, wn = wid & 1, g = lane >> 2, q = lane & 3;
    int grp = lane >> 3, lam = lane & 7;

    float acc[2][8][4];
#pragma unroll
    for (int mt = 0; mt < 2; mt++)
#pragma unroll
        for (int nt = 0; nt < 8; nt++)
#pragma unroll
            for (int i = 0; i < 4; i++) acc[mt][nt][i] = 0.f;

    auto fill = [&](int kc, int st) {
        unsigned sb0 = base + st * 10240 * 4;
#pragma unroll
        for (int i = 0; i < 2; i++) {
            int idx = tid + i * 256, row = idx >> 2, u = idx & 3;
            unsigned off = (row * 20 + 4 * u) * 4;
            size_t sa = (size_t)(m0 + row) * 256 + kc * 16 + 4 * u;
            cpa(sb0 + off,            &g_wh[sa]);
            cpa(sb0 + 2560 * 4 + off, &g_wl[sa]);
            size_t sb = ((size_t)b * T + t0 + row) * 256 + kc * 16 + 4 * u;
            cpa(sb0 + 5120 * 4 + off, &g_xh[sb]);
            cpa(sb0 + 7680 * 4 + off, &g_xl[sb]);
        }
    };

    fill(0, 0); CPA_COMMIT;
    for (int kc = 0; kc < 16; kc++) {
        CPA_WAIT0;
        __syncthreads();
        if (kc < 15) { fill(kc + 1, (kc + 1) & 1); CPA_COMMIT; }
        unsigned stb = base + (kc & 1) * 10240 * 4;
        unsigned baseAh = stb, baseAl = stb + 2560 * 4;
        unsigned baseBh = stb + 5120 * 4, baseBl = stb + 7680 * 4;
#pragma unroll
        for (int ks = 0; ks < 2; ks++) {
            unsigned ah[2][4], al[2][4];
#pragma unroll
            for (int mt = 0; mt < 2; mt++) {
                unsigned row = wm * 32 + mt * 16 + (grp & 1) * 8 + lam;
                unsigned col = ks * 8 + (grp >> 1) * 4;
                unsigned off = (row * 20 + col) * 4;
                ldsm4(ah[mt], baseAh + off);
                ldsm4(al[mt], baseAl + off);
            }
#pragma unroll
            for (int half = 0; half < 2; half++) {
                unsigned bh[2][4], bl[2][4];
#pragma unroll
                for (int p = 0; p < 2; p++) {
                    int ntp = half * 4 + 2 * p;
                    unsigned row = wn * 64 + (ntp + (grp >> 1)) * 8 + lam;
                    unsigned col = ks * 8 + (grp & 1) * 4;
                    unsigned off = (row * 20 + col) * 4;
                    ldsm4(bh[p], baseBh + off);
                    ldsm4(bl[p], baseBl + off);
                }
#pragma unroll
                for (int p = 0; p < 2; p++)
#pragma unroll
                    for (int mt = 0; mt < 2; mt++) {
                        mma16(acc[mt][half * 4 + 2 * p],     ah[mt], bh[p][0], bh[p][1]);
                        mma16(acc[mt][half * 4 + 2 * p + 1], ah[mt], bh[p][2], bh[p][3]);
                    }
#pragma unroll
                for (int p = 0; p < 2; p++)
#pragma unroll
                    for (int mt = 0; mt < 2; mt++) {
                        mma16(acc[mt][half * 4 + 2 * p],     ah[mt], bl[p][0], bl[p][1]);
                        mma16(acc[mt][half * 4 + 2 * p + 1], ah[mt], bl[p][2], bl[p][3]);
                    }
#pragma unroll
                for (int p = 0; p < 2; p++)
#pragma unroll
                    for (int mt = 0; mt < 2; mt++) {
                        mma16(acc[mt][half * 4 + 2 * p],     al[mt], bh[p][0], bh[p][1]);
                        mma16(acc[mt][half * 4 + 2 * p + 1], al[mt], bh[p][2], bh[p][3]);
                    }
            }
        }
        __syncthreads();
    }

    // ---- phase 1: final values into smem ts[t][row] (row stride 133) ----
    float* ts = (float*)smg;
#pragma unroll
    for (int mt = 0; mt < 2; mt++) {
        int rowl = wm * 32 + mt * 16 + g;
        int row = m0 + rowl;
        float bi0 = bias[row], bi1 = bias[row + 8];
        // q rows pre-scaled by ch^-0.5 * log2(e) for exp2-domain softmax
        float s0 = ((row % 192) < 64) ? 0.18033688f : 1.f;
        float s1 = (((row + 8) % 192) < 64) ? 0.18033688f : 1.f;
#pragma unroll
        for (int nt = 0; nt < 8; nt++) {
            int coll = wn * 64 + nt * 8 + 2 * q;
            ts[coll * 133 + rowl]           = (acc[mt][nt][0] * (1.f / 256.f) + bi0) * s0;
            ts[(coll + 1) * 133 + rowl]     = (acc[mt][nt][1] * (1.f / 256.f) + bi0) * s0;
            ts[coll * 133 + rowl + 8]       = (acc[mt][nt][2] * (1.f / 256.f) + bi1) * s1;
            ts[(coll + 1) * 133 + rowl + 8] = (acc[mt][nt][3] * (1.f / 256.f) + bi1) * s1;
        }
    }
    __syncthreads();

    // ---- phase 2: emit per-segment outputs ----
#pragma unroll
    for (int half = 0; half < 2; half++) {
        int grow0 = m0 + half * 64;
        int st = (grow0 / 64) % 3;           // 0=q, 1=k, 2=v
        int hh2 = grow0 / 192;
        if (st < 2) {
            unsigned* dH = st ? g_kTh : g_qTh;
            unsigned* dL = st ? g_kTl : g_qTl;
            size_t obase = ((size_t)(b * 8 + hh2) * T + t0) * 32;
#pragma unroll
            for (int i = 0; i < 16; i++) {
                int idx = tid + i * 256;
                int t = idx >> 5, cp = idx & 31;
                unsigned h, l;
                split2(ts[t * 133 + half * 64 + 2 * cp],
                       ts[t * 133 + half * 64 + 2 * cp + 1], h, l);
                size_t d = obase + (size_t)t * 32 + cp;
                dH[d] = h; dL[d] = l;
            }
        } else {
#pragma unroll
            for (int i = 0; i < 16; i++) {
                int idx = tid + i * 256;
                int c = idx >> 6, tp = idx & 63;
                unsigned h, l;
                split2(ts[(2 * tp) * 133 + half * 64 + c],
                       ts[(2 * tp + 1) * 133 + half * 64 + c], h, l);
                g_vh[((size_t)b * M3 + grow0 + c) * 2048 + ((t0 >> 1) + tp)] = h;
            }
        }
    }
}

// ---------------------------------------------------------------------------
// Flash attention: QK^T split fp16, PV with P in registers.
// Epilogue writes a as packed fp16 [t][c] hi-plane for the fp16 proj.
__global__ void __launch_bounds__(256, 2) attn_mma() {
    extern __shared__ unsigned sma[];
    unsigned base = (unsigned)__cvta_generic_to_shared(sma);
    unsigned* Ps  = sma;
    unsigned* Qlo = sma + 4608;
    unsigned basePs = base;
    unsigned baseQl = base + 4608 * 4;

    int t0 = blockIdx.x * 128, head = blockIdx.y;
    int b = head >> 3, hh = head & 7;
    int tid = threadIdx.x, lane = tid & 31, wid = tid >> 5;
    int g = lane >> 2, q = lane & 3, rb = wid * 16;
    int grp = lane >> 3, lam = lane & 7;

    const unsigned* qThp = g_qTh + ((size_t)head * T + t0) * 32;
    const unsigned* qTlp = g_qTl + ((size_t)head * T + t0) * 32;
    const unsigned* kThp = g_kTh + (size_t)head * T * 32;
    const unsigned* kTlp = g_kTl + (size_t)head * T * 32;
    const unsigned* vhp  = g_vh + ((size_t)b * M3 + hh * 192 + 128) * 2048;

#pragma unroll
    for (int i = 0; i < 4; i++) {
        int idx = tid + i * 256, row = idx >> 3, u = idx & 7;
        *(uint4*)&Ps[row * 36 + 4 * u]  = *(const uint4*)&qThp[(size_t)row * 32 + 4 * u];
        *(uint4*)&Qlo[row * 36 + 4 * u] = *(const uint4*)&qTlp[(size_t)row * 32 + 4 * u];
    }
    __syncthreads();
    unsigned qh[4][4], ql[4][4];
#pragma unroll
    for (int ks = 0; ks < 4; ks++) {
        unsigned row = rb + (grp & 1) * 8 + lam;
        unsigned col = ks * 8 + (grp >> 1) * 4;
        unsigned off = (row * 36 + col) * 4;
        ldsm4(qh[ks], basePs + off);
        ldsm4(ql[ks], baseQl + off);
    }
    __syncthreads();   // q frags loaded before stage0 overwrites Qlo

    auto fillKV = [&](int it, int st) {
        unsigned sb0 = base + (4608 + st * 6912) * 4;
        int s0 = it * 64;
#pragma unroll
        for (int i = 0; i < 2; i++) {
            int idx = tid + i * 256, row = idx >> 3, u = idx & 7;
            unsigned off = (row * 36 + 4 * u) * 4;
            cpa(sb0 + off,            &kThp[(size_t)(s0 + row) * 32 + 4 * u]);
            cpa(sb0 + 2304 * 4 + off, &kTlp[(size_t)(s0 + row) * 32 + 4 * u]);
            cpa(sb0 + 4608 * 4 + off, &vhp[(size_t)row * 2048 + (s0 >> 1) + 4 * u]);
        }
    };

    float o[8][4];
#pragma unroll
    for (int nt = 0; nt < 8; nt++)
#pragma unroll
        for (int i = 0; i < 4; i++) o[nt][i] = 0.f;
    float m_a = -1e30f, m_b = -1e30f, l_a = 0.f, l_b = 0.f;

    fillKV(0, 0); CPA_COMMIT;
    for (int it = 0; it < 64; it++) {
        CPA_WAIT0;
        __syncthreads();
        if (it < 63) { fillKV(it + 1, (it + 1) & 1); CPA_COMMIT; }
        unsigned stb = base + (4608 + (it & 1) * 6912) * 4;
        unsigned baseKh = stb, baseKl = stb + 2304 * 4, baseVh = stb + 4608 * 4;

        float sacc[8][4];
#pragma unroll
        for (int nt = 0; nt < 8; nt++)
#pragma unroll
            for (int i = 0; i < 4; i++) sacc[nt][i] = 0.f;
#pragma unroll
        for (int ks = 0; ks < 4; ks++) {
#pragma unroll
            for (int half = 0; half < 2; half++) {
                unsigned kh[2][4], kl[2][4];
#pragma unroll
                for (int p = 0; p < 2; p++) {
                    int ntp = half * 4 + 2 * p;
                    unsigned row = (ntp + (grp >> 1)) * 8 + lam;
                    unsigned col = ks * 8 + (grp & 1) * 4;
                    unsigned off = (row * 36 + col) * 4;
                    ldsm4(kh[p], baseKh + off);
                    ldsm4(kl[p], baseKl + off);
                }
#pragma unroll
                for (int p = 0; p < 2; p++) {
                    mma16(sacc[half * 4 + 2 * p],     qh[ks], kh[p][0], kh[p][1]);
                    mma16(sacc[half * 4 + 2 * p + 1], qh[ks], kh[p][2], kh[p][3]);
                }
#pragma unroll
                for (int p = 0; p < 2; p++) {
                    mma16(sacc[half * 4 + 2 * p],     qh[ks], kl[p][0], kl[p][1]);
                    mma16(sacc[half * 4 + 2 * p + 1], qh[ks], kl[p][2], kl[p][3]);
                }
#pragma unroll
                for (int p = 0; p < 2; p++) {
                    mma16(sacc[half * 4 + 2 * p],     ql[ks], kh[p][0], kh[p][1]);
                    mma16(sacc[half * 4 + 2 * p + 1], ql[ks], kh[p][2], kh[p][3]);
                }
            }
        }

        float mx_a = -1e30f, mx_b = -1e30f;
#pragma unroll
        for (int nt = 0; nt < 8; nt++) {
            mx_a = fmaxf(mx_a, fmaxf(sacc[nt][0], sacc[nt][1]));
            mx_b = fmaxf(mx_b, fmaxf(sacc[nt][2], sacc[nt][3]));
        }
        mx_a = fmaxf(mx_a, __shfl_xor_sync(~0u, mx_a, 1));
        mx_a = fmaxf(mx_a, __shfl_xor_sync(~0u, mx_a, 2));
        mx_b = fmaxf(mx_b, __shfl_xor_sync(~0u, mx_b, 1));
        mx_b = fmaxf(mx_b, __shfl_xor_sync(~0u, mx_b, 2));
        float mn_a = fmaxf(m_a, mx_a), mn_b = fmaxf(m_b, mx_b);
        float ca = ex2(m_a - mn_a), cb = ex2(m_b - mn_b);
        float sum_a = 0.f, sum_b = 0.f;
        unsigned ph2[8][2];
#pragma unroll
        for (int nt = 0; nt < 8; nt++) {
            float p0 = ex2(sacc[nt][0] - mn_a), p1 = ex2(sacc[nt][1] - mn_a);
            float p2 = ex2(sacc[nt][2] - mn_b), p3 = ex2(sacc[nt][3] - mn_b);
            sum_a += p0 + p1; sum_b += p2 + p3;
            ph2[nt][0] = pack2h(p0, p1);
            ph2[nt][1] = pack2h(p2, p3);
        }
        sum_a += __shfl_xor_sync(~0u, sum_a, 1);
        sum_a += __shfl_xor_sync(~0u, sum_a, 2);
        sum_b += __shfl_xor_sync(~0u, sum_b, 1);
        sum_b += __shfl_xor_sync(~0u, sum_b, 2);
        m_a = mn_a; m_b = mn_b;
        l_a = l_a * ca + sum_a; l_b = l_b * cb + sum_b;
#pragma unroll
        for (int nt = 0; nt < 8; nt++) {
            o[nt][0] *= ca; o[nt][1] *= ca; o[nt][2] *= cb; o[nt][3] *= cb;
        }
#pragma unroll
        for (int ks = 0; ks < 4; ks++) {
            unsigned pa[4] = { ph2[2 * ks][0], ph2[2 * ks][1],
                               ph2[2 * ks + 1][0], ph2[2 * ks + 1][1] };
#pragma unroll
            for (int ntp = 0; ntp < 8; ntp += 2) {
                unsigned row = (ntp + (grp >> 1)) * 8 + lam;
                unsigned col = ks * 8 + (grp & 1) * 4;
                unsigned vh[4];
                ldsm4(vh, baseVh + (row * 36 + col) * 4);
                mma16(o[ntp],     pa, vh[0], vh[1]);
                mma16(o[ntp + 1], pa, vh[2], vh[3]);
            }
        }
    }

    float inv_a = 1.f / l_a, inv_b = 1.f / l_b;
    unsigned* aT = g_aTh + (size_t)b * T * 256 + hh * 32;
    int t_a = t0 + rb + g, t_b = t_a + 8;
#pragma unroll
    for (int nt = 0; nt < 8; nt++) {
        aT[(size_t)t_a * 256 + nt * 4 + q] = pack2h(o[nt][0] * inv_a, o[nt][1] * inv_a);
        aT[(size_t)t_b * 256 + nt * 4 + q] = pack2h(o[nt][2] * inv_b, o[nt][3] * inv_b);
    }
}

// ---------------------------------------------------------------------------
// proj GEMM + bias + residual: single fp16, cp.async 2-stage, pure-copy fills.
__global__ void __launch_bounds__(256, 2) proj_mma(
        const float* __restrict__ bias,
        const float* __restrict__ resid, float* __restrict__ outp)
{
    extern __shared__ unsigned smg[];
    unsigned base = (unsigned)__cvta_generic_to_shared(smg);

    int b = blockIdx.z, m0 = blockIdx.y * 128, t0 = blockIdx.x * 128;
    int tid = threadIdx.x, lane = tid & 31, wid = tid >> 5;
    int wm = wid >> 1, wn = wid & 1, g = lane >> 2, q = lane & 3;
    int grp = lane >> 3, lam = lane & 7;

    float acc[2][8][4];
#pragma unroll
    for (int mt = 0; mt < 2; mt++)
#pragma unroll
        for (int nt = 0; nt < 8; nt++)
#pragma unroll
            for (int i = 0; i < 4; i++) acc[mt][nt][i] = 0.f;

    auto fill = [&](int kc, int st) {
        unsigned sb0 = base + st * 5120 * 4;
#pragma unroll
        for (int i = 0; i < 2; i++) {
            int idx = tid + i * 256, row = idx >> 2, u = idx & 3;
            unsigned off = (row * 20 + 4 * u) * 4;
            cpa(sb0 + off,
                &g_pwh[(size_t)(m0 + row) * 256 + kc * 16 + 4 * u]);
            cpa(sb0 + 2560 * 4 + off,
                &g_aTh[((size_t)b * T + t0 + row) * 256 + kc * 16 + 4 * u]);
        }
    };

    fill(0, 0); CPA_COMMIT;
    for (int kc = 0; kc < 16; kc++) {
        CPA_WAIT0;
        __syncthreads();
        if (kc < 15) { fill(kc + 1, (kc + 1) & 1); CPA_COMMIT; }
        unsigned stb = base + (kc & 1) * 5120 * 4;
        unsigned baseA = stb, baseB = stb + 2560 * 4;
#pragma unroll
        for (int ks = 0; ks < 2; ks++) {
            unsigned ah[2][4];
#pragma unroll
            for (int mt = 0; mt < 2; mt++) {
                unsigned row = wm * 32 + mt * 16 + (grp & 1) * 8 + lam;
                unsigned col = ks * 8 + (grp >> 1) * 4;
                ldsm4(ah[mt], baseA + (row * 20 + col) * 4);
            }
#pragma unroll
            for (int ntp = 0; ntp < 8; ntp += 2) {
                unsigned row = wn * 64 + (ntp + (grp >> 1)) * 8 + lam;
                unsigned col = ks * 8 + (grp & 1) * 4;
                unsigned bh[4];
                ldsm4(bh, baseB + (row * 20 + col) * 4);
#pragma unroll
                for (int mt = 0; mt < 2; mt++) {
                    mma16(acc[mt][ntp], ah[mt], bh[0], bh[1]);
                    mma16(acc[mt][ntp + 1], ah[mt], bh[2], bh[3]);
                }
            }
        }
        __syncthreads();
    }
#pragma unroll
    for (int mt = 0; mt < 2; mt++) {
        int row = m0 + wm * 32 + mt * 16 + g;
        float bi0 = bias[row], bi1 = bias[row + 8];
#pragma unroll
        for (int nt = 0; nt < 8; nt++) {
            int col = t0 + wn * 64 + nt * 8 + 2 * q;
            size_t i0 = ((size_t)b * CHN + row) * T + col;
            size_t i1 = ((size_t)b * CHN + row + 8) * T + col;
            float2 r0 = *(const float2*)&resid[i0];
            float2 r1 = *(const float2*)&resid[i1];
            *(float2*)&outp[i0] = make_float2(
                acc[mt][nt][0] * (1.f / 256.f) + bi0 + r0.x,
                acc[mt][nt][1] * (1.f / 256.f) + bi0 + r0.y);
            *(float2*)&outp[i1] = make_float2(
                acc[mt][nt][2] * (1.f / 256.f) + bi1 + r1.x,
                acc[mt][nt][3] * (1.f / 256.f) + bi1 + r1.y);
        }
    }
}

// ---------------------------------------------------------------------------
extern "C" void kernel_launch(void* const* d_in, const int* in_sizes, int n_in,
                              void* d_out, int out_size) {
    const float* x      = (const float*)d_in[0];
    const float* nw     = (const float*)d_in[1];
    const float* qkv_w  = (const float*)d_in[2];
    const float* qkv_b  = (const float*)d_in[3];
    const float* proj_w = (const float*)d_in[4];
    const float* proj_b = (const float*)d_in[5];
    float* out = (float*)d_out;

    const int QKV_SMEM  = 20480 * 4;  // 81920 (2 stages; epilogue reuses as ts)
    const int PROJ_SMEM = 10240 * 4;  // 40960 (2 stages)
    const int ATT_SMEM  = 18432 * 4;  // 73728 (Ps + 2 stages)
    static bool init = false;
    if (!init) {
        cudaFuncSetAttribute(qkv_mma,  cudaFuncAttributeMaxDynamicSharedMemorySize, QKV_SMEM);
        cudaFuncSetAttribute(proj_mma, cudaFuncAttributeMaxDynamicSharedMemorySize, PROJ_SMEM);
        cudaFuncSetAttribute(attn_mma, cudaFuncAttributeMaxDynamicSharedMemorySize, ATT_SMEM);
        cudaFuncSetAttribute(qkv_mma,  cudaFuncAttributePreferredSharedMemoryCarveout, 100);
        cudaFuncSetAttribute(proj_mma, cudaFuncAttributePreferredSharedMemoryCarveout, 100);
        cudaFuncSetAttribute(attn_mma, cudaFuncAttributePreferredSharedMemoryCarveout, 100);
        init = true;
    }
    rms_kernel<<<256, 256>>>(x);
    prep_w<<<768, 256>>>(qkv_w);
    prep_pw<<<256, 256>>>(proj_w);
    prep_x<<<dim3(64, 8, 2), 256>>>(x, nw);
    qkv_mma<<<dim3(32, 12, 2), 256, QKV_SMEM>>>(qkv_b);
    attn_mma<<<dim3(32, 16), 256, ATT_SMEM>>>();
    proj_mma<<<dim3(32, 4, 2), 256, PROJ_SMEM>>>(proj_b, x, out);
}